// round 1
// baseline (speedup 1.0000x reference)
#include <cuda_runtime.h>
#include <math.h>

#define Bsz 4
#define Sq 512
#define Dm 512
#define Hn 8
#define DKh 64
#define Lyr 6
#define DFFn 2048
#define VOCn 50257
#define NTOK (Bsz*Sq)      // 2048
#define VPAD 50304         // 393*128, multiple of 128 for aligned/vectorized B loads

// ---------------- device scratch (allocation-free rule: __device__ globals) ----------
__device__ float g_x[NTOK*Dm];
__device__ float g_q[NTOK*Dm];
__device__ float g_k[NTOK*Dm];
__device__ float g_v[NTOK*Dm];
__device__ float g_t[NTOK*Dm];
__device__ float g_sc[(size_t)Bsz*Hn*Sq*Sq];     // 8.4M floats
__device__ float g_ff[(size_t)NTOK*DFFn];        // 4M floats
__device__ float g_wpad[(size_t)Dm*VPAD];        // padded Wout

// ---------------- reductions ----------------
__device__ __forceinline__ float blockReduceSum(float v, float* sh) {
    int lane = threadIdx.x & 31, w = threadIdx.x >> 5;
#pragma unroll
    for (int o = 16; o; o >>= 1) v += __shfl_xor_sync(0xffffffffu, v, o);
    if (!lane) sh[w] = v;
    __syncthreads();
    if (threadIdx.x < 8) {
        v = sh[threadIdx.x];
#pragma unroll
        for (int o = 4; o; o >>= 1) v += __shfl_xor_sync(0xffu, v, o);
        if (!threadIdx.x) sh[0] = v;
    }
    __syncthreads();
    float r = sh[0];
    __syncthreads();
    return r;
}

__device__ __forceinline__ float blockReduceMax(float v, float* sh) {
    int lane = threadIdx.x & 31, w = threadIdx.x >> 5;
#pragma unroll
    for (int o = 16; o; o >>= 1) v = fmaxf(v, __shfl_xor_sync(0xffffffffu, v, o));
    if (!lane) sh[w] = v;
    __syncthreads();
    if (threadIdx.x < 8) {
        v = sh[threadIdx.x];
#pragma unroll
        for (int o = 4; o; o >>= 1) v = fmaxf(v, __shfl_xor_sync(0xffu, v, o));
        if (!threadIdx.x) sh[0] = v;
    }
    __syncthreads();
    float r = sh[0];
    __syncthreads();
    return r;
}

// ---------------- embedding ----------------
__global__ void embed_kernel(const int* __restrict__ ids,
                             const float* __restrict__ tok,
                             const float* __restrict__ pos,
                             float* __restrict__ x) {
    int row = blockIdx.x;            // 0..NTOK-1
    int s = row % Sq;
    int id = ids[row];
    const float4* t4 = reinterpret_cast<const float4*>(tok) + (size_t)id * (Dm / 4);
    const float4* p4 = reinterpret_cast<const float4*>(pos) + (size_t)s * (Dm / 4);
    float4* x4 = reinterpret_cast<float4*>(x) + (size_t)row * (Dm / 4);
    int t = threadIdx.x;             // 128 threads, Dm/4 = 128
    float4 a = t4[t], b = p4[t];
    a.x += b.x; a.y += b.y; a.z += b.z; a.w += b.w;
    x4[t] = a;
}

// ---------------- generic SGEMM: C[M,Nc] = act(A[M,K] @ B[K,Nb](cols 0..Nc) + bias) --
// M % BM == 0 and K % BK == 0 assumed (true for all call sites).
// ACT: 0 = none, 1 = exact GELU
template <int BM, int BN, int BK, int TM, int TN, int ACT>
__global__ __launch_bounds__(256)
void gemm_bias(int M, int Nb, int K,
               const float* __restrict__ A,
               const float* __restrict__ B,
               const float* __restrict__ bias,
               float* __restrict__ C, int Nc) {
    constexpr int THREADS = (BM / TM) * (BN / TN);
    __shared__ float As[BK][BM];
    __shared__ float Bs[BK][BN];

    const int tid = threadIdx.x;
    const int crow = blockIdx.y * BM;
    const int ccol = blockIdx.x * BN;
    const bool vecOK = ((Nb & 3) == 0) && (ccol + BN <= Nb);

    constexpr int A_TPR = BK / 4;                 // threads per A row
    const int aRow = tid / A_TPR;
    const int aCol = (tid % A_TPR) * 4;
    constexpr int A_RS = THREADS / A_TPR;

    constexpr int B_TPR = BN / 4;
    const int bRow = tid / B_TPR;
    const int bCol = (tid % B_TPR) * 4;
    constexpr int B_RS = THREADS / B_TPR;

    const int tcol = tid % (BN / TN);
    const int trow = tid / (BN / TN);

    float acc[TM][TN];
#pragma unroll
    for (int i = 0; i < TM; i++)
#pragma unroll
        for (int j = 0; j < TN; j++) acc[i][j] = 0.f;

    for (int k0 = 0; k0 < K; k0 += BK) {
        // load A tile (transposed into smem)
#pragma unroll
        for (int r = aRow; r < BM; r += A_RS) {
            float4 v = *reinterpret_cast<const float4*>(&A[(size_t)(crow + r) * K + k0 + aCol]);
            As[aCol + 0][r] = v.x; As[aCol + 1][r] = v.y;
            As[aCol + 2][r] = v.z; As[aCol + 3][r] = v.w;
        }
        // load B tile
        if (vecOK) {
#pragma unroll
            for (int r = bRow; r < BK; r += B_RS) {
                float4 v = *reinterpret_cast<const float4*>(&B[(size_t)(k0 + r) * Nb + ccol + bCol]);
                *reinterpret_cast<float4*>(&Bs[r][bCol]) = v;
            }
        } else {
#pragma unroll
            for (int r = bRow; r < BK; r += B_RS) {
#pragma unroll
                for (int c = 0; c < 4; c++) {
                    int col = ccol + bCol + c;
                    Bs[r][bCol + c] = (col < Nb) ? B[(size_t)(k0 + r) * Nb + col] : 0.f;
                }
            }
        }
        __syncthreads();

#pragma unroll
        for (int k = 0; k < BK; k++) {
            float ra[TM], rb[TN];
#pragma unroll
            for (int i = 0; i < TM; i++) ra[i] = As[k][trow * TM + i];
#pragma unroll
            for (int j = 0; j < TN; j++) rb[j] = Bs[k][tcol * TN + j];
#pragma unroll
            for (int i = 0; i < TM; i++)
#pragma unroll
                for (int j = 0; j < TN; j++) acc[i][j] += ra[i] * rb[j];
        }
        __syncthreads();
    }

#pragma unroll
    for (int i = 0; i < TM; i++) {
        int row = crow + trow * TM + i;
#pragma unroll
        for (int j = 0; j < TN; j++) {
            int col = ccol + tcol * TN + j;
            if (col < Nc) {
                float v = acc[i][j] + bias[col];
                if (ACT == 1) v = 0.5f * v * (1.0f + erff(v * 0.70710678118654752f));
                C[(size_t)row * Nc + col] = v;
            }
        }
    }
}

// ---------------- attention: scores[bh, q, k] = (Q_row . K_row) * 1/8 -------------
__global__ __launch_bounds__(256)
void attn_scores(const float* __restrict__ Q, const float* __restrict__ Kk,
                 float* __restrict__ Sc) {
    const int bh = blockIdx.z;
    const int b = bh / Hn, h = bh % Hn;
    const float* qb = Q + (size_t)b * Sq * Dm + h * DKh;
    const float* kb = Kk + (size_t)b * Sq * Dm + h * DKh;
    float* sb = Sc + (size_t)bh * Sq * Sq;

    __shared__ float Qs[DKh][64];
    __shared__ float Ks[DKh][64];

    const int q0 = blockIdx.y * 64, k0 = blockIdx.x * 64;
    const int tid = threadIdx.x;
    const int lr = tid / 16, lc = (tid % 16) * 4;

#pragma unroll
    for (int r = lr; r < 64; r += 16) {
        float4 v = *reinterpret_cast<const float4*>(&qb[(size_t)(q0 + r) * Dm + lc]);
        Qs[lc + 0][r] = v.x; Qs[lc + 1][r] = v.y; Qs[lc + 2][r] = v.z; Qs[lc + 3][r] = v.w;
        float4 w = *reinterpret_cast<const float4*>(&kb[(size_t)(k0 + r) * Dm + lc]);
        Ks[lc + 0][r] = w.x; Ks[lc + 1][r] = w.y; Ks[lc + 2][r] = w.z; Ks[lc + 3][r] = w.w;
    }
    __syncthreads();

    const int tcol = tid % 16, trow = tid / 16;
    float acc[4][4] = {};
#pragma unroll
    for (int d = 0; d < DKh; d++) {
        float ra[4], rb[4];
#pragma unroll
        for (int i = 0; i < 4; i++) ra[i] = Qs[d][trow * 4 + i];
#pragma unroll
        for (int j = 0; j < 4; j++) rb[j] = Ks[d][tcol * 4 + j];
#pragma unroll
        for (int i = 0; i < 4; i++)
#pragma unroll
            for (int j = 0; j < 4; j++) acc[i][j] += ra[i] * rb[j];
    }
    const float sc = 0.125f;   // 1/sqrt(64)
#pragma unroll
    for (int i = 0; i < 4; i++)
#pragma unroll
        for (int j = 0; j < 4; j++)
            sb[(size_t)(q0 + trow * 4 + i) * Sq + k0 + tcol * 4 + j] = acc[i][j] * sc;
}

// ---------------- softmax over rows of length 512 ----------------
__global__ void softmax_kernel(float* __restrict__ s) {
    float* p = s + (size_t)blockIdx.x * Sq;
    int t = threadIdx.x;                       // 256 threads
    float a = p[t], b = p[t + 256];
    __shared__ float sh[32];
    float m = blockReduceMax(fmaxf(a, b), sh);
    float e0 = __expf(a - m), e1 = __expf(b - m);
    float sum = blockReduceSum(e0 + e1, sh);
    float inv = 1.0f / sum;
    p[t] = e0 * inv;
    p[t + 256] = e1 * inv;
}

// ---------------- o[b,q,h*64+d] = sum_k att[bh,q,k] * v[b*S+k, h*64+d] ------------
__global__ __launch_bounds__(256)
void attn_av(const float* __restrict__ Sc, const float* __restrict__ V,
             float* __restrict__ O) {
    const int bh = blockIdx.z;
    const int b = bh / Hn, h = bh % Hn;
    const float* sb = Sc + (size_t)bh * Sq * Sq;
    const float* vb = V + (size_t)b * Sq * Dm + h * DKh;
    float* ob = O + (size_t)b * Sq * Dm + h * DKh;

    __shared__ float As[64][64];   // [k][m]
    __shared__ float Bs[64][64];   // [k][n]

    const int q0 = blockIdx.y * 64;
    const int tid = threadIdx.x;
    const int lr = tid / 16, lc = (tid % 16) * 4;
    const int tcol = tid % 16, trow = tid / 16;

    float acc[4][4] = {};
    for (int kk = 0; kk < Sq; kk += 64) {
#pragma unroll
        for (int r = lr; r < 64; r += 16) {
            float4 v = *reinterpret_cast<const float4*>(&sb[(size_t)(q0 + r) * Sq + kk + lc]);
            As[lc + 0][r] = v.x; As[lc + 1][r] = v.y; As[lc + 2][r] = v.z; As[lc + 3][r] = v.w;
            float4 w = *reinterpret_cast<const float4*>(&vb[(size_t)(kk + r) * Dm + lc]);
            *reinterpret_cast<float4*>(&Bs[r][lc]) = w;
        }
        __syncthreads();
#pragma unroll
        for (int k = 0; k < 64; k++) {
            float ra[4], rb[4];
#pragma unroll
            for (int i = 0; i < 4; i++) ra[i] = As[k][trow * 4 + i];
#pragma unroll
            for (int j = 0; j < 4; j++) rb[j] = Bs[k][tcol * 4 + j];
#pragma unroll
            for (int i = 0; i < 4; i++)
#pragma unroll
                for (int j = 0; j < 4; j++) acc[i][j] += ra[i] * rb[j];
        }
        __syncthreads();
    }
#pragma unroll
    for (int i = 0; i < 4; i++)
#pragma unroll
        for (int j = 0; j < 4; j++)
            ob[(size_t)(q0 + trow * 4 + i) * Dm + tcol * 4 + j] = acc[i][j];
}

// ---------------- LayerNorm (optionally with residual add): out = LN(a + res) -----
__global__ void ln_kernel(const float* __restrict__ a, const float* __restrict__ res,
                          const float* __restrict__ g, const float* __restrict__ beta,
                          float* __restrict__ out) {
    const size_t row = blockIdx.x;
    const int t = threadIdx.x;                 // 256 threads
    float v0 = a[row * Dm + t], v1 = a[row * Dm + t + 256];
    if (res) { v0 += res[row * Dm + t]; v1 += res[row * Dm + t + 256]; }
    __shared__ float sh[32];
    float s = blockReduceSum(v0 + v1, sh);
    float mean = s * (1.0f / Dm);
    float d0 = v0 - mean, d1 = v1 - mean;
    float ss = blockReduceSum(d0 * d0 + d1 * d1, sh);
    float inv = rsqrtf(ss * (1.0f / Dm) + 1e-5f);
    out[row * Dm + t]       = d0 * inv * g[t] + beta[t];
    out[row * Dm + t + 256] = d1 * inv * g[t + 256] + beta[t + 256];
}

// ---------------- pad Wout [K,N] into [K,VPAD] (aligned float4 rows) ---------------
__global__ void pad_copy(const float* __restrict__ src, float* __restrict__ dst) {
    const size_t total = (size_t)Dm * VPAD;
    for (size_t i = (size_t)blockIdx.x * blockDim.x + threadIdx.x; i < total;
         i += (size_t)gridDim.x * blockDim.x) {
        size_t r = i / VPAD, c = i % VPAD;
        dst[i] = (c < VOCn) ? src[r * VOCn + c] : 0.f;
    }
}

// ---------------- orchestration ----------------
extern "C" void kernel_launch(void* const* d_in, const int* in_sizes, int n_in,
                              void* d_out, int out_size) {
    const int*   ids  = (const int*)  d_in[0];
    const float* tok  = (const float*)d_in[1];
    const float* pos  = (const float*)d_in[2];
    const float* Wq   = (const float*)d_in[3];
    const float* bq   = (const float*)d_in[4];
    const float* Wk   = (const float*)d_in[5];
    const float* bk   = (const float*)d_in[6];
    const float* Wv   = (const float*)d_in[7];
    const float* bv   = (const float*)d_in[8];
    const float* Wo   = (const float*)d_in[9];
    const float* bo   = (const float*)d_in[10];
    const float* ln_g = (const float*)d_in[11];
    const float* ln_b = (const float*)d_in[12];
    const float* W1   = (const float*)d_in[13];
    const float* b1   = (const float*)d_in[14];
    const float* W2   = (const float*)d_in[15];
    const float* b2   = (const float*)d_in[16];
    const float* on_g = (const float*)d_in[17];
    const float* on_b = (const float*)d_in[18];
    const float* Wout = (const float*)d_in[19];
    const float* bout = (const float*)d_in[20];
    float* out = (float*)d_out;

    float *x, *q, *k, *v, *t, *sc, *ff, *wp;
    cudaGetSymbolAddress((void**)&x,  g_x);
    cudaGetSymbolAddress((void**)&q,  g_q);
    cudaGetSymbolAddress((void**)&k,  g_k);
    cudaGetSymbolAddress((void**)&v,  g_v);
    cudaGetSymbolAddress((void**)&t,  g_t);
    cudaGetSymbolAddress((void**)&sc, g_sc);
    cudaGetSymbolAddress((void**)&ff, g_ff);
    cudaGetSymbolAddress((void**)&wp, g_wpad);

    // embeddings
    embed_kernel<<<NTOK, 128>>>(ids, tok, pos, x);

    const dim3 gProj(Dm / 64, NTOK / 64);        // 8 x 32 = 256 blocks
    const dim3 gScores(Sq / 64, Sq / 64, Bsz * Hn);
    const dim3 gAV(1, Sq / 64, Bsz * Hn);

    for (int l = 0; l < Lyr; l++) {
        const size_t wOff = (size_t)l * Dm * Dm;
        const size_t bOff = (size_t)l * Dm;
        gemm_bias<64, 64, 16, 4, 4, 0><<<gProj, 256>>>(NTOK, Dm, Dm, x, Wq + wOff, bq + bOff, q, Dm);
        gemm_bias<64, 64, 16, 4, 4, 0><<<gProj, 256>>>(NTOK, Dm, Dm, x, Wk + wOff, bk + bOff, k, Dm);
        gemm_bias<64, 64, 16, 4, 4, 0><<<gProj, 256>>>(NTOK, Dm, Dm, x, Wv + wOff, bv + bOff, v, Dm);

        attn_scores<<<gScores, 256>>>(q, k, sc);
        softmax_kernel<<<Bsz * Hn * Sq, 256>>>(sc);
        attn_av<<<gAV, 256>>>(sc, v, t);

        // output projection (reuse q as temp), then residual + LN in-place into x
        gemm_bias<64, 64, 16, 4, 4, 0><<<gProj, 256>>>(NTOK, Dm, Dm, t, Wo + wOff, bo + bOff, q, Dm);
        ln_kernel<<<NTOK, 256>>>(x, q, ln_g + bOff, ln_b + bOff, x);
    }

    // FFN: gelu(x@W1+b1)@W2+b2, then LN (no residual)
    gemm_bias<128, 128, 16, 8, 8, 1><<<dim3(DFFn / 128, NTOK / 128), 256>>>(NTOK, DFFn, Dm, x, W1, b1, ff, DFFn);
    gemm_bias<64, 64, 16, 4, 4, 0><<<dim3(Dm / 64, NTOK / 64), 256>>>(NTOK, Dm, DFFn, ff, W2, b2, t, Dm);
    ln_kernel<<<NTOK, 256>>>(t, nullptr, on_g, on_b, x);

    // logits: pad Wout to aligned stride, then big GEMM straight into d_out
    pad_copy<<<2048, 256>>>(Wout, wp);
    gemm_bias<128, 128, 16, 8, 8, 0><<<dim3(VPAD / 128, NTOK / 128), 256>>>(NTOK, VPAD, Dm, x, wp, bout, out, VOCn);
}

// round 3
// speedup vs baseline: 1.3185x; 1.3185x over previous
#include <cuda_runtime.h>
#include <mma.h>
#include <cstdint>
#include <math.h>

using namespace nvcuda;

#define Bsz 4
#define Sq 512
#define Dm 512
#define Hn 8
#define DKh 64
#define Lyr 6
#define DFFn 2048
#define VOCn 50257
#define NTOK (Bsz*Sq)      // 2048
#define VPAD 50304         // padded Wout column stride (multiple of 128)
#define QKVLD 1536

// ---------------- ptx helpers ----------------
__device__ __forceinline__ uint32_t smem_u32(const void* p) {
    uint32_t a;
    asm("{ .reg .u64 t; cvta.to.shared.u64 t, %1; cvt.u32.u64 %0, t; }" : "=r"(a) : "l"(p));
    return a;
}
__device__ __forceinline__ float f32_tf32(float f) {
    uint32_t u;
    asm("cvt.rna.tf32.f32 %0, %1;" : "=r"(u) : "f"(f));
    return __uint_as_float(u);
}
#define CP_ASYNC16(dst, src) \
    asm volatile("cp.async.cg.shared.global [%0], [%1], 16;" :: "r"(dst), "l"(src))
#define CP_COMMIT()  asm volatile("cp.async.commit_group;" ::: "memory")
#define CP_WAIT0()   asm volatile("cp.async.wait_group 0;" ::: "memory")

// ---------------- device scratch ----------------
__device__ float g_x[NTOK*Dm];
__device__ float g_qkv[(size_t)NTOK*QKVLD];
__device__ float g_t[NTOK*Dm];
__device__ float g_tmp[NTOK*Dm];
__device__ float g_sc[(size_t)Bsz*Hn*Sq*Sq];
__device__ float g_ff[(size_t)NTOK*DFFn];
__device__ float g_wqkv[(size_t)Lyr*Dm*QKVLD];   // [L][512][1536] tf32, row-major K x N
__device__ float g_wo[(size_t)Lyr*Dm*Dm];        // tf32 copies
__device__ float g_w1[(size_t)Dm*DFFn];
__device__ float g_w2[(size_t)DFFn*Dm];
__device__ float g_wout[(size_t)Dm*VPAD];        // padded + tf32
__device__ float g_bqkv[Lyr*QKVLD];

// ---------------- reductions ----------------
__device__ __forceinline__ float blockReduceSum(float v, float* sh) {
    int lane = threadIdx.x & 31, w = threadIdx.x >> 5;
#pragma unroll
    for (int o = 16; o; o >>= 1) v += __shfl_xor_sync(0xffffffffu, v, o);
    if (!lane) sh[w] = v;
    __syncthreads();
    if (threadIdx.x < 8) {
        v = sh[threadIdx.x];
#pragma unroll
        for (int o = 4; o; o >>= 1) v += __shfl_xor_sync(0xffu, v, o);
        if (!threadIdx.x) sh[0] = v;
    }
    __syncthreads();
    float r = sh[0];
    __syncthreads();
    return r;
}
__device__ __forceinline__ float blockReduceMax(float v, float* sh) {
    int lane = threadIdx.x & 31, w = threadIdx.x >> 5;
#pragma unroll
    for (int o = 16; o; o >>= 1) v = fmaxf(v, __shfl_xor_sync(0xffffffffu, v, o));
    if (!lane) sh[w] = v;
    __syncthreads();
    if (threadIdx.x < 8) {
        v = sh[threadIdx.x];
#pragma unroll
        for (int o = 4; o; o >>= 1) v = fmaxf(v, __shfl_xor_sync(0xffu, v, o));
        if (!threadIdx.x) sh[0] = v;
    }
    __syncthreads();
    float r = sh[0];
    __syncthreads();
    return r;
}

// ---------------- small kernels ----------------
__global__ void embed_kernel(const int* __restrict__ ids,
                             const float* __restrict__ tok,
                             const float* __restrict__ pos,
                             float* __restrict__ x) {
    int row = blockIdx.x;
    int s = row % Sq;
    int id = ids[row];
    const float4* t4 = reinterpret_cast<const float4*>(tok) + (size_t)id * (Dm / 4);
    const float4* p4 = reinterpret_cast<const float4*>(pos) + (size_t)s * (Dm / 4);
    float4* x4 = reinterpret_cast<float4*>(x) + (size_t)row * (Dm / 4);
    int t = threadIdx.x;
    float4 a = t4[t], b = p4[t];
    a.x += b.x; a.y += b.y; a.z += b.z; a.w += b.w;
    x4[t] = a;
}

// tf32-round copy (vectorized)
__global__ void cvt_copy(const float* __restrict__ in, float* __restrict__ out, size_t n4) {
    size_t i = (size_t)blockIdx.x * blockDim.x + threadIdx.x;
    if (i >= n4) return;
    float4 v = reinterpret_cast<const float4*>(in)[i];
    v.x = f32_tf32(v.x); v.y = f32_tf32(v.y); v.z = f32_tf32(v.z); v.w = f32_tf32(v.w);
    reinterpret_cast<float4*>(out)[i] = v;
}

// build concatenated QKV weight [L][512][1536] with tf32 rounding
__global__ void build_wqkv(const float* __restrict__ Wq, const float* __restrict__ Wk,
                           const float* __restrict__ Wv, float* __restrict__ out) {
    size_t i = (size_t)blockIdx.x * blockDim.x + threadIdx.x;   // over L*512*384 float4s
    size_t total = (size_t)Lyr * Dm * (QKVLD / 4);
    if (i >= total) return;
    size_t n4 = i % (QKVLD / 4);
    size_t k  = (i / (QKVLD / 4)) % Dm;
    size_t l  = i / ((size_t)(QKVLD / 4) * Dm);
    const float* src = (n4 < 128) ? Wq : (n4 < 256) ? Wk : Wv;
    size_t nn = (n4 % 128) * 4;
    float4 v = *reinterpret_cast<const float4*>(&src[(l * Dm + k) * Dm + nn]);
    v.x = f32_tf32(v.x); v.y = f32_tf32(v.y); v.z = f32_tf32(v.z); v.w = f32_tf32(v.w);
    reinterpret_cast<float4*>(out)[i] = v;
}

// pad Wout [512][50257] -> [512][50304] with tf32 rounding
__global__ void pad_cvt_wout(const float* __restrict__ src, float* __restrict__ dst) {
    const size_t total = (size_t)Dm * VPAD;
    for (size_t i = (size_t)blockIdx.x * blockDim.x + threadIdx.x; i < total;
         i += (size_t)gridDim.x * blockDim.x) {
        size_t r = i / VPAD, c = i % VPAD;
        dst[i] = (c < VOCn) ? f32_tf32(src[r * VOCn + c]) : 0.f;
    }
}

__global__ void concat_bias(const float* __restrict__ bq, const float* __restrict__ bk,
                            const float* __restrict__ bv, float* __restrict__ o) {
    int i = blockIdx.x * blockDim.x + threadIdx.x;
    if (i >= Lyr * QKVLD) return;
    int l = i / QKVLD, j = i % QKVLD;
    float v = (j < 512) ? bq[l * 512 + j] : (j < 1024) ? bk[l * 512 + j - 512]
                                                       : bv[l * 512 + j - 1024];
    o[i] = v;
}

// ================= wmma tf32 GEMM =================
// C[M, ldc](cols<Nc) = act(A[M,K] @ W[K, ldw](cols ccol..) + bias)
// A fp32 (rounded on load), W pre-rounded tf32. BM=128 BN=128 BK=16, 256 thr.
template <int ACT>
__global__ __launch_bounds__(256, 2)
void gemm_wmma(int K, const float* __restrict__ A,
               const float* __restrict__ W, int ldw,
               const float* __restrict__ bias,
               float* __restrict__ C, int ldc, int Nc) {
    __shared__ float As[2][128][20];
    __shared__ float Bs[2][16][132];
    __shared__ float stg[8][16][20];

    const int tid = threadIdx.x;
    const int wid = tid >> 5, lane = tid & 31;
    const int crow = blockIdx.y * 128;
    const int ccol = blockIdx.x * 128;
    const int wm = wid & 3, wn = wid >> 2;          // 4 x 2 warp grid

    wmma::fragment<wmma::accumulator, 16, 16, 8, float> acc[2][4];
#pragma unroll
    for (int i = 0; i < 2; i++)
#pragma unroll
        for (int j = 0; j < 4; j++) wmma::fill_fragment(acc[i][j], 0.f);

    const int arow = tid >> 2;                      // 0..63
    const int aq = (tid & 3) * 4;                   // 0,4,8,12
    const float* Abase = A + (size_t)crow * K;
    const uint32_t bs0 = smem_u32(&Bs[0][0][0]);

    const int T = K >> 4;
    float4 preA0, preA1;

    // --- prologue: tile 0 ---
    preA0 = *reinterpret_cast<const float4*>(&Abase[(size_t)arow * K + aq]);
    preA1 = *reinterpret_cast<const float4*>(&Abase[(size_t)(arow + 64) * K + aq]);
    {
        const uint32_t dstb = bs0;
#pragma unroll
        for (int rep = 0; rep < 2; rep++) {
            int idx = rep * 256 + tid;
            int row = idx >> 5, seg = idx & 31;
            CP_ASYNC16(dstb + row * 528 + seg * 16,
                       &W[(size_t)row * ldw + ccol + seg * 4]);
        }
        CP_COMMIT();
    }
    {
        float4 u;
        u.x = f32_tf32(preA0.x); u.y = f32_tf32(preA0.y);
        u.z = f32_tf32(preA0.z); u.w = f32_tf32(preA0.w);
        *reinterpret_cast<float4*>(&As[0][arow][aq]) = u;
        u.x = f32_tf32(preA1.x); u.y = f32_tf32(preA1.y);
        u.z = f32_tf32(preA1.z); u.w = f32_tf32(preA1.w);
        *reinterpret_cast<float4*>(&As[0][arow + 64][aq]) = u;
    }
    CP_WAIT0();
    __syncthreads();

    for (int t = 0; t < T; t++) {
        const int buf = t & 1;
        if (t + 1 < T) {
            const int k0 = (t + 1) << 4;
            preA0 = *reinterpret_cast<const float4*>(&Abase[(size_t)arow * K + k0 + aq]);
            preA1 = *reinterpret_cast<const float4*>(&Abase[(size_t)(arow + 64) * K + k0 + aq]);
            const uint32_t dstb = bs0 + (buf ^ 1) * (16 * 528);
#pragma unroll
            for (int rep = 0; rep < 2; rep++) {
                int idx = rep * 256 + tid;
                int row = idx >> 5, seg = idx & 31;
                CP_ASYNC16(dstb + row * 528 + seg * 16,
                           &W[(size_t)(k0 + row) * ldw + ccol + seg * 4]);
            }
            CP_COMMIT();
        }

        // compute on buf
#pragma unroll
        for (int ks = 0; ks < 2; ks++) {
            wmma::fragment<wmma::matrix_a, 16, 16, 8, wmma::precision::tf32, wmma::row_major> af[2];
            wmma::fragment<wmma::matrix_b, 16, 16, 8, wmma::precision::tf32, wmma::row_major> bf[4];
            wmma::load_matrix_sync(af[0], &As[buf][wm * 32][ks * 8], 20);
            wmma::load_matrix_sync(af[1], &As[buf][wm * 32 + 16][ks * 8], 20);
#pragma unroll
            for (int j = 0; j < 4; j++)
                wmma::load_matrix_sync(bf[j], &Bs[buf][ks * 8][wn * 64 + j * 16], 132);
#pragma unroll
            for (int i = 0; i < 2; i++)
#pragma unroll
                for (int j = 0; j < 4; j++)
                    wmma::mma_sync(acc[i][j], af[i], bf[j], acc[i][j]);
        }

        if (t + 1 < T) {
            float4 u;
            u.x = f32_tf32(preA0.x); u.y = f32_tf32(preA0.y);
            u.z = f32_tf32(preA0.z); u.w = f32_tf32(preA0.w);
            *reinterpret_cast<float4*>(&As[buf ^ 1][arow][aq]) = u;
            u.x = f32_tf32(preA1.x); u.y = f32_tf32(preA1.y);
            u.z = f32_tf32(preA1.z); u.w = f32_tf32(preA1.w);
            *reinterpret_cast<float4*>(&As[buf ^ 1][arow + 64][aq]) = u;
            CP_WAIT0();
            __syncthreads();
        }
    }

    // --- epilogue: stage each 16x16 frag through smem, bias(+gelu), store ---
    const int r = lane & 15;
    const int cs = (lane >> 4) * 8;
#pragma unroll
    for (int i = 0; i < 2; i++) {
#pragma unroll
        for (int j = 0; j < 4; j++) {
            wmma::store_matrix_sync(&stg[wid][0][0], acc[i][j], 20, wmma::mem_row_major);
            __syncwarp();
            int row = crow + wm * 32 + i * 16 + r;
            int colb = ccol + wn * 64 + j * 16 + cs;
            float* cp = &C[(size_t)row * ldc + colb];
#pragma unroll
            for (int c = 0; c < 8; c++) {
                int col = colb + c;
                if (col < Nc) {
                    float v = stg[wid][r][cs + c] + bias[col];
                    if (ACT == 1) v = 0.5f * v * (1.0f + erff(v * 0.70710678118654752f));
                    cp[c] = v;
                }
            }
            __syncwarp();
        }
    }
}

// ================= attention (fp32 scalar) =================
__global__ __launch_bounds__(256)
void attn_scores(const float* __restrict__ QKV, float* __restrict__ Sc) {
    const int bh = blockIdx.z;
    const int b = bh / Hn, h = bh % Hn;
    const float* qb = QKV + (size_t)b * Sq * QKVLD + h * DKh;
    const float* kb = QKV + (size_t)b * Sq * QKVLD + 512 + h * DKh;
    float* sbp = Sc + (size_t)bh * Sq * Sq;

    __shared__ float Qs[DKh][64];
    __shared__ float Ks[DKh][64];

    const int q0 = blockIdx.y * 64, k0 = blockIdx.x * 64;
    const int tid = threadIdx.x;
    const int lr = tid / 16, lc = (tid % 16) * 4;
#pragma unroll
    for (int r = lr; r < 64; r += 16) {
        float4 v = *reinterpret_cast<const float4*>(&qb[(size_t)(q0 + r) * QKVLD + lc]);
        Qs[lc + 0][r] = v.x; Qs[lc + 1][r] = v.y; Qs[lc + 2][r] = v.z; Qs[lc + 3][r] = v.w;
        float4 w = *reinterpret_cast<const float4*>(&kb[(size_t)(k0 + r) * QKVLD + lc]);
        Ks[lc + 0][r] = w.x; Ks[lc + 1][r] = w.y; Ks[lc + 2][r] = w.z; Ks[lc + 3][r] = w.w;
    }
    __syncthreads();

    const int tcol = tid % 16, trow = tid / 16;
    float acc[4][4] = {};
#pragma unroll
    for (int d = 0; d < DKh; d++) {
        float ra[4], rb[4];
#pragma unroll
        for (int i = 0; i < 4; i++) ra[i] = Qs[d][trow * 4 + i];
#pragma unroll
        for (int j = 0; j < 4; j++) rb[j] = Ks[d][tcol * 4 + j];
#pragma unroll
        for (int i = 0; i < 4; i++)
#pragma unroll
            for (int j = 0; j < 4; j++) acc[i][j] += ra[i] * rb[j];
    }
#pragma unroll
    for (int i = 0; i < 4; i++)
#pragma unroll
        for (int j = 0; j < 4; j++)
            sbp[(size_t)(q0 + trow * 4 + i) * Sq + k0 + tcol * 4 + j] = acc[i][j] * 0.125f;
}

__global__ void softmax_kernel(float* __restrict__ s) {
    float* p = s + (size_t)blockIdx.x * Sq;
    int t = threadIdx.x;
    float a = p[t], b = p[t + 256];
    __shared__ float sh[32];
    float m = blockReduceMax(fmaxf(a, b), sh);
    float e0 = __expf(a - m), e1 = __expf(b - m);
    float sum = blockReduceSum(e0 + e1, sh);
    float inv = 1.0f / sum;
    p[t] = e0 * inv;
    p[t + 256] = e1 * inv;
}

__global__ __launch_bounds__(256)
void attn_av(const float* __restrict__ Sc, const float* __restrict__ QKV,
             float* __restrict__ O) {
    const int bh = blockIdx.z;
    const int b = bh / Hn, h = bh % Hn;
    const float* sbp = Sc + (size_t)bh * Sq * Sq;
    const float* vb = QKV + (size_t)b * Sq * QKVLD + 1024 + h * DKh;
    float* ob = O + (size_t)b * Sq * Dm + h * DKh;

    __shared__ float As[64][64];
    __shared__ float Bs[64][64];

    const int q0 = blockIdx.y * 64;
    const int tid = threadIdx.x;
    const int lr = tid / 16, lc = (tid % 16) * 4;
    const int tcol = tid % 16, trow = tid / 16;

    float acc[4][4] = {};
    for (int kk = 0; kk < Sq; kk += 64) {
#pragma unroll
        for (int r = lr; r < 64; r += 16) {
            float4 v = *reinterpret_cast<const float4*>(&sbp[(size_t)(q0 + r) * Sq + kk + lc]);
            As[lc + 0][r] = v.x; As[lc + 1][r] = v.y; As[lc + 2][r] = v.z; As[lc + 3][r] = v.w;
            float4 w = *reinterpret_cast<const float4*>(&vb[(size_t)(kk + r) * QKVLD + lc]);
            *reinterpret_cast<float4*>(&Bs[r][lc]) = w;
        }
        __syncthreads();
#pragma unroll
        for (int k = 0; k < 64; k++) {
            float ra[4], rb[4];
#pragma unroll
            for (int i = 0; i < 4; i++) ra[i] = As[k][trow * 4 + i];
#pragma unroll
            for (int j = 0; j < 4; j++) rb[j] = Bs[k][tcol * 4 + j];
#pragma unroll
            for (int i = 0; i < 4; i++)
#pragma unroll
                for (int j = 0; j < 4; j++) acc[i][j] += ra[i] * rb[j];
        }
        __syncthreads();
    }
#pragma unroll
    for (int i = 0; i < 4; i++)
#pragma unroll
        for (int j = 0; j < 4; j++)
            ob[(size_t)(q0 + trow * 4 + i) * Dm + tcol * 4 + j] = acc[i][j];
}

__global__ void ln_kernel(const float* __restrict__ a, const float* __restrict__ res,
                          const float* __restrict__ g, const float* __restrict__ beta,
                          float* __restrict__ out) {
    const size_t row = blockIdx.x;
    const int t = threadIdx.x;
    float v0 = a[row * Dm + t], v1 = a[row * Dm + t + 256];
    if (res) { v0 += res[row * Dm + t]; v1 += res[row * Dm + t + 256]; }
    __shared__ float sh[32];
    float s = blockReduceSum(v0 + v1, sh);
    float mean = s * (1.0f / Dm);
    float d0 = v0 - mean, d1 = v1 - mean;
    float ss = blockReduceSum(d0 * d0 + d1 * d1, sh);
    float inv = rsqrtf(ss * (1.0f / Dm) + 1e-5f);
    out[row * Dm + t]       = d0 * inv * g[t] + beta[t];
    out[row * Dm + t + 256] = d1 * inv * g[t + 256] + beta[t + 256];
}

// ================= orchestration =================
extern "C" void kernel_launch(void* const* d_in, const int* in_sizes, int n_in,
                              void* d_out, int out_size) {
    const int*   ids  = (const int*)  d_in[0];
    const float* tok  = (const float*)d_in[1];
    const float* pos  = (const float*)d_in[2];
    const float* Wq   = (const float*)d_in[3];
    const float* bq   = (const float*)d_in[4];
    const float* Wk   = (const float*)d_in[5];
    const float* bk   = (const float*)d_in[6];
    const float* Wv   = (const float*)d_in[7];
    const float* bv   = (const float*)d_in[8];
    const float* Wo   = (const float*)d_in[9];
    const float* bo   = (const float*)d_in[10];
    const float* ln_g = (const float*)d_in[11];
    const float* ln_b = (const float*)d_in[12];
    const float* W1   = (const float*)d_in[13];
    const float* b1   = (const float*)d_in[14];
    const float* W2   = (const float*)d_in[15];
    const float* b2   = (const float*)d_in[16];
    const float* on_g = (const float*)d_in[17];
    const float* on_b = (const float*)d_in[18];
    const float* Wout = (const float*)d_in[19];
    const float* bout = (const float*)d_in[20];
    float* out = (float*)d_out;

    float *x, *qkv, *t, *tmp, *sc, *ff, *wqkv, *wo, *w1, *w2, *wout, *bqkv;
    cudaGetSymbolAddress((void**)&x,    g_x);
    cudaGetSymbolAddress((void**)&qkv,  g_qkv);
    cudaGetSymbolAddress((void**)&t,    g_t);
    cudaGetSymbolAddress((void**)&tmp,  g_tmp);
    cudaGetSymbolAddress((void**)&sc,   g_sc);
    cudaGetSymbolAddress((void**)&ff,   g_ff);
    cudaGetSymbolAddress((void**)&wqkv, g_wqkv);
    cudaGetSymbolAddress((void**)&wo,   g_wo);
    cudaGetSymbolAddress((void**)&w1,   g_w1);
    cudaGetSymbolAddress((void**)&w2,   g_w2);
    cudaGetSymbolAddress((void**)&wout, g_wout);
    cudaGetSymbolAddress((void**)&bqkv, g_bqkv);

    // ---- weight preprocessing (tf32 rounding, concat, pad) ----
    {
        size_t n4;
        n4 = (size_t)Lyr * Dm * (QKVLD / 4);
        build_wqkv<<<(unsigned)((n4 + 255) / 256), 256>>>(Wq, Wk, Wv, wqkv);
        n4 = (size_t)Lyr * Dm * Dm / 4;
        cvt_copy<<<(unsigned)((n4 + 255) / 256), 256>>>(Wo, wo, n4);
        n4 = (size_t)Dm * DFFn / 4;
        cvt_copy<<<(unsigned)((n4 + 255) / 256), 256>>>(W1, w1, n4);
        cvt_copy<<<(unsigned)((n4 + 255) / 256), 256>>>(W2, w2, n4);
        pad_cvt_wout<<<4096, 256>>>(Wout, wout);
        concat_bias<<<(Lyr * QKVLD + 255) / 256, 256>>>(bq, bk, bv, bqkv);
    }

    embed_kernel<<<NTOK, 128>>>(ids, tok, pos, x);

    const dim3 gScores(Sq / 64, Sq / 64, Bsz * Hn);
    const dim3 gAV(1, Sq / 64, Bsz * Hn);

    for (int l = 0; l < Lyr; l++) {
        const size_t bOff = (size_t)l * Dm;
        // fused QKV: [2048,512] @ [512,1536]
        gemm_wmma<0><<<dim3(QKVLD / 128, NTOK / 128), 256>>>(
            Dm, x, wqkv + (size_t)l * Dm * QKVLD, QKVLD,
            bqkv + (size_t)l * QKVLD, qkv, QKVLD, QKVLD);

        attn_scores<<<gScores, 256>>>(qkv, sc);
        softmax_kernel<<<Bsz * Hn * Sq, 256>>>(sc);
        attn_av<<<gAV, 256>>>(sc, qkv, t);

        gemm_wmma<0><<<dim3(Dm / 128, NTOK / 128), 256>>>(
            Dm, t, wo + (size_t)l * Dm * Dm, Dm, bo + bOff, tmp, Dm, Dm);
        ln_kernel<<<NTOK, 256>>>(x, tmp, ln_g + bOff, ln_b + bOff, x);
    }

    // FFN
    gemm_wmma<1><<<dim3(DFFn / 128, NTOK / 128), 256>>>(Dm, x, w1, DFFn, b1, ff, DFFn, DFFn);
    gemm_wmma<0><<<dim3(Dm / 128, NTOK / 128), 256>>>(DFFn, ff, w2, Dm, b2, t, Dm, Dm);
    ln_kernel<<<NTOK, 256>>>(t, nullptr, on_g, on_b, x);

    // logits: [2048,512] @ [512,50304], store cols < 50257
    gemm_wmma<0><<<dim3(VPAD / 128, NTOK / 128), 256>>>(
        Dm, x, wout, VPAD, bout, out, VOCn, VOCn);
}

// round 4
// speedup vs baseline: 1.5017x; 1.1389x over previous
#include <cuda_runtime.h>
#include <mma.h>
#include <cstdint>
#include <math.h>

using namespace nvcuda;

#define Bsz 4
#define Sq 512
#define Dm 512
#define Hn 8
#define DKh 64
#define Lyr 6
#define DFFn 2048
#define VOCn 50257
#define NTOK (Bsz*Sq)      // 2048
#define VPAD 50304
#define QKVLD 1536

// ---------------- helpers ----------------
__device__ __forceinline__ uint32_t smem_u32(const void* p) {
    uint32_t a;
    asm("{ .reg .u64 t; cvta.to.shared.u64 t, %1; cvt.u32.u64 %0, t; }" : "=r"(a) : "l"(p));
    return a;
}
__device__ __forceinline__ float f32_tf32(float f) {
    uint32_t u;
    asm("cvt.rna.tf32.f32 %0, %1;" : "=r"(u) : "f"(f));
    return __uint_as_float(u);
}
#define CP_ASYNC16(dst, src) \
    asm volatile("cp.async.cg.shared.global [%0], [%1], 16;" :: "r"(dst), "l"(src))
#define CP_COMMIT()  asm volatile("cp.async.commit_group;" ::: "memory")
#define CP_WAIT(n)   asm volatile("cp.async.wait_group %0;" :: "n"(n) : "memory")

// ---------------- device scratch ----------------
__device__ float g_x[NTOK*Dm];
__device__ float g_qkv[(size_t)NTOK*QKVLD];
__device__ float g_t[NTOK*Dm];
__device__ float g_tmp[NTOK*Dm];
__device__ float g_sc[(size_t)Bsz*Hn*Sq*Sq];
__device__ float g_ff[(size_t)NTOK*DFFn];
__device__ float g_wqkv[(size_t)Lyr*Dm*QKVLD];
__device__ float g_wo[(size_t)Lyr*Dm*Dm];
__device__ float g_w1[(size_t)Dm*DFFn];
__device__ float g_w2[(size_t)DFFn*Dm];
__device__ float g_wout[(size_t)Dm*VPAD];
__device__ float g_bqkv[Lyr*QKVLD];

// ---------------- reductions ----------------
__device__ __forceinline__ float blockReduceSum(float v, float* sh) {
    int lane = threadIdx.x & 31, w = threadIdx.x >> 5;
#pragma unroll
    for (int o = 16; o; o >>= 1) v += __shfl_xor_sync(0xffffffffu, v, o);
    if (!lane) sh[w] = v;
    __syncthreads();
    if (threadIdx.x < 8) {
        v = sh[threadIdx.x];
#pragma unroll
        for (int o = 4; o; o >>= 1) v += __shfl_xor_sync(0xffu, v, o);
        if (!threadIdx.x) sh[0] = v;
    }
    __syncthreads();
    float r = sh[0];
    __syncthreads();
    return r;
}
__device__ __forceinline__ float blockReduceMax(float v, float* sh) {
    int lane = threadIdx.x & 31, w = threadIdx.x >> 5;
#pragma unroll
    for (int o = 16; o; o >>= 1) v = fmaxf(v, __shfl_xor_sync(0xffffffffu, v, o));
    if (!lane) sh[w] = v;
    __syncthreads();
    if (threadIdx.x < 8) {
        v = sh[threadIdx.x];
#pragma unroll
        for (int o = 4; o; o >>= 1) v = fmaxf(v, __shfl_xor_sync(0xffu, v, o));
        if (!threadIdx.x) sh[0] = v;
    }
    __syncthreads();
    float r = sh[0];
    __syncthreads();
    return r;
}

// ---------------- small kernels ----------------
__global__ void embed_kernel(const int* __restrict__ ids,
                             const float* __restrict__ tok,
                             const float* __restrict__ pos,
                             float* __restrict__ x) {
    int row = blockIdx.x;
    int s = row % Sq;
    int id = ids[row];
    const float4* t4 = reinterpret_cast<const float4*>(tok) + (size_t)id * (Dm / 4);
    const float4* p4 = reinterpret_cast<const float4*>(pos) + (size_t)s * (Dm / 4);
    float4* x4 = reinterpret_cast<float4*>(x) + (size_t)row * (Dm / 4);
    int t = threadIdx.x;
    float4 a = t4[t], b = p4[t];
    a.x = f32_tf32(a.x + b.x); a.y = f32_tf32(a.y + b.y);
    a.z = f32_tf32(a.z + b.z); a.w = f32_tf32(a.w + b.w);
    x4[t] = a;
}

__global__ void cvt_copy(const float* __restrict__ in, float* __restrict__ out, size_t n4) {
    size_t i = (size_t)blockIdx.x * blockDim.x + threadIdx.x;
    if (i >= n4) return;
    float4 v = reinterpret_cast<const float4*>(in)[i];
    v.x = f32_tf32(v.x); v.y = f32_tf32(v.y); v.z = f32_tf32(v.z); v.w = f32_tf32(v.w);
    reinterpret_cast<float4*>(out)[i] = v;
}

__global__ void build_wqkv(const float* __restrict__ Wq, const float* __restrict__ Wk,
                           const float* __restrict__ Wv, float* __restrict__ out) {
    size_t i = (size_t)blockIdx.x * blockDim.x + threadIdx.x;
    size_t total = (size_t)Lyr * Dm * (QKVLD / 4);
    if (i >= total) return;
    size_t n4 = i % (QKVLD / 4);
    size_t k  = (i / (QKVLD / 4)) % Dm;
    size_t l  = i / ((size_t)(QKVLD / 4) * Dm);
    const float* src = (n4 < 128) ? Wq : (n4 < 256) ? Wk : Wv;
    size_t nn = (n4 % 128) * 4;
    float4 v = *reinterpret_cast<const float4*>(&src[(l * Dm + k) * Dm + nn]);
    v.x = f32_tf32(v.x); v.y = f32_tf32(v.y); v.z = f32_tf32(v.z); v.w = f32_tf32(v.w);
    reinterpret_cast<float4*>(out)[i] = v;
}

__global__ void pad_cvt_wout(const float* __restrict__ src, float* __restrict__ dst) {
    const size_t total = (size_t)Dm * VPAD;
    for (size_t i = (size_t)blockIdx.x * blockDim.x + threadIdx.x; i < total;
         i += (size_t)gridDim.x * blockDim.x) {
        size_t r = i / VPAD, c = i % VPAD;
        dst[i] = (c < VOCn) ? f32_tf32(src[r * VOCn + c]) : 0.f;
    }
}

__global__ void concat_bias(const float* __restrict__ bq, const float* __restrict__ bk,
                            const float* __restrict__ bv, float* __restrict__ o) {
    int i = blockIdx.x * blockDim.x + threadIdx.x;
    if (i >= Lyr * QKVLD) return;
    int l = i / QKVLD, j = i % QKVLD;
    float v = (j < 512) ? bq[l * 512 + j] : (j < 1024) ? bk[l * 512 + j - 512]
                                                       : bv[l * 512 + j - 1024];
    o[i] = v;
}

// ================= wmma tf32 GEMM, 3-stage cp.async =================
// C[M,ldc](cols<Nc) = act(A[M,K] @ W[K,ldw] + bias). A,W pre-rounded tf32.
// block 128x128, BK=16, 256 thr, 8 warps (4 x 2), warp tile 32x64.
#define GSM_A_FLOATS (3*128*20)          // 7680
#define GSM_B_FLOATS (3*16*132)          // 6336
#define GSM_BYTES ((GSM_A_FLOATS + GSM_B_FLOATS) * 4)   // 56064

template <int ACT, int RND, int VEC>
__global__ __launch_bounds__(256, 2)
void gemm_wmma(int K, const float* __restrict__ A,
               const float* __restrict__ W, int ldw,
               const float* __restrict__ bias,
               float* __restrict__ C, int ldc, int Nc) {
    extern __shared__ float smem[];
    float* As = smem;                       // [3][128][20]
    float* Bs = smem + GSM_A_FLOATS;        // [3][16][132]
    const uint32_t sb = smem_u32(smem);
    const uint32_t sbB = sb + GSM_A_FLOATS * 4;

    const int tid = threadIdx.x;
    const int wid = tid >> 5;
    const int wm = wid & 3, wn = wid >> 2;
    const int crow = blockIdx.y * 128;
    const int ccol = blockIdx.x * 128;

    wmma::fragment<wmma::accumulator, 16, 16, 8, float> acc[2][4];
#pragma unroll
    for (int i = 0; i < 2; i++)
#pragma unroll
        for (int j = 0; j < 4; j++) wmma::fill_fragment(acc[i][j], 0.f);

    const float* Ab = A + (size_t)crow * K;
    const int T = K >> 4;

    // per-thread cp.async coordinates
    const int aRow0 = tid >> 1, aSeg0 = (tid & 1) * 2;      // 2 chunks: rows tid>>1, segs {s, s+1}? use idx scheme below
    (void)aRow0; (void)aSeg0;

    auto issue_stage = [&](int st, int t) {
        const int k0 = t << 4;
        // A: 512 chunks of 16B
#pragma unroll
        for (int rep = 0; rep < 2; rep++) {
            int c = rep * 256 + tid;
            int row = c >> 2, seg = c & 3;
            CP_ASYNC16(sb + ((st * 128 + row) * 20 + seg * 4) * 4,
                       &Ab[(size_t)row * K + k0 + seg * 4]);
        }
        // B: 512 chunks of 16B
#pragma unroll
        for (int rep = 0; rep < 2; rep++) {
            int c = rep * 256 + tid;
            int row = c >> 5, seg = c & 31;
            CP_ASYNC16(sbB + ((st * 16 + row) * 132 + seg * 4) * 4,
                       &W[(size_t)(k0 + row) * ldw + ccol + seg * 4]);
        }
        CP_COMMIT();
    };

    issue_stage(0, 0);
    issue_stage(1, 1);

    for (int t = 0; t < T; t++) {
        if (t + 2 < T) issue_stage((t + 2) % 3, t + 2);
        CP_WAIT(2);
        __syncthreads();
        const int st = t % 3;
        float* Ast = As + st * 128 * 20;
        float* Bst = Bs + st * 16 * 132;
#pragma unroll
        for (int ks = 0; ks < 2; ks++) {
            wmma::fragment<wmma::matrix_a, 16, 16, 8, wmma::precision::tf32, wmma::row_major> af[2];
            wmma::fragment<wmma::matrix_b, 16, 16, 8, wmma::precision::tf32, wmma::row_major> bf[4];
            wmma::load_matrix_sync(af[0], Ast + (wm * 32) * 20 + ks * 8, 20);
            wmma::load_matrix_sync(af[1], Ast + (wm * 32 + 16) * 20 + ks * 8, 20);
#pragma unroll
            for (int j = 0; j < 4; j++)
                wmma::load_matrix_sync(bf[j], Bst + (ks * 8) * 132 + wn * 64 + j * 16, 132);
#pragma unroll
            for (int i = 0; i < 2; i++)
#pragma unroll
                for (int j = 0; j < 4; j++)
                    wmma::mma_sync(acc[i][j], af[i], bf[j], acc[i][j]);
        }
        __syncthreads();
    }

    // ---- epilogue: stage 64x128 per pass in reused smem ----
    float* stg = smem;   // [8][16][68] floats, 34816 B < 56064 B
#pragma unroll
    for (int i = 0; i < 2; i++) {
        __syncthreads();
#pragma unroll
        for (int j = 0; j < 4; j++)
            wmma::store_matrix_sync(stg + wid * 1088 + j * 16, acc[i][j], 68, wmma::mem_row_major);
        __syncthreads();
#pragma unroll
        for (int it = 0; it < 8; it++) {
            int idx = it * 256 + tid;          // 2048 float4 positions
            int r = idx >> 5;                   // 0..63
            int c4 = (idx & 31) * 4;            // 0..124
            int wmg = r >> 4, rr = r & 15;
            int wng = c4 >> 6, cc = c4 & 63;
            const float* sp = stg + (wng * 4 + wmg) * 1088 + rr * 68 + cc;
            int row = crow + wmg * 32 + i * 16 + rr;
            int colb = ccol + c4;
            float4 bvv = *reinterpret_cast<const float4*>(&bias[colb]);
            float v0 = sp[0] + bvv.x, v1 = sp[1] + bvv.y;
            float v2 = sp[2] + bvv.z, v3 = sp[3] + bvv.w;
            if (ACT == 1) {
                v0 = 0.5f * v0 * (1.0f + erff(v0 * 0.70710678118654752f));
                v1 = 0.5f * v1 * (1.0f + erff(v1 * 0.70710678118654752f));
                v2 = 0.5f * v2 * (1.0f + erff(v2 * 0.70710678118654752f));
                v3 = 0.5f * v3 * (1.0f + erff(v3 * 0.70710678118654752f));
            }
            if (RND == 1) {
                v0 = f32_tf32(v0); v1 = f32_tf32(v1);
                v2 = f32_tf32(v2); v3 = f32_tf32(v3);
            }
            if (VEC == 1) {
                *reinterpret_cast<float4*>(&C[(size_t)row * ldc + colb]) =
                    make_float4(v0, v1, v2, v3);
            } else {
                float* cp = &C[(size_t)row * ldc + colb];
                if (colb + 0 < Nc) cp[0] = v0;
                if (colb + 1 < Nc) cp[1] = v1;
                if (colb + 2 < Nc) cp[2] = v2;
                if (colb + 3 < Nc) cp[3] = v3;
            }
        }
    }
}

// ================= wmma attention =================
// scores[bh,q,k] = 0.125 * Q.K  — direct-from-global fragments
__global__ __launch_bounds__(128)
void attn_scores_wmma(const float* __restrict__ QKV, float* __restrict__ Sc) {
    const int bh = blockIdx.z;
    const int b = bh / Hn, h = bh % Hn;
    const float* qb = QKV + (size_t)b * Sq * QKVLD + h * DKh;
    const float* kb = QKV + (size_t)b * Sq * QKVLD + 512 + h * DKh;
    float* sbp = Sc + (size_t)bh * Sq * Sq;
    const int q0 = blockIdx.y * 64, k0 = blockIdx.x * 64;
    const int wid = threadIdx.x >> 5;
    const int wm = wid & 1, wn = wid >> 1;   // 2x2 warps, warp tile 32x32

    wmma::fragment<wmma::accumulator, 16, 16, 8, float> acc[2][2];
#pragma unroll
    for (int i = 0; i < 2; i++)
#pragma unroll
        for (int j = 0; j < 2; j++) wmma::fill_fragment(acc[i][j], 0.f);

#pragma unroll
    for (int d0 = 0; d0 < DKh; d0 += 8) {
        wmma::fragment<wmma::matrix_a, 16, 16, 8, wmma::precision::tf32, wmma::row_major> af[2];
        wmma::fragment<wmma::matrix_b, 16, 16, 8, wmma::precision::tf32, wmma::col_major> bf[2];
#pragma unroll
        for (int i = 0; i < 2; i++)
            wmma::load_matrix_sync(af[i], &qb[(size_t)(q0 + wm * 32 + i * 16) * QKVLD + d0], QKVLD);
#pragma unroll
        for (int j = 0; j < 2; j++)
            wmma::load_matrix_sync(bf[j], &kb[(size_t)(k0 + wn * 32 + j * 16) * QKVLD + d0], QKVLD);
#pragma unroll
        for (int i = 0; i < 2; i++)
#pragma unroll
            for (int j = 0; j < 2; j++)
                wmma::mma_sync(acc[i][j], af[i], bf[j], acc[i][j]);
    }
#pragma unroll
    for (int i = 0; i < 2; i++)
#pragma unroll
        for (int j = 0; j < 2; j++) {
#pragma unroll
            for (int e = 0; e < acc[i][j].num_elements; e++) acc[i][j].x[e] *= 0.125f;
            wmma::store_matrix_sync(
                &sbp[(size_t)(q0 + wm * 32 + i * 16) * Sq + k0 + wn * 32 + j * 16],
                acc[i][j], Sq, wmma::mem_row_major);
        }
}

__global__ void softmax_kernel(float* __restrict__ s) {
    float* p = s + (size_t)blockIdx.x * Sq;
    int t = threadIdx.x;
    float a = p[t], b = p[t + 256];
    __shared__ float sh[32];
    float m = blockReduceMax(fmaxf(a, b), sh);
    float e0 = __expf(a - m), e1 = __expf(b - m);
    float sum = blockReduceSum(e0 + e1, sh);
    float inv = 1.0f / sum;
    p[t]       = f32_tf32(e0 * inv);
    p[t + 256] = f32_tf32(e1 * inv);
}

// O = P @ V  (P tf32-rounded by softmax, V rounded by qkv epilogue)
__global__ __launch_bounds__(128)
void attn_av_wmma(const float* __restrict__ Sc, const float* __restrict__ QKV,
                  float* __restrict__ O) {
    const int bh = blockIdx.z;
    const int b = bh / Hn, h = bh % Hn;
    const float* sbp = Sc + (size_t)bh * Sq * Sq;
    const float* vb = QKV + (size_t)b * Sq * QKVLD + 1024 + h * DKh;
    float* ob = O + (size_t)b * Sq * Dm + h * DKh;
    const int q0 = blockIdx.y * 64;
    const int wid = threadIdx.x >> 5;
    const int wm = wid & 1, wn = wid >> 1;   // 2x2, warp 32(q) x 32(d)

    wmma::fragment<wmma::accumulator, 16, 16, 8, float> acc[2][2];
#pragma unroll
    for (int i = 0; i < 2; i++)
#pragma unroll
        for (int j = 0; j < 2; j++) wmma::fill_fragment(acc[i][j], 0.f);

    for (int k0 = 0; k0 < Sq; k0 += 8) {
        wmma::fragment<wmma::matrix_a, 16, 16, 8, wmma::precision::tf32, wmma::row_major> af[2];
        wmma::fragment<wmma::matrix_b, 16, 16, 8, wmma::precision::tf32, wmma::row_major> bf[2];
#pragma unroll
        for (int i = 0; i < 2; i++)
            wmma::load_matrix_sync(af[i], &sbp[(size_t)(q0 + wm * 32 + i * 16) * Sq + k0], Sq);
#pragma unroll
        for (int j = 0; j < 2; j++)
            wmma::load_matrix_sync(bf[j], &vb[(size_t)k0 * QKVLD + wn * 32 + j * 16], QKVLD);
#pragma unroll
        for (int i = 0; i < 2; i++)
#pragma unroll
            for (int j = 0; j < 2; j++)
                wmma::mma_sync(acc[i][j], af[i], bf[j], acc[i][j]);
    }
#pragma unroll
    for (int i = 0; i < 2; i++)
#pragma unroll
        for (int j = 0; j < 2; j++) {
#pragma unroll
            for (int e = 0; e < acc[i][j].num_elements; e++)
                acc[i][j].x[e] = f32_tf32(acc[i][j].x[e]);
            wmma::store_matrix_sync(
                &ob[(size_t)(q0 + wm * 32 + i * 16) * Dm + wn * 32 + j * 16],
                acc[i][j], Dm, wmma::mem_row_major);
        }
}

__global__ void ln_kernel(const float* __restrict__ a, const float* __restrict__ res,
                          const float* __restrict__ g, const float* __restrict__ beta,
                          float* __restrict__ out) {
    const size_t row = blockIdx.x;
    const int t = threadIdx.x;
    float v0 = a[row * Dm + t], v1 = a[row * Dm + t + 256];
    if (res) { v0 += res[row * Dm + t]; v1 += res[row * Dm + t + 256]; }
    __shared__ float sh[32];
    float s = blockReduceSum(v0 + v1, sh);
    float mean = s * (1.0f / Dm);
    float d0 = v0 - mean, d1 = v1 - mean;
    float ss = blockReduceSum(d0 * d0 + d1 * d1, sh);
    float inv = rsqrtf(ss * (1.0f / Dm) + 1e-5f);
    out[row * Dm + t]       = f32_tf32(d0 * inv * g[t] + beta[t]);
    out[row * Dm + t + 256] = f32_tf32(d1 * inv * g[t + 256] + beta[t + 256]);
}

// ================= orchestration =================
extern "C" void kernel_launch(void* const* d_in, const int* in_sizes, int n_in,
                              void* d_out, int out_size) {
    const int*   ids  = (const int*)  d_in[0];
    const float* tok  = (const float*)d_in[1];
    const float* pos  = (const float*)d_in[2];
    const float* Wq   = (const float*)d_in[3];
    const float* bq   = (const float*)d_in[4];
    const float* Wk   = (const float*)d_in[5];
    const float* bk   = (const float*)d_in[6];
    const float* Wv   = (const float*)d_in[7];
    const float* bv   = (const float*)d_in[8];
    const float* Wo   = (const float*)d_in[9];
    const float* bo   = (const float*)d_in[10];
    const float* ln_g = (const float*)d_in[11];
    const float* ln_b = (const float*)d_in[12];
    const float* W1   = (const float*)d_in[13];
    const float* b1   = (const float*)d_in[14];
    const float* W2   = (const float*)d_in[15];
    const float* b2   = (const float*)d_in[16];
    const float* on_g = (const float*)d_in[17];
    const float* on_b = (const float*)d_in[18];
    const float* Wout = (const float*)d_in[19];
    const float* bout = (const float*)d_in[20];
    float* out = (float*)d_out;

    float *x, *qkv, *t, *tmp, *sc, *ff, *wqkv, *wo, *w1, *w2, *wout, *bqkv;
    cudaGetSymbolAddress((void**)&x,    g_x);
    cudaGetSymbolAddress((void**)&qkv,  g_qkv);
    cudaGetSymbolAddress((void**)&t,    g_t);
    cudaGetSymbolAddress((void**)&tmp,  g_tmp);
    cudaGetSymbolAddress((void**)&sc,   g_sc);
    cudaGetSymbolAddress((void**)&ff,   g_ff);
    cudaGetSymbolAddress((void**)&wqkv, g_wqkv);
    cudaGetSymbolAddress((void**)&wo,   g_wo);
    cudaGetSymbolAddress((void**)&w1,   g_w1);
    cudaGetSymbolAddress((void**)&w2,   g_w2);
    cudaGetSymbolAddress((void**)&wout, g_wout);
    cudaGetSymbolAddress((void**)&bqkv, g_bqkv);

    // opt into 56KB dynamic smem for all gemm instantiations (idempotent)
    cudaFuncSetAttribute(gemm_wmma<0,1,1>, cudaFuncAttributeMaxDynamicSharedMemorySize, GSM_BYTES);
    cudaFuncSetAttribute(gemm_wmma<0,0,1>, cudaFuncAttributeMaxDynamicSharedMemorySize, GSM_BYTES);
    cudaFuncSetAttribute(gemm_wmma<1,1,1>, cudaFuncAttributeMaxDynamicSharedMemorySize, GSM_BYTES);
    cudaFuncSetAttribute(gemm_wmma<0,0,0>, cudaFuncAttributeMaxDynamicSharedMemorySize, GSM_BYTES);

    // ---- weight preprocessing ----
    {
        size_t n4;
        n4 = (size_t)Lyr * Dm * (QKVLD / 4);
        build_wqkv<<<(unsigned)((n4 + 255) / 256), 256>>>(Wq, Wk, Wv, wqkv);
        n4 = (size_t)Lyr * Dm * Dm / 4;
        cvt_copy<<<(unsigned)((n4 + 255) / 256), 256>>>(Wo, wo, n4);
        n4 = (size_t)Dm * DFFn / 4;
        cvt_copy<<<(unsigned)((n4 + 255) / 256), 256>>>(W1, w1, n4);
        cvt_copy<<<(unsigned)((n4 + 255) / 256), 256>>>(W2, w2, n4);
        pad_cvt_wout<<<4096, 256>>>(Wout, wout);
        concat_bias<<<(Lyr * QKVLD + 255) / 256, 256>>>(bq, bk, bv, bqkv);
    }

    embed_kernel<<<NTOK, 128>>>(ids, tok, pos, x);

    const dim3 gScores(Sq / 64, Sq / 64, Bsz * Hn);
    const dim3 gAV(1, Sq / 64, Bsz * Hn);

    for (int l = 0; l < Lyr; l++) {
        const size_t bOff = (size_t)l * Dm;
        gemm_wmma<0,1,1><<<dim3(QKVLD / 128, NTOK / 128), 256, GSM_BYTES>>>(
            Dm, x, wqkv + (size_t)l * Dm * QKVLD, QKVLD,
            bqkv + (size_t)l * QKVLD, qkv, QKVLD, QKVLD);

        attn_scores_wmma<<<gScores, 128>>>(qkv, sc);
        softmax_kernel<<<Bsz * Hn * Sq, 256>>>(sc);
        attn_av_wmma<<<gAV, 128>>>(sc, qkv, t);

        gemm_wmma<0,0,1><<<dim3(Dm / 128, NTOK / 128), 256, GSM_BYTES>>>(
            Dm, t, wo + (size_t)l * Dm * Dm, Dm, bo + bOff, tmp, Dm, Dm);
        ln_kernel<<<NTOK, 256>>>(x, tmp, ln_g + bOff, ln_b + bOff, x);
    }

    // FFN
    gemm_wmma<1,1,1><<<dim3(DFFn / 128, NTOK / 128), 256, GSM_BYTES>>>(
        Dm, x, w1, DFFn, b1, ff, DFFn, DFFn);
    gemm_wmma<0,0,1><<<dim3(Dm / 128, NTOK / 128), 256, GSM_BYTES>>>(
        DFFn, ff, w2, Dm, b2, t, Dm, Dm);
    ln_kernel<<<NTOK, 256>>>(t, nullptr, on_g, on_b, x);

    // logits
    gemm_wmma<0,0,0><<<dim3(VPAD / 128, NTOK / 128), 256, GSM_BYTES>>>(
        Dm, x, wout, VPAD, bout, out, VOCn, VOCn);
}

// round 5
// speedup vs baseline: 1.6152x; 1.0756x over previous
#include <cuda_runtime.h>
#include <mma.h>
#include <cstdint>
#include <math.h>

using namespace nvcuda;

#define Bsz 4
#define Sq 512
#define Dm 512
#define Hn 8
#define DKh 64
#define Lyr 6
#define DFFn 2048
#define VOCn 50257
#define NTOK (Bsz*Sq)      // 2048
#define VPAD 50432         // 197*256
#define QKVLD 1536

// ---------------- helpers ----------------
__device__ __forceinline__ uint32_t smem_u32(const void* p) {
    uint32_t a;
    asm("{ .reg .u64 t; cvta.to.shared.u64 t, %1; cvt.u32.u64 %0, t; }" : "=r"(a) : "l"(p));
    return a;
}
__device__ __forceinline__ float f32_tf32(float f) {
    uint32_t u;
    asm("cvt.rna.tf32.f32 %0, %1;" : "=r"(u) : "f"(f));
    return __uint_as_float(u);
}
#define CP_ASYNC16(dst, src) \
    asm volatile("cp.async.cg.shared.global [%0], [%1], 16;" :: "r"(dst), "l"(src))
#define CP_COMMIT()  asm volatile("cp.async.commit_group;" ::: "memory")
#define CP_WAIT(n)   asm volatile("cp.async.wait_group %0;" :: "n"(n) : "memory")

// ---------------- device scratch ----------------
__device__ float g_x[NTOK*Dm];
__device__ float g_qkv[(size_t)NTOK*QKVLD];
__device__ float g_t[NTOK*Dm];
__device__ float g_tmp[NTOK*Dm];
__device__ float g_sc[(size_t)Bsz*Hn*Sq*Sq];
__device__ float g_ff[(size_t)NTOK*DFFn];
__device__ float g_wqkv[(size_t)Lyr*Dm*QKVLD];
__device__ float g_wo[(size_t)Lyr*Dm*Dm];
__device__ float g_w1[(size_t)Dm*DFFn];
__device__ float g_w2[(size_t)DFFn*Dm];
__device__ float g_wout[(size_t)Dm*VPAD];
__device__ float g_bqkv[Lyr*QKVLD];
__device__ float g_bout[VPAD];

// ---------------- reductions ----------------
__device__ __forceinline__ float blockReduceSum(float v, float* sh) {
    int lane = threadIdx.x & 31, w = threadIdx.x >> 5;
#pragma unroll
    for (int o = 16; o; o >>= 1) v += __shfl_xor_sync(0xffffffffu, v, o);
    if (!lane) sh[w] = v;
    __syncthreads();
    if (threadIdx.x < 8) {
        v = sh[threadIdx.x];
#pragma unroll
        for (int o = 4; o; o >>= 1) v += __shfl_xor_sync(0xffu, v, o);
        if (!threadIdx.x) sh[0] = v;
    }
    __syncthreads();
    float r = sh[0];
    __syncthreads();
    return r;
}
__device__ __forceinline__ float blockReduceMax(float v, float* sh) {
    int lane = threadIdx.x & 31, w = threadIdx.x >> 5;
#pragma unroll
    for (int o = 16; o; o >>= 1) v = fmaxf(v, __shfl_xor_sync(0xffffffffu, v, o));
    if (!lane) sh[w] = v;
    __syncthreads();
    if (threadIdx.x < 8) {
        v = sh[threadIdx.x];
#pragma unroll
        for (int o = 4; o; o >>= 1) v = fmaxf(v, __shfl_xor_sync(0xffu, v, o));
        if (!threadIdx.x) sh[0] = v;
    }
    __syncthreads();
    float r = sh[0];
    __syncthreads();
    return r;
}

// ---------------- small kernels ----------------
__global__ void embed_kernel(const int* __restrict__ ids,
                             const float* __restrict__ tok,
                             const float* __restrict__ pos,
                             float* __restrict__ x) {
    int row = blockIdx.x;
    int s = row % Sq;
    int id = ids[row];
    const float4* t4 = reinterpret_cast<const float4*>(tok) + (size_t)id * (Dm / 4);
    const float4* p4 = reinterpret_cast<const float4*>(pos) + (size_t)s * (Dm / 4);
    float4* x4 = reinterpret_cast<float4*>(x) + (size_t)row * (Dm / 4);
    int t = threadIdx.x;
    float4 a = t4[t], b = p4[t];
    a.x = f32_tf32(a.x + b.x); a.y = f32_tf32(a.y + b.y);
    a.z = f32_tf32(a.z + b.z); a.w = f32_tf32(a.w + b.w);
    x4[t] = a;
}

__global__ void cvt_copy(const float* __restrict__ in, float* __restrict__ out, size_t n4) {
    size_t i = (size_t)blockIdx.x * blockDim.x + threadIdx.x;
    if (i >= n4) return;
    float4 v = reinterpret_cast<const float4*>(in)[i];
    v.x = f32_tf32(v.x); v.y = f32_tf32(v.y); v.z = f32_tf32(v.z); v.w = f32_tf32(v.w);
    reinterpret_cast<float4*>(out)[i] = v;
}

__global__ void build_wqkv(const float* __restrict__ Wq, const float* __restrict__ Wk,
                           const float* __restrict__ Wv, float* __restrict__ out) {
    size_t i = (size_t)blockIdx.x * blockDim.x + threadIdx.x;
    size_t total = (size_t)Lyr * Dm * (QKVLD / 4);
    if (i >= total) return;
    size_t n4 = i % (QKVLD / 4);
    size_t k  = (i / (QKVLD / 4)) % Dm;
    size_t l  = i / ((size_t)(QKVLD / 4) * Dm);
    const float* src = (n4 < 128) ? Wq : (n4 < 256) ? Wk : Wv;
    size_t nn = (n4 % 128) * 4;
    float4 v = *reinterpret_cast<const float4*>(&src[(l * Dm + k) * Dm + nn]);
    v.x = f32_tf32(v.x); v.y = f32_tf32(v.y); v.z = f32_tf32(v.z); v.w = f32_tf32(v.w);
    reinterpret_cast<float4*>(out)[i] = v;
}

__global__ void pad_cvt_wout(const float* __restrict__ src, float* __restrict__ dst,
                             const float* __restrict__ bsrc, float* __restrict__ bdst) {
    const size_t total = (size_t)Dm * VPAD;
    for (size_t i = (size_t)blockIdx.x * blockDim.x + threadIdx.x; i < total;
         i += (size_t)gridDim.x * blockDim.x) {
        size_t r = i / VPAD, c = i % VPAD;
        dst[i] = (c < VOCn) ? f32_tf32(src[r * VOCn + c]) : 0.f;
        if (i < VPAD) bdst[i] = (i < VOCn) ? bsrc[i] : 0.f;
    }
}

__global__ void concat_bias(const float* __restrict__ bq, const float* __restrict__ bk,
                            const float* __restrict__ bv, float* __restrict__ o) {
    int i = blockIdx.x * blockDim.x + threadIdx.x;
    if (i >= Lyr * QKVLD) return;
    int l = i / QKVLD, j = i % QKVLD;
    float v = (j < 512) ? bq[l * 512 + j] : (j < 1024) ? bk[l * 512 + j - 512]
                                                       : bv[l * 512 + j - 1024];
    o[i] = v;
}

// ================= GEMM v1: 128x128, 2 CTA/SM (used for N=512) =================
#define GSM_A_FLOATS (3*128*20)
#define GSM_B_FLOATS (3*16*132)
#define GSM_BYTES ((GSM_A_FLOATS + GSM_B_FLOATS) * 4)

template <int ACT, int RND>
__global__ __launch_bounds__(256, 2)
void gemm_wmma(int K, const float* __restrict__ A,
               const float* __restrict__ W, int ldw,
               const float* __restrict__ bias,
               float* __restrict__ C, int ldc) {
    extern __shared__ float smem[];
    float* As = smem;
    float* Bs = smem + GSM_A_FLOATS;
    const uint32_t sb = smem_u32(smem);
    const uint32_t sbB = sb + GSM_A_FLOATS * 4;

    const int tid = threadIdx.x;
    const int wid = tid >> 5;
    const int wm = wid & 3, wn = wid >> 2;
    const int crow = blockIdx.y * 128;
    const int ccol = blockIdx.x * 128;

    wmma::fragment<wmma::accumulator, 16, 16, 8, float> acc[2][4];
#pragma unroll
    for (int i = 0; i < 2; i++)
#pragma unroll
        for (int j = 0; j < 4; j++) wmma::fill_fragment(acc[i][j], 0.f);

    const float* Ab = A + (size_t)crow * K;
    const int T = K >> 4;

    auto issue_stage = [&](int st, int t) {
        const int k0 = t << 4;
#pragma unroll
        for (int rep = 0; rep < 2; rep++) {
            int c = rep * 256 + tid;
            int row = c >> 2, seg = c & 3;
            CP_ASYNC16(sb + ((st * 128 + row) * 20 + seg * 4) * 4,
                       &Ab[(size_t)row * K + k0 + seg * 4]);
        }
#pragma unroll
        for (int rep = 0; rep < 2; rep++) {
            int c = rep * 256 + tid;
            int row = c >> 5, seg = c & 31;
            CP_ASYNC16(sbB + ((st * 16 + row) * 132 + seg * 4) * 4,
                       &W[(size_t)(k0 + row) * ldw + ccol + seg * 4]);
        }
        CP_COMMIT();
    };

    issue_stage(0, 0);
    issue_stage(1, 1);

    for (int t = 0; t < T; t++) {
        if (t + 2 < T) issue_stage((t + 2) % 3, t + 2);
        CP_WAIT(2);
        __syncthreads();
        const int st = t % 3;
        float* Ast = As + st * 128 * 20;
        float* Bst = Bs + st * 16 * 132;
#pragma unroll
        for (int ks = 0; ks < 2; ks++) {
            wmma::fragment<wmma::matrix_a, 16, 16, 8, wmma::precision::tf32, wmma::row_major> af[2];
            wmma::fragment<wmma::matrix_b, 16, 16, 8, wmma::precision::tf32, wmma::row_major> bf[4];
            wmma::load_matrix_sync(af[0], Ast + (wm * 32) * 20 + ks * 8, 20);
            wmma::load_matrix_sync(af[1], Ast + (wm * 32 + 16) * 20 + ks * 8, 20);
#pragma unroll
            for (int j = 0; j < 4; j++)
                wmma::load_matrix_sync(bf[j], Bst + (ks * 8) * 132 + wn * 64 + j * 16, 132);
#pragma unroll
            for (int i = 0; i < 2; i++)
#pragma unroll
                for (int j = 0; j < 4; j++)
                    wmma::mma_sync(acc[i][j], af[i], bf[j], acc[i][j]);
        }
        __syncthreads();
    }

    float* stg = smem;   // [8][16][68]
#pragma unroll
    for (int i = 0; i < 2; i++) {
        __syncthreads();
#pragma unroll
        for (int j = 0; j < 4; j++)
            wmma::store_matrix_sync(stg + wid * 1088 + j * 16, acc[i][j], 68, wmma::mem_row_major);
        __syncthreads();
#pragma unroll
        for (int it = 0; it < 8; it++) {
            int idx = it * 256 + tid;
            int r = idx >> 5;
            int c4 = (idx & 31) * 4;
            int wmg = r >> 4, rr = r & 15;
            int wng = c4 >> 6, cc = c4 & 63;
            const float* sp = stg + (wng * 4 + wmg) * 1088 + rr * 68 + cc;
            int row = crow + wmg * 32 + i * 16 + rr;
            int colb = ccol + c4;
            float4 bvv = *reinterpret_cast<const float4*>(&bias[colb]);
            float v0 = sp[0] + bvv.x, v1 = sp[1] + bvv.y;
            float v2 = sp[2] + bvv.z, v3 = sp[3] + bvv.w;
            if (ACT == 1) {
                v0 = 0.5f * v0 * (1.0f + erff(v0 * 0.70710678118654752f));
                v1 = 0.5f * v1 * (1.0f + erff(v1 * 0.70710678118654752f));
                v2 = 0.5f * v2 * (1.0f + erff(v2 * 0.70710678118654752f));
                v3 = 0.5f * v3 * (1.0f + erff(v3 * 0.70710678118654752f));
            }
            if (RND == 1) {
                v0 = f32_tf32(v0); v1 = f32_tf32(v1);
                v2 = f32_tf32(v2); v3 = f32_tf32(v3);
            }
            *reinterpret_cast<float4*>(&C[(size_t)row * ldc + colb]) =
                make_float4(v0, v1, v2, v3);
        }
    }
}

// ================= GEMM v2: 128x256, warp tile 64x64, 1 CTA/SM =================
#define G2_A_FLOATS (3*128*20)            // 7680
#define G2_B_FLOATS (3*16*264)            // 12672
#define G2_BYTES ((G2_A_FLOATS + G2_B_FLOATS) * 4)   // 81408

template <int ACT, int RND, int VEC>
__global__ __launch_bounds__(256, 1)
void gemm_wmma2(int K, const float* __restrict__ A,
                const float* __restrict__ W, int ldw,
                const float* __restrict__ bias,
                float* __restrict__ C, int ldc, int Nc) {
    extern __shared__ float smem[];
    float* As = smem;                       // [3][128][20]
    float* Bs = smem + G2_A_FLOATS;         // [3][16][264]
    const uint32_t sb = smem_u32(smem);
    const uint32_t sbB = sb + G2_A_FLOATS * 4;

    const int tid = threadIdx.x;
    const int wid = tid >> 5;
    const int wm = wid & 1, wn = wid >> 1;     // 2 x 4 warps, tile 64x64
    const int crow = blockIdx.y * 128;
    const int ccol = blockIdx.x * 256;

    wmma::fragment<wmma::accumulator, 16, 16, 8, float> acc[4][4];
#pragma unroll
    for (int i = 0; i < 4; i++)
#pragma unroll
        for (int j = 0; j < 4; j++) wmma::fill_fragment(acc[i][j], 0.f);

    const float* Ab = A + (size_t)crow * K;
    const int T = K >> 4;

    auto issue_stage = [&](int st, int t) {
        const int k0 = t << 4;
        // A: 512 16B-chunks
#pragma unroll
        for (int rep = 0; rep < 2; rep++) {
            int c = rep * 256 + tid;
            int row = c >> 2, seg = c & 3;
            CP_ASYNC16(sb + ((st * 128 + row) * 20 + seg * 4) * 4,
                       &Ab[(size_t)row * K + k0 + seg * 4]);
        }
        // B: 1024 16B-chunks
#pragma unroll
        for (int rep = 0; rep < 4; rep++) {
            int c = rep * 256 + tid;
            int row = c >> 6, seg = c & 63;
            CP_ASYNC16(sbB + ((st * 16 + row) * 264 + seg * 4) * 4,
                       &W[(size_t)(k0 + row) * ldw + ccol + seg * 4]);
        }
        CP_COMMIT();
    };

    issue_stage(0, 0);
    issue_stage(1, 1);

    for (int t = 0; t < T; t++) {
        if (t + 2 < T) issue_stage((t + 2) % 3, t + 2);
        CP_WAIT(2);
        __syncthreads();
        const int st = t % 3;
        float* Ast = As + st * 128 * 20;
        float* Bst = Bs + st * 16 * 264;
#pragma unroll
        for (int ks = 0; ks < 2; ks++) {
            wmma::fragment<wmma::matrix_a, 16, 16, 8, wmma::precision::tf32, wmma::row_major> af[4];
            wmma::fragment<wmma::matrix_b, 16, 16, 8, wmma::precision::tf32, wmma::row_major> bf[4];
#pragma unroll
            for (int i = 0; i < 4; i++)
                wmma::load_matrix_sync(af[i], Ast + (wm * 64 + i * 16) * 20 + ks * 8, 20);
#pragma unroll
            for (int j = 0; j < 4; j++)
                wmma::load_matrix_sync(bf[j], Bst + (ks * 8) * 264 + wn * 64 + j * 16, 264);
#pragma unroll
            for (int i = 0; i < 4; i++)
#pragma unroll
                for (int j = 0; j < 4; j++)
                    wmma::mma_sync(acc[i][j], af[i], bf[j], acc[i][j]);
        }
        __syncthreads();
    }

    // epilogue: per i-chunk (16 rows per warp-row), stage 32 rows x 256 cols
    float* stg = smem;   // [8][16][68] = 8704 floats
#pragma unroll
    for (int i = 0; i < 4; i++) {
        __syncthreads();
#pragma unroll
        for (int j = 0; j < 4; j++)
            wmma::store_matrix_sync(stg + wid * 1088 + j * 16, acc[i][j], 68, wmma::mem_row_major);
        __syncthreads();
#pragma unroll
        for (int it = 0; it < 8; it++) {
            int idx = it * 256 + tid;           // 2048 float4 slots
            int r = idx >> 6;                    // 0..31
            int c4 = (idx & 63) * 4;             // 0..252
            int wmg = r >> 4, rr = r & 15;       // warp-row, row-in-frag
            int wng = c4 >> 6, cc = c4 & 63;     // warp-col, col-in-tile
            const float* sp = stg + (wng * 2 + wmg) * 1088 + rr * 68 + cc;
            int row = crow + wmg * 64 + i * 16 + rr;
            int colb = ccol + c4;
            float4 bvv = *reinterpret_cast<const float4*>(&bias[colb]);
            float v0 = sp[0] + bvv.x, v1 = sp[1] + bvv.y;
            float v2 = sp[2] + bvv.z, v3 = sp[3] + bvv.w;
            if (ACT == 1) {
                v0 = 0.5f * v0 * (1.0f + erff(v0 * 0.70710678118654752f));
                v1 = 0.5f * v1 * (1.0f + erff(v1 * 0.70710678118654752f));
                v2 = 0.5f * v2 * (1.0f + erff(v2 * 0.70710678118654752f));
                v3 = 0.5f * v3 * (1.0f + erff(v3 * 0.70710678118654752f));
            }
            if (RND == 1) {
                v0 = f32_tf32(v0); v1 = f32_tf32(v1);
                v2 = f32_tf32(v2); v3 = f32_tf32(v3);
            }
            if (VEC == 1) {
                *reinterpret_cast<float4*>(&C[(size_t)row * ldc + colb]) =
                    make_float4(v0, v1, v2, v3);
            } else {
                float* cp = &C[(size_t)row * ldc + colb];
                if (colb + 0 < Nc) cp[0] = v0;
                if (colb + 1 < Nc) cp[1] = v1;
                if (colb + 2 < Nc) cp[2] = v2;
                if (colb + 3 < Nc) cp[3] = v3;
            }
        }
    }
}

// ================= wmma attention =================
__global__ __launch_bounds__(128)
void attn_scores_wmma(const float* __restrict__ QKV, float* __restrict__ Sc) {
    const int bh = blockIdx.z;
    const int b = bh / Hn, h = bh % Hn;
    const float* qb = QKV + (size_t)b * Sq * QKVLD + h * DKh;
    const float* kb = QKV + (size_t)b * Sq * QKVLD + 512 + h * DKh;
    float* sbp = Sc + (size_t)bh * Sq * Sq;
    const int q0 = blockIdx.y * 64, k0 = blockIdx.x * 64;
    const int wid = threadIdx.x >> 5;
    const int wm = wid & 1, wn = wid >> 1;

    wmma::fragment<wmma::accumulator, 16, 16, 8, float> acc[2][2];
#pragma unroll
    for (int i = 0; i < 2; i++)
#pragma unroll
        for (int j = 0; j < 2; j++) wmma::fill_fragment(acc[i][j], 0.f);

#pragma unroll
    for (int d0 = 0; d0 < DKh; d0 += 8) {
        wmma::fragment<wmma::matrix_a, 16, 16, 8, wmma::precision::tf32, wmma::row_major> af[2];
        wmma::fragment<wmma::matrix_b, 16, 16, 8, wmma::precision::tf32, wmma::col_major> bf[2];
#pragma unroll
        for (int i = 0; i < 2; i++)
            wmma::load_matrix_sync(af[i], &qb[(size_t)(q0 + wm * 32 + i * 16) * QKVLD + d0], QKVLD);
#pragma unroll
        for (int j = 0; j < 2; j++)
            wmma::load_matrix_sync(bf[j], &kb[(size_t)(k0 + wn * 32 + j * 16) * QKVLD + d0], QKVLD);
#pragma unroll
        for (int i = 0; i < 2; i++)
#pragma unroll
            for (int j = 0; j < 2; j++)
                wmma::mma_sync(acc[i][j], af[i], bf[j], acc[i][j]);
    }
#pragma unroll
    for (int i = 0; i < 2; i++)
#pragma unroll
        for (int j = 0; j < 2; j++) {
#pragma unroll
            for (int e = 0; e < acc[i][j].num_elements; e++) acc[i][j].x[e] *= 0.125f;
            wmma::store_matrix_sync(
                &sbp[(size_t)(q0 + wm * 32 + i * 16) * Sq + k0 + wn * 32 + j * 16],
                acc[i][j], Sq, wmma::mem_row_major);
        }
}

__global__ void softmax_kernel(float* __restrict__ s) {
    float* p = s + (size_t)blockIdx.x * Sq;
    int t = threadIdx.x;
    float a = p[t], b = p[t + 256];
    __shared__ float sh[32];
    float m = blockReduceMax(fmaxf(a, b), sh);
    float e0 = __expf(a - m), e1 = __expf(b - m);
    float sum = blockReduceSum(e0 + e1, sh);
    float inv = 1.0f / sum;
    p[t]       = f32_tf32(e0 * inv);
    p[t + 256] = f32_tf32(e1 * inv);
}

__global__ __launch_bounds__(128)
void attn_av_wmma(const float* __restrict__ Sc, const float* __restrict__ QKV,
                  float* __restrict__ O) {
    const int bh = blockIdx.z;
    const int b = bh / Hn, h = bh % Hn;
    const float* sbp = Sc + (size_t)bh * Sq * Sq;
    const float* vb = QKV + (size_t)b * Sq * QKVLD + 1024 + h * DKh;
    float* ob = O + (size_t)b * Sq * Dm + h * DKh;
    const int q0 = blockIdx.y * 64;
    const int wid = threadIdx.x >> 5;
    const int wm = wid & 1, wn = wid >> 1;

    wmma::fragment<wmma::accumulator, 16, 16, 8, float> acc[2][2];
#pragma unroll
    for (int i = 0; i < 2; i++)
#pragma unroll
        for (int j = 0; j < 2; j++) wmma::fill_fragment(acc[i][j], 0.f);

    for (int k0 = 0; k0 < Sq; k0 += 8) {
        wmma::fragment<wmma::matrix_a, 16, 16, 8, wmma::precision::tf32, wmma::row_major> af[2];
        wmma::fragment<wmma::matrix_b, 16, 16, 8, wmma::precision::tf32, wmma::row_major> bf[2];
#pragma unroll
        for (int i = 0; i < 2; i++)
            wmma::load_matrix_sync(af[i], &sbp[(size_t)(q0 + wm * 32 + i * 16) * Sq + k0], Sq);
#pragma unroll
        for (int j = 0; j < 2; j++)
            wmma::load_matrix_sync(bf[j], &vb[(size_t)k0 * QKVLD + wn * 32 + j * 16], QKVLD);
#pragma unroll
        for (int i = 0; i < 2; i++)
#pragma unroll
            for (int j = 0; j < 2; j++)
                wmma::mma_sync(acc[i][j], af[i], bf[j], acc[i][j]);
    }
#pragma unroll
    for (int i = 0; i < 2; i++)
#pragma unroll
        for (int j = 0; j < 2; j++) {
#pragma unroll
            for (int e = 0; e < acc[i][j].num_elements; e++)
                acc[i][j].x[e] = f32_tf32(acc[i][j].x[e]);
            wmma::store_matrix_sync(
                &ob[(size_t)(q0 + wm * 32 + i * 16) * Dm + wn * 32 + j * 16],
                acc[i][j], Dm, wmma::mem_row_major);
        }
}

__global__ void ln_kernel(const float* __restrict__ a, const float* __restrict__ res,
                          const float* __restrict__ g, const float* __restrict__ beta,
                          float* __restrict__ out) {
    const size_t row = blockIdx.x;
    const int t = threadIdx.x;
    float v0 = a[row * Dm + t], v1 = a[row * Dm + t + 256];
    if (res) { v0 += res[row * Dm + t]; v1 += res[row * Dm + t + 256]; }
    __shared__ float sh[32];
    float s = blockReduceSum(v0 + v1, sh);
    float mean = s * (1.0f / Dm);
    float d0 = v0 - mean, d1 = v1 - mean;
    float ss = blockReduceSum(d0 * d0 + d1 * d1, sh);
    float inv = rsqrtf(ss * (1.0f / Dm) + 1e-5f);
    out[row * Dm + t]       = f32_tf32(d0 * inv * g[t] + beta[t]);
    out[row * Dm + t + 256] = f32_tf32(d1 * inv * g[t + 256] + beta[t + 256]);
}

// ================= orchestration =================
extern "C" void kernel_launch(void* const* d_in, const int* in_sizes, int n_in,
                              void* d_out, int out_size) {
    const int*   ids  = (const int*)  d_in[0];
    const float* tok  = (const float*)d_in[1];
    const float* pos  = (const float*)d_in[2];
    const float* Wq   = (const float*)d_in[3];
    const float* bq   = (const float*)d_in[4];
    const float* Wk   = (const float*)d_in[5];
    const float* bk   = (const float*)d_in[6];
    const float* Wv   = (const float*)d_in[7];
    const float* bv   = (const float*)d_in[8];
    const float* Wo   = (const float*)d_in[9];
    const float* bo   = (const float*)d_in[10];
    const float* ln_g = (const float*)d_in[11];
    const float* ln_b = (const float*)d_in[12];
    const float* W1   = (const float*)d_in[13];
    const float* b1   = (const float*)d_in[14];
    const float* W2   = (const float*)d_in[15];
    const float* b2   = (const float*)d_in[16];
    const float* on_g = (const float*)d_in[17];
    const float* on_b = (const float*)d_in[18];
    const float* Wout = (const float*)d_in[19];
    const float* bout = (const float*)d_in[20];
    float* out = (float*)d_out;

    float *x, *qkv, *t, *tmp, *sc, *ff, *wqkv, *wo, *w1, *w2, *wout, *bqkv, *boutp;
    cudaGetSymbolAddress((void**)&x,     g_x);
    cudaGetSymbolAddress((void**)&qkv,   g_qkv);
    cudaGetSymbolAddress((void**)&t,     g_t);
    cudaGetSymbolAddress((void**)&tmp,   g_tmp);
    cudaGetSymbolAddress((void**)&sc,    g_sc);
    cudaGetSymbolAddress((void**)&ff,    g_ff);
    cudaGetSymbolAddress((void**)&wqkv,  g_wqkv);
    cudaGetSymbolAddress((void**)&wo,    g_wo);
    cudaGetSymbolAddress((void**)&w1,    g_w1);
    cudaGetSymbolAddress((void**)&w2,    g_w2);
    cudaGetSymbolAddress((void**)&wout,  g_wout);
    cudaGetSymbolAddress((void**)&bqkv,  g_bqkv);
    cudaGetSymbolAddress((void**)&boutp, g_bout);

    cudaFuncSetAttribute(gemm_wmma<0,0>, cudaFuncAttributeMaxDynamicSharedMemorySize, GSM_BYTES);
    cudaFuncSetAttribute(gemm_wmma2<0,1,1>, cudaFuncAttributeMaxDynamicSharedMemorySize, G2_BYTES);
    cudaFuncSetAttribute(gemm_wmma2<1,1,1>, cudaFuncAttributeMaxDynamicSharedMemorySize, G2_BYTES);
    cudaFuncSetAttribute(gemm_wmma2<0,0,0>, cudaFuncAttributeMaxDynamicSharedMemorySize, G2_BYTES);

    // ---- weight preprocessing ----
    {
        size_t n4;
        n4 = (size_t)Lyr * Dm * (QKVLD / 4);
        build_wqkv<<<(unsigned)((n4 + 255) / 256), 256>>>(Wq, Wk, Wv, wqkv);
        n4 = (size_t)Lyr * Dm * Dm / 4;
        cvt_copy<<<(unsigned)((n4 + 255) / 256), 256>>>(Wo, wo, n4);
        n4 = (size_t)Dm * DFFn / 4;
        cvt_copy<<<(unsigned)((n4 + 255) / 256), 256>>>(W1, w1, n4);
        cvt_copy<<<(unsigned)((n4 + 255) / 256), 256>>>(W2, w2, n4);
        pad_cvt_wout<<<4096, 256>>>(Wout, wout, bout, boutp);
        concat_bias<<<(Lyr * QKVLD + 255) / 256, 256>>>(bq, bk, bv, bqkv);
    }

    embed_kernel<<<NTOK, 128>>>(ids, tok, pos, x);

    const dim3 gScores(Sq / 64, Sq / 64, Bsz * Hn);
    const dim3 gAV(1, Sq / 64, Bsz * Hn);

    for (int l = 0; l < Lyr; l++) {
        const size_t bOff = (size_t)l * Dm;
        // fused QKV: N=1536 -> 6x16=96 blocks of v2
        gemm_wmma2<0,1,1><<<dim3(QKVLD / 256, NTOK / 128), 256, G2_BYTES>>>(
            Dm, x, wqkv + (size_t)l * Dm * QKVLD, QKVLD,
            bqkv + (size_t)l * QKVLD, qkv, QKVLD, QKVLD);

        attn_scores_wmma<<<gScores, 128>>>(qkv, sc);
        softmax_kernel<<<Bsz * Hn * Sq, 256>>>(sc);
        attn_av_wmma<<<gAV, 128>>>(sc, qkv, t);

        gemm_wmma<0,0><<<dim3(Dm / 128, NTOK / 128), 256, GSM_BYTES>>>(
            Dm, t, wo + (size_t)l * Dm * Dm, Dm, bo + bOff, tmp, Dm);
        ln_kernel<<<NTOK, 256>>>(x, tmp, ln_g + bOff, ln_b + bOff, x);
    }

    // FFN
    gemm_wmma2<1,1,1><<<dim3(DFFn / 256, NTOK / 128), 256, G2_BYTES>>>(
        Dm, x, w1, DFFn, b1, ff, DFFn, DFFn);
    gemm_wmma<0,0><<<dim3(Dm / 128, NTOK / 128), 256, GSM_BYTES>>>(
        DFFn, ff, w2, Dm, b2, t, Dm);
    ln_kernel<<<NTOK, 256>>>(t, nullptr, on_g, on_b, x);

    // logits
    gemm_wmma2<0,0,0><<<dim3(VPAD / 256, NTOK / 128), 256, G2_BYTES>>>(
        Dm, x, wout, VPAD, boutp, out, VOCn, VOCn);
}

// round 6
// speedup vs baseline: 3.9272x; 2.4314x over previous
#include <cuda_runtime.h>
#include <cuda_fp16.h>
#include <mma.h>
#include <cstdint>
#include <math.h>

using namespace nvcuda;

#define Bsz 4
#define Sq 512
#define Dm 512
#define Hn 8
#define DKh 64
#define Lyr 6
#define DFFn 2048
#define VOCn 50257
#define NTOK (Bsz*Sq)      // 2048
#define VPAD 50432         // 197*256
#define QKVLD 1536

// ---------------- helpers ----------------
__device__ __forceinline__ uint32_t smem_u32(const void* p) {
    uint32_t a;
    asm("{ .reg .u64 t; cvta.to.shared.u64 t, %1; cvt.u32.u64 %0, t; }" : "=r"(a) : "l"(p));
    return a;
}
#define CP_ASYNC16(dst, src) \
    asm volatile("cp.async.cg.shared.global [%0], [%1], 16;" :: "r"(dst), "l"(src))
#define CP_COMMIT()  asm volatile("cp.async.commit_group;" ::: "memory")
#define CP_WAIT(n)   asm volatile("cp.async.wait_group %0;" :: "n"(n) : "memory")

// ---------------- device scratch ----------------
__device__ __half g_x[NTOK*Dm];
__device__ __half g_qkv[(size_t)NTOK*QKVLD];
__device__ __half g_t[NTOK*Dm];
__device__ __half g_tmp[NTOK*Dm];
__device__ float  g_sc[(size_t)Bsz*Hn*Sq*Sq];     // raw scores fp32
__device__ __half g_p[(size_t)Bsz*Hn*Sq*Sq];      // softmax probs half
__device__ __half g_ff[(size_t)NTOK*DFFn];
__device__ __half g_wqkv[(size_t)Lyr*Dm*QKVLD];
__device__ __half g_wo[(size_t)Lyr*Dm*Dm];
__device__ __half g_w1[(size_t)Dm*DFFn];
__device__ __half g_w2[(size_t)DFFn*Dm];
__device__ __half g_wout[(size_t)Dm*VPAD];
__device__ float  g_bqkv[Lyr*QKVLD];
__device__ float  g_bout[VPAD];

// ---------------- reductions ----------------
__device__ __forceinline__ float blockReduceSum(float v, float* sh) {
    int lane = threadIdx.x & 31, w = threadIdx.x >> 5;
#pragma unroll
    for (int o = 16; o; o >>= 1) v += __shfl_xor_sync(0xffffffffu, v, o);
    if (!lane) sh[w] = v;
    __syncthreads();
    if (threadIdx.x < 8) {
        v = sh[threadIdx.x];
#pragma unroll
        for (int o = 4; o; o >>= 1) v += __shfl_xor_sync(0xffu, v, o);
        if (!threadIdx.x) sh[0] = v;
    }
    __syncthreads();
    float r = sh[0];
    __syncthreads();
    return r;
}
__device__ __forceinline__ float blockReduceMax(float v, float* sh) {
    int lane = threadIdx.x & 31, w = threadIdx.x >> 5;
#pragma unroll
    for (int o = 16; o; o >>= 1) v = fmaxf(v, __shfl_xor_sync(0xffffffffu, v, o));
    if (!lane) sh[w] = v;
    __syncthreads();
    if (threadIdx.x < 8) {
        v = sh[threadIdx.x];
#pragma unroll
        for (int o = 4; o; o >>= 1) v = fmaxf(v, __shfl_xor_sync(0xffu, v, o));
        if (!threadIdx.x) sh[0] = v;
    }
    __syncthreads();
    float r = sh[0];
    __syncthreads();
    return r;
}

// ---------------- small kernels ----------------
__global__ void embed_kernel(const int* __restrict__ ids,
                             const float* __restrict__ tok,
                             const float* __restrict__ pos,
                             __half* __restrict__ x) {
    int row = blockIdx.x;
    int s = row % Sq;
    int id = ids[row];
    const float4* t4 = reinterpret_cast<const float4*>(tok) + (size_t)id * (Dm / 4);
    const float4* p4 = reinterpret_cast<const float4*>(pos) + (size_t)s * (Dm / 4);
    int t = threadIdx.x;   // 128
    float4 a = t4[t], b = p4[t];
    __half2 h0 = __floats2half2_rn(a.x + b.x, a.y + b.y);
    __half2 h1 = __floats2half2_rn(a.z + b.z, a.w + b.w);
    uint2 u = make_uint2(*(uint32_t*)&h0, *(uint32_t*)&h1);
    reinterpret_cast<uint2*>(x + (size_t)row * Dm)[t] = u;
}

__global__ void cvt_copy_h(const float* __restrict__ in, __half* __restrict__ out, size_t n4) {
    size_t i = (size_t)blockIdx.x * blockDim.x + threadIdx.x;
    if (i >= n4) return;
    float4 v = reinterpret_cast<const float4*>(in)[i];
    __half2 h0 = __floats2half2_rn(v.x, v.y);
    __half2 h1 = __floats2half2_rn(v.z, v.w);
    reinterpret_cast<uint2*>(out)[i] = make_uint2(*(uint32_t*)&h0, *(uint32_t*)&h1);
}

__global__ void build_wqkv(const float* __restrict__ Wq, const float* __restrict__ Wk,
                           const float* __restrict__ Wv, __half* __restrict__ out) {
    size_t i = (size_t)blockIdx.x * blockDim.x + threadIdx.x;
    size_t total = (size_t)Lyr * Dm * (QKVLD / 4);
    if (i >= total) return;
    size_t n4 = i % (QKVLD / 4);
    size_t k  = (i / (QKVLD / 4)) % Dm;
    size_t l  = i / ((size_t)(QKVLD / 4) * Dm);
    const float* src = (n4 < 128) ? Wq : (n4 < 256) ? Wk : Wv;
    size_t nn = (n4 % 128) * 4;
    float4 v = *reinterpret_cast<const float4*>(&src[(l * Dm + k) * Dm + nn]);
    __half2 h0 = __floats2half2_rn(v.x, v.y);
    __half2 h1 = __floats2half2_rn(v.z, v.w);
    reinterpret_cast<uint2*>(out)[i] = make_uint2(*(uint32_t*)&h0, *(uint32_t*)&h1);
}

__global__ void pad_cvt_wout(const float* __restrict__ src, __half* __restrict__ dst,
                             const float* __restrict__ bsrc, float* __restrict__ bdst) {
    const size_t total = (size_t)Dm * VPAD;
    for (size_t i = (size_t)blockIdx.x * blockDim.x + threadIdx.x; i < total;
         i += (size_t)gridDim.x * blockDim.x) {
        size_t r = i / VPAD, c = i % VPAD;
        dst[i] = (c < VOCn) ? __float2half(src[r * VOCn + c]) : __half(0.f);
        if (i < VPAD) bdst[i] = (i < VOCn) ? bsrc[i] : 0.f;
    }
}

__global__ void concat_bias(const float* __restrict__ bq, const float* __restrict__ bk,
                            const float* __restrict__ bv, float* __restrict__ o) {
    int i = blockIdx.x * blockDim.x + threadIdx.x;
    if (i >= Lyr * QKVLD) return;
    int l = i / QKVLD, j = i % QKVLD;
    float v = (j < 512) ? bq[l * 512 + j] : (j < 1024) ? bk[l * 512 + j - 512]
                                                       : bv[l * 512 + j - 1024];
    o[i] = v;
}

// ================= GEMM h1: 128x128, BK=32, half, 2 CTA/SM =================
// smem: A [3][128][40]h (30720B) + B [3][32][144]h (27648B) = 58368B
#define H1_BYTES 58368

template <int ACT>
__global__ __launch_bounds__(256, 2)
void gemm_h1(int K, const __half* __restrict__ A,
             const __half* __restrict__ W, int ldw,
             const float* __restrict__ bias,
             __half* __restrict__ C, int ldc) {
    extern __shared__ char smraw[];
    __half* As = reinterpret_cast<__half*>(smraw);
    __half* Bs = reinterpret_cast<__half*>(smraw + 30720);
    const uint32_t sb = smem_u32(smraw);
    const uint32_t sbB = sb + 30720;

    const int tid = threadIdx.x;
    const int wid = tid >> 5;
    const int wm = wid & 3, wn = wid >> 2;   // 4x2 warps, warp tile 32x64
    const int crow = blockIdx.y * 128;
    const int ccol = blockIdx.x * 128;

    wmma::fragment<wmma::accumulator, 16, 16, 16, float> acc[2][4];
#pragma unroll
    for (int i = 0; i < 2; i++)
#pragma unroll
        for (int j = 0; j < 4; j++) wmma::fill_fragment(acc[i][j], 0.f);

    const __half* Ab = A + (size_t)crow * K;
    const int T = K >> 5;

    auto issue_stage = [&](int st, int t) {
        const int k0 = t << 5;
        // A: 128 rows x 64B = 512 chunks
#pragma unroll
        for (int rep = 0; rep < 2; rep++) {
            int c = rep * 256 + tid;
            int row = c >> 2, seg = c & 3;
            CP_ASYNC16(sb + st * 10240 + row * 80 + seg * 16,
                       &Ab[(size_t)row * K + k0 + seg * 8]);
        }
        // B: 32 rows x 256B = 512 chunks
#pragma unroll
        for (int rep = 0; rep < 2; rep++) {
            int c = rep * 256 + tid;
            int row = c >> 4, seg = c & 15;
            CP_ASYNC16(sbB + st * 9216 + row * 288 + seg * 16,
                       &W[(size_t)(k0 + row) * ldw + ccol + seg * 8]);
        }
        CP_COMMIT();
    };

    issue_stage(0, 0);
    issue_stage(1, 1);

    for (int t = 0; t < T; t++) {
        if (t + 2 < T) issue_stage((t + 2) % 3, t + 2);
        CP_WAIT(2);
        __syncthreads();
        const int st = t % 3;
        __half* Ast = As + st * 128 * 40;
        __half* Bst = Bs + st * 32 * 144;
#pragma unroll
        for (int ks = 0; ks < 2; ks++) {
            wmma::fragment<wmma::matrix_a, 16, 16, 16, __half, wmma::row_major> af[2];
            wmma::fragment<wmma::matrix_b, 16, 16, 16, __half, wmma::row_major> bf[4];
            wmma::load_matrix_sync(af[0], Ast + (wm * 32) * 40 + ks * 16, 40);
            wmma::load_matrix_sync(af[1], Ast + (wm * 32 + 16) * 40 + ks * 16, 40);
#pragma unroll
            for (int j = 0; j < 4; j++)
                wmma::load_matrix_sync(bf[j], Bst + (ks * 16) * 144 + wn * 64 + j * 16, 144);
#pragma unroll
            for (int i = 0; i < 2; i++)
#pragma unroll
                for (int j = 0; j < 4; j++)
                    wmma::mma_sync(acc[i][j], af[i], bf[j], acc[i][j]);
        }
        __syncthreads();
    }

    float* stg = reinterpret_cast<float*>(smraw);   // [8][16][68]
#pragma unroll
    for (int i = 0; i < 2; i++) {
        __syncthreads();
#pragma unroll
        for (int j = 0; j < 4; j++)
            wmma::store_matrix_sync(stg + wid * 1088 + j * 16, acc[i][j], 68, wmma::mem_row_major);
        __syncthreads();
#pragma unroll
        for (int it = 0; it < 8; it++) {
            int idx = it * 256 + tid;
            int r = idx >> 5;
            int c4 = (idx & 31) * 4;
            int wmg = r >> 4, rr = r & 15;
            int wng = c4 >> 6, cc = c4 & 63;
            const float* sp = stg + (wng * 4 + wmg) * 1088 + rr * 68 + cc;
            int row = crow + wmg * 32 + i * 16 + rr;
            int colb = ccol + c4;
            float4 bvv = *reinterpret_cast<const float4*>(&bias[colb]);
            float v0 = sp[0] + bvv.x, v1 = sp[1] + bvv.y;
            float v2 = sp[2] + bvv.z, v3 = sp[3] + bvv.w;
            if (ACT == 1) {
                v0 = 0.5f * v0 * (1.0f + erff(v0 * 0.70710678118654752f));
                v1 = 0.5f * v1 * (1.0f + erff(v1 * 0.70710678118654752f));
                v2 = 0.5f * v2 * (1.0f + erff(v2 * 0.70710678118654752f));
                v3 = 0.5f * v3 * (1.0f + erff(v3 * 0.70710678118654752f));
            }
            __half2 h0 = __floats2half2_rn(v0, v1);
            __half2 h1 = __floats2half2_rn(v2, v3);
            *reinterpret_cast<uint2*>(&C[(size_t)row * ldc + colb]) =
                make_uint2(*(uint32_t*)&h0, *(uint32_t*)&h1);
        }
    }
}

// ================= GEMM h2: 128x256, BK=32, half, 1 CTA/SM =================
// smem: A [3][128][40]h (30720B) + B [3][32][272]h (52224B) = 82944B
#define H2_BYTES 82944

template <int ACT, int OUTH>
__global__ __launch_bounds__(256, 1)
void gemm_h2(int K, const __half* __restrict__ A,
             const __half* __restrict__ W, int ldw,
             const float* __restrict__ bias,
             void* __restrict__ Cv, int ldc, int Nc) {
    extern __shared__ char smraw[];
    __half* As = reinterpret_cast<__half*>(smraw);
    __half* Bs = reinterpret_cast<__half*>(smraw + 30720);
    const uint32_t sb = smem_u32(smraw);
    const uint32_t sbB = sb + 30720;

    const int tid = threadIdx.x;
    const int wid = tid >> 5;
    const int wm = wid & 1, wn = wid >> 1;   // 2x4 warps, warp tile 64x64
    const int crow = blockIdx.y * 128;
    const int ccol = blockIdx.x * 256;

    wmma::fragment<wmma::accumulator, 16, 16, 16, float> acc[4][4];
#pragma unroll
    for (int i = 0; i < 4; i++)
#pragma unroll
        for (int j = 0; j < 4; j++) wmma::fill_fragment(acc[i][j], 0.f);

    const __half* Ab = A + (size_t)crow * K;
    const int T = K >> 5;

    auto issue_stage = [&](int st, int t) {
        const int k0 = t << 5;
#pragma unroll
        for (int rep = 0; rep < 2; rep++) {
            int c = rep * 256 + tid;
            int row = c >> 2, seg = c & 3;
            CP_ASYNC16(sb + st * 10240 + row * 80 + seg * 16,
                       &Ab[(size_t)row * K + k0 + seg * 8]);
        }
        // B: 32 rows x 512B = 1024 chunks
#pragma unroll
        for (int rep = 0; rep < 4; rep++) {
            int c = rep * 256 + tid;
            int row = c >> 5, seg = c & 31;
            CP_ASYNC16(sbB + st * 17408 + row * 544 + seg * 16,
                       &W[(size_t)(k0 + row) * ldw + ccol + seg * 8]);
        }
        CP_COMMIT();
    };

    issue_stage(0, 0);
    issue_stage(1, 1);

    for (int t = 0; t < T; t++) {
        if (t + 2 < T) issue_stage((t + 2) % 3, t + 2);
        CP_WAIT(2);
        __syncthreads();
        const int st = t % 3;
        __half* Ast = As + st * 128 * 40;
        __half* Bst = Bs + st * 32 * 272;
#pragma unroll
        for (int ks = 0; ks < 2; ks++) {
            wmma::fragment<wmma::matrix_a, 16, 16, 16, __half, wmma::row_major> af[4];
            wmma::fragment<wmma::matrix_b, 16, 16, 16, __half, wmma::row_major> bf[4];
#pragma unroll
            for (int i = 0; i < 4; i++)
                wmma::load_matrix_sync(af[i], Ast + (wm * 64 + i * 16) * 40 + ks * 16, 40);
#pragma unroll
            for (int j = 0; j < 4; j++)
                wmma::load_matrix_sync(bf[j], Bst + (ks * 16) * 272 + wn * 64 + j * 16, 272);
#pragma unroll
            for (int i = 0; i < 4; i++)
#pragma unroll
                for (int j = 0; j < 4; j++)
                    wmma::mma_sync(acc[i][j], af[i], bf[j], acc[i][j]);
        }
        __syncthreads();
    }

    float* stg = reinterpret_cast<float*>(smraw);   // [8][16][68]
#pragma unroll
    for (int i = 0; i < 4; i++) {
        __syncthreads();
#pragma unroll
        for (int j = 0; j < 4; j++)
            wmma::store_matrix_sync(stg + wid * 1088 + j * 16, acc[i][j], 68, wmma::mem_row_major);
        __syncthreads();
#pragma unroll
        for (int it = 0; it < 8; it++) {
            int idx = it * 256 + tid;
            int r = idx >> 6;                     // 0..31
            int c4 = (idx & 63) * 4;              // 0..252
            int wmg = r >> 4, rr = r & 15;
            int wng = c4 >> 6, cc = c4 & 63;
            const float* sp = stg + (wng * 2 + wmg) * 1088 + rr * 68 + cc;
            int row = crow + wmg * 64 + i * 16 + rr;
            int colb = ccol + c4;
            float4 bvv = *reinterpret_cast<const float4*>(&bias[colb]);
            float v0 = sp[0] + bvv.x, v1 = sp[1] + bvv.y;
            float v2 = sp[2] + bvv.z, v3 = sp[3] + bvv.w;
            if (ACT == 1) {
                v0 = 0.5f * v0 * (1.0f + erff(v0 * 0.70710678118654752f));
                v1 = 0.5f * v1 * (1.0f + erff(v1 * 0.70710678118654752f));
                v2 = 0.5f * v2 * (1.0f + erff(v2 * 0.70710678118654752f));
                v3 = 0.5f * v3 * (1.0f + erff(v3 * 0.70710678118654752f));
            }
            if (OUTH == 1) {
                __half* C = reinterpret_cast<__half*>(Cv);
                __half2 h0 = __floats2half2_rn(v0, v1);
                __half2 h1 = __floats2half2_rn(v2, v3);
                *reinterpret_cast<uint2*>(&C[(size_t)row * ldc + colb]) =
                    make_uint2(*(uint32_t*)&h0, *(uint32_t*)&h1);
            } else {
                float* C = reinterpret_cast<float*>(Cv);
                float* cp = &C[(size_t)row * ldc + colb];
                if (colb + 0 < Nc) cp[0] = v0;
                if (colb + 1 < Nc) cp[1] = v1;
                if (colb + 2 < Nc) cp[2] = v2;
                if (colb + 3 < Nc) cp[3] = v3;
            }
        }
    }
}

// ================= attention =================
// scores (fp32) = 0.125 * Q K^T, half inputs, m16n16k16
__global__ __launch_bounds__(128)
void attn_scores_wmma(const __half* __restrict__ QKV, float* __restrict__ Sc) {
    const int bh = blockIdx.z;
    const int b = bh / Hn, h = bh % Hn;
    const __half* qb = QKV + (size_t)b * Sq * QKVLD + h * DKh;
    const __half* kb = QKV + (size_t)b * Sq * QKVLD + 512 + h * DKh;
    float* sbp = Sc + (size_t)bh * Sq * Sq;
    const int q0 = blockIdx.y * 64, k0 = blockIdx.x * 64;
    const int wid = threadIdx.x >> 5;
    const int wm = wid & 1, wn = wid >> 1;

    wmma::fragment<wmma::accumulator, 16, 16, 16, float> acc[2][2];
#pragma unroll
    for (int i = 0; i < 2; i++)
#pragma unroll
        for (int j = 0; j < 2; j++) wmma::fill_fragment(acc[i][j], 0.f);

#pragma unroll
    for (int d0 = 0; d0 < DKh; d0 += 16) {
        wmma::fragment<wmma::matrix_a, 16, 16, 16, __half, wmma::row_major> af[2];
        wmma::fragment<wmma::matrix_b, 16, 16, 16, __half, wmma::col_major> bf[2];
#pragma unroll
        for (int i = 0; i < 2; i++)
            wmma::load_matrix_sync(af[i], &qb[(size_t)(q0 + wm * 32 + i * 16) * QKVLD + d0], QKVLD);
#pragma unroll
        for (int j = 0; j < 2; j++)
            wmma::load_matrix_sync(bf[j], &kb[(size_t)(k0 + wn * 32 + j * 16) * QKVLD + d0], QKVLD);
#pragma unroll
        for (int i = 0; i < 2; i++)
#pragma unroll
            for (int j = 0; j < 2; j++)
                wmma::mma_sync(acc[i][j], af[i], bf[j], acc[i][j]);
    }
#pragma unroll
    for (int i = 0; i < 2; i++)
#pragma unroll
        for (int j = 0; j < 2; j++) {
#pragma unroll
            for (int e = 0; e < acc[i][j].num_elements; e++) acc[i][j].x[e] *= 0.125f;
            wmma::store_matrix_sync(
                &sbp[(size_t)(q0 + wm * 32 + i * 16) * Sq + k0 + wn * 32 + j * 16],
                acc[i][j], Sq, wmma::mem_row_major);
        }
}

// softmax: read fp32 scores, write half probs
__global__ void softmax_kernel(const float* __restrict__ s, __half* __restrict__ p) {
    const float* sp = s + (size_t)blockIdx.x * Sq;
    __half* pp = p + (size_t)blockIdx.x * Sq;
    int t = threadIdx.x;
    float a = sp[t], b = sp[t + 256];
    __shared__ float sh[32];
    float m = blockReduceMax(fmaxf(a, b), sh);
    float e0 = __expf(a - m), e1 = __expf(b - m);
    float sum = blockReduceSum(e0 + e1, sh);
    float inv = 1.0f / sum;
    pp[t]       = __float2half(e0 * inv);
    pp[t + 256] = __float2half(e1 * inv);
}

// O = P @ V, half in, half out (via smem stage)
__global__ __launch_bounds__(128)
void attn_av_wmma(const __half* __restrict__ P, const __half* __restrict__ QKV,
                  __half* __restrict__ O) {
    const int bh = blockIdx.z;
    const int b = bh / Hn, h = bh % Hn;
    const __half* sbp = P + (size_t)bh * Sq * Sq;
    const __half* vb = QKV + (size_t)b * Sq * QKVLD + 1024 + h * DKh;
    __half* ob = O + (size_t)b * Sq * Dm + h * DKh;
    const int q0 = blockIdx.y * 64;
    const int tid = threadIdx.x;
    const int wid = tid >> 5;
    const int wm = wid & 1, wn = wid >> 1;

    __shared__ float stg[64][68];

    wmma::fragment<wmma::accumulator, 16, 16, 16, float> acc[2][2];
#pragma unroll
    for (int i = 0; i < 2; i++)
#pragma unroll
        for (int j = 0; j < 2; j++) wmma::fill_fragment(acc[i][j], 0.f);

    for (int k0 = 0; k0 < Sq; k0 += 16) {
        wmma::fragment<wmma::matrix_a, 16, 16, 16, __half, wmma::row_major> af[2];
        wmma::fragment<wmma::matrix_b, 16, 16, 16, __half, wmma::row_major> bf[2];
#pragma unroll
        for (int i = 0; i < 2; i++)
            wmma::load_matrix_sync(af[i], &sbp[(size_t)(q0 + wm * 32 + i * 16) * Sq + k0], Sq);
#pragma unroll
        for (int j = 0; j < 2; j++)
            wmma::load_matrix_sync(bf[j], &vb[(size_t)k0 * QKVLD + wn * 32 + j * 16], QKVLD);
#pragma unroll
        for (int i = 0; i < 2; i++)
#pragma unroll
            for (int j = 0; j < 2; j++)
                wmma::mma_sync(acc[i][j], af[i], bf[j], acc[i][j]);
    }
#pragma unroll
    for (int i = 0; i < 2; i++)
#pragma unroll
        for (int j = 0; j < 2; j++)
            wmma::store_matrix_sync(&stg[wm * 32 + i * 16][wn * 32 + j * 16],
                                    acc[i][j], 68, wmma::mem_row_major);
    __syncthreads();
    // write 64x64 halfs
#pragma unroll
    for (int it = 0; it < 16; it++) {
        int idx = it * 128 + tid;        // 2048 half2 slots
        int r = idx >> 5, c2 = idx & 31;
        __half2 h = __floats2half2_rn(stg[r][c2 * 2], stg[r][c2 * 2 + 1]);
        *reinterpret_cast<uint32_t*>(&ob[(size_t)(q0 + r) * Dm + c2 * 2]) = *(uint32_t*)&h;
    }
}

// LN: half in (a [+ res]), half out; fp32 math
__global__ void ln_kernel(const __half* __restrict__ a, const __half* __restrict__ res,
                          const float* __restrict__ g, const float* __restrict__ beta,
                          __half* __restrict__ out) {
    const size_t row = blockIdx.x;
    const int t = threadIdx.x;    // 256, 2 elems each via half2
    __half2 a2 = reinterpret_cast<const __half2*>(a + row * Dm)[t];
    float v0 = __half2float(__low2half(a2)), v1 = __half2float(__high2half(a2));
    if (res) {
        __half2 r2 = reinterpret_cast<const __half2*>(res + row * Dm)[t];
        v0 += __half2float(__low2half(r2));
        v1 += __half2float(__high2half(r2));
    }
    __shared__ float sh[32];
    float s = blockReduceSum(v0 + v1, sh);
    float mean = s * (1.0f / Dm);
    float d0 = v0 - mean, d1 = v1 - mean;
    float ss = blockReduceSum(d0 * d0 + d1 * d1, sh);
    float inv = rsqrtf(ss * (1.0f / Dm) + 1e-5f);
    float o0 = d0 * inv * g[2 * t] + beta[2 * t];
    float o1 = d1 * inv * g[2 * t + 1] + beta[2 * t + 1];
    reinterpret_cast<__half2*>(out + row * Dm)[t] = __floats2half2_rn(o0, o1);
}

// ================= orchestration =================
extern "C" void kernel_launch(void* const* d_in, const int* in_sizes, int n_in,
                              void* d_out, int out_size) {
    const int*   ids  = (const int*)  d_in[0];
    const float* tok  = (const float*)d_in[1];
    const float* pos  = (const float*)d_in[2];
    const float* Wq   = (const float*)d_in[3];
    const float* bq   = (const float*)d_in[4];
    const float* Wk   = (const float*)d_in[5];
    const float* bk   = (const float*)d_in[6];
    const float* Wv   = (const float*)d_in[7];
    const float* bv   = (const float*)d_in[8];
    const float* Wo   = (const float*)d_in[9];
    const float* bo   = (const float*)d_in[10];
    const float* ln_g = (const float*)d_in[11];
    const float* ln_b = (const float*)d_in[12];
    const float* W1   = (const float*)d_in[13];
    const float* b1   = (const float*)d_in[14];
    const float* W2   = (const float*)d_in[15];
    const float* b2   = (const float*)d_in[16];
    const float* on_g = (const float*)d_in[17];
    const float* on_b = (const float*)d_in[18];
    const float* Wout = (const float*)d_in[19];
    const float* bout = (const float*)d_in[20];
    float* out = (float*)d_out;

    __half *x, *qkv, *t, *tmp, *p, *ff, *wqkv, *wo, *w1, *w2, *wout;
    float *sc, *bqkv, *boutp;
    cudaGetSymbolAddress((void**)&x,     g_x);
    cudaGetSymbolAddress((void**)&qkv,   g_qkv);
    cudaGetSymbolAddress((void**)&t,     g_t);
    cudaGetSymbolAddress((void**)&tmp,   g_tmp);
    cudaGetSymbolAddress((void**)&sc,    g_sc);
    cudaGetSymbolAddress((void**)&p,     g_p);
    cudaGetSymbolAddress((void**)&ff,    g_ff);
    cudaGetSymbolAddress((void**)&wqkv,  g_wqkv);
    cudaGetSymbolAddress((void**)&wo,    g_wo);
    cudaGetSymbolAddress((void**)&w1,    g_w1);
    cudaGetSymbolAddress((void**)&w2,    g_w2);
    cudaGetSymbolAddress((void**)&wout,  g_wout);
    cudaGetSymbolAddress((void**)&bqkv,  g_bqkv);
    cudaGetSymbolAddress((void**)&boutp, g_bout);

    cudaFuncSetAttribute(gemm_h1<0>, cudaFuncAttributeMaxDynamicSharedMemorySize, H1_BYTES);
    cudaFuncSetAttribute(gemm_h2<0,1>, cudaFuncAttributeMaxDynamicSharedMemorySize, H2_BYTES);
    cudaFuncSetAttribute(gemm_h2<1,1>, cudaFuncAttributeMaxDynamicSharedMemorySize, H2_BYTES);
    cudaFuncSetAttribute(gemm_h2<0,0>, cudaFuncAttributeMaxDynamicSharedMemorySize, H2_BYTES);

    // ---- weight preprocessing ----
    {
        size_t n4;
        n4 = (size_t)Lyr * Dm * (QKVLD / 4);
        build_wqkv<<<(unsigned)((n4 + 255) / 256), 256>>>(Wq, Wk, Wv, wqkv);
        n4 = (size_t)Lyr * Dm * Dm / 4;
        cvt_copy_h<<<(unsigned)((n4 + 255) / 256), 256>>>(Wo, wo, n4);
        n4 = (size_t)Dm * DFFn / 4;
        cvt_copy_h<<<(unsigned)((n4 + 255) / 256), 256>>>(W1, w1, n4);
        cvt_copy_h<<<(unsigned)((n4 + 255) / 256), 256>>>(W2, w2, n4);
        pad_cvt_wout<<<4096, 256>>>(Wout, wout, bout, boutp);
        concat_bias<<<(Lyr * QKVLD + 255) / 256, 256>>>(bq, bk, bv, bqkv);
    }

    embed_kernel<<<NTOK, 128>>>(ids, tok, pos, x);

    const dim3 gScores(Sq / 64, Sq / 64, Bsz * Hn);
    const dim3 gAV(1, Sq / 64, Bsz * Hn);

    for (int l = 0; l < Lyr; l++) {
        const size_t bOff = (size_t)l * Dm;
        gemm_h2<0,1><<<dim3(QKVLD / 256, NTOK / 128), 256, H2_BYTES>>>(
            Dm, x, wqkv + (size_t)l * Dm * QKVLD, QKVLD,
            bqkv + (size_t)l * QKVLD, qkv, QKVLD, QKVLD);

        attn_scores_wmma<<<gScores, 128>>>(qkv, sc);
        softmax_kernel<<<Bsz * Hn * Sq, 256>>>(sc, p);
        attn_av_wmma<<<gAV, 128>>>(p, qkv, t);

        gemm_h1<0><<<dim3(Dm / 128, NTOK / 128), 256, H1_BYTES>>>(
            Dm, t, wo + (size_t)l * Dm * Dm, Dm, bo + bOff, tmp, Dm);
        ln_kernel<<<NTOK, 256>>>(x, tmp, ln_g + bOff, ln_b + bOff, x);
    }

    // FFN
    gemm_h2<1,1><<<dim3(DFFn / 256, NTOK / 128), 256, H2_BYTES>>>(
        Dm, x, w1, DFFn, b1, ff, DFFn, DFFn);
    gemm_h1<0><<<dim3(Dm / 128, NTOK / 128), 256, H1_BYTES>>>(
        DFFn, ff, w2, Dm, b2, t, Dm);
    ln_kernel<<<NTOK, 256>>>(t, nullptr, on_g, on_b, x);

    // logits (float out to d_out)
    gemm_h2<0,0><<<dim3(VPAD / 256, NTOK / 128), 256, H2_BYTES>>>(
        Dm, x, wout, VPAD, boutp, out, VOCn, VOCn);
}

// round 7
// speedup vs baseline: 4.0875x; 1.0408x over previous
#include <cuda_runtime.h>
#include <cuda_fp16.h>
#include <mma.h>
#include <cstdint>
#include <math.h>

using namespace nvcuda;

#define Bsz 4
#define Sq 512
#define Dm 512
#define Hn 8
#define DKh 64
#define Lyr 6
#define DFFn 2048
#define VOCn 50257
#define NTOK (Bsz*Sq)      // 2048
#define VPAD 50432         // 197*256
#define QKVLD 1536

// ---------------- helpers ----------------
__device__ __forceinline__ uint32_t smem_u32(const void* p) {
    uint32_t a;
    asm("{ .reg .u64 t; cvta.to.shared.u64 t, %1; cvt.u32.u64 %0, t; }" : "=r"(a) : "l"(p));
    return a;
}
#define CP_ASYNC16(dst, src) \
    asm volatile("cp.async.cg.shared.global [%0], [%1], 16;" :: "r"(dst), "l"(src))
#define CP_COMMIT()  asm volatile("cp.async.commit_group;" ::: "memory")
#define CP_WAIT(n)   asm volatile("cp.async.wait_group %0;" :: "n"(n) : "memory")

// ---------------- device scratch ----------------
__device__ __half g_x[NTOK*Dm];
__device__ __half g_qkv[(size_t)NTOK*QKVLD];
__device__ __half g_t[NTOK*Dm];
__device__ __half g_tmp[NTOK*Dm];
__device__ __half g_ff[(size_t)NTOK*DFFn];
__device__ __half g_wqkv[(size_t)Lyr*Dm*QKVLD];
__device__ __half g_wo[(size_t)Lyr*Dm*Dm];
__device__ __half g_w1[(size_t)Dm*DFFn];
__device__ __half g_w2[(size_t)DFFn*Dm];
__device__ __half g_wout[(size_t)Dm*VPAD];
__device__ float  g_bqkv[Lyr*QKVLD];
__device__ float  g_bout[VPAD];

// ---------------- reductions ----------------
__device__ __forceinline__ float blockReduceSum(float v, float* sh) {
    int lane = threadIdx.x & 31, w = threadIdx.x >> 5;
#pragma unroll
    for (int o = 16; o; o >>= 1) v += __shfl_xor_sync(0xffffffffu, v, o);
    if (!lane) sh[w] = v;
    __syncthreads();
    if (threadIdx.x < 8) {
        v = sh[threadIdx.x];
#pragma unroll
        for (int o = 4; o; o >>= 1) v += __shfl_xor_sync(0xffu, v, o);
        if (!threadIdx.x) sh[0] = v;
    }
    __syncthreads();
    float r = sh[0];
    __syncthreads();
    return r;
}

// ---------------- small kernels ----------------
__global__ void embed_kernel(const int* __restrict__ ids,
                             const float* __restrict__ tok,
                             const float* __restrict__ pos,
                             __half* __restrict__ x) {
    int row = blockIdx.x;
    int s = row % Sq;
    int id = ids[row];
    const float4* t4 = reinterpret_cast<const float4*>(tok) + (size_t)id * (Dm / 4);
    const float4* p4 = reinterpret_cast<const float4*>(pos) + (size_t)s * (Dm / 4);
    int t = threadIdx.x;   // 128
    float4 a = t4[t], b = p4[t];
    __half2 h0 = __floats2half2_rn(a.x + b.x, a.y + b.y);
    __half2 h1 = __floats2half2_rn(a.z + b.z, a.w + b.w);
    reinterpret_cast<uint2*>(x + (size_t)row * Dm)[t] = make_uint2(*(uint32_t*)&h0, *(uint32_t*)&h1);
}

__global__ void cvt_copy_h(const float* __restrict__ in, __half* __restrict__ out, size_t n4) {
    size_t i = (size_t)blockIdx.x * blockDim.x + threadIdx.x;
    if (i >= n4) return;
    float4 v = reinterpret_cast<const float4*>(in)[i];
    __half2 h0 = __floats2half2_rn(v.x, v.y);
    __half2 h1 = __floats2half2_rn(v.z, v.w);
    reinterpret_cast<uint2*>(out)[i] = make_uint2(*(uint32_t*)&h0, *(uint32_t*)&h1);
}

__global__ void build_wqkv(const float* __restrict__ Wq, const float* __restrict__ Wk,
                           const float* __restrict__ Wv, __half* __restrict__ out) {
    size_t i = (size_t)blockIdx.x * blockDim.x + threadIdx.x;
    size_t total = (size_t)Lyr * Dm * (QKVLD / 4);
    if (i >= total) return;
    size_t n4 = i % (QKVLD / 4);
    size_t k  = (i / (QKVLD / 4)) % Dm;
    size_t l  = i / ((size_t)(QKVLD / 4) * Dm);
    const float* src = (n4 < 128) ? Wq : (n4 < 256) ? Wk : Wv;
    size_t nn = (n4 % 128) * 4;
    float4 v = *reinterpret_cast<const float4*>(&src[(l * Dm + k) * Dm + nn]);
    __half2 h0 = __floats2half2_rn(v.x, v.y);
    __half2 h1 = __floats2half2_rn(v.z, v.w);
    reinterpret_cast<uint2*>(out)[i] = make_uint2(*(uint32_t*)&h0, *(uint32_t*)&h1);
}

__global__ void pad_cvt_wout(const float* __restrict__ src, __half* __restrict__ dst,
                             const float* __restrict__ bsrc, float* __restrict__ bdst) {
    const size_t total = (size_t)Dm * VPAD;
    for (size_t i = (size_t)blockIdx.x * blockDim.x + threadIdx.x; i < total;
         i += (size_t)gridDim.x * blockDim.x) {
        size_t r = i / VPAD, c = i % VPAD;
        dst[i] = (c < VOCn) ? __float2half(src[r * VOCn + c]) : __half(0.f);
        if (i < VPAD) bdst[i] = (i < VOCn) ? bsrc[i] : 0.f;
    }
}

__global__ void concat_bias(const float* __restrict__ bq, const float* __restrict__ bk,
                            const float* __restrict__ bv, float* __restrict__ o) {
    int i = blockIdx.x * blockDim.x + threadIdx.x;
    if (i >= Lyr * QKVLD) return;
    int l = i / QKVLD, j = i % QKVLD;
    float v = (j < 512) ? bq[l * 512 + j] : (j < 1024) ? bk[l * 512 + j - 512]
                                                       : bv[l * 512 + j - 1024];
    o[i] = v;
}

// ================= GEMM h2: 128x256, BK=32, half, 1 CTA/SM =================
#define H2_BYTES 82944

template <int ACT, int OUTH>
__global__ __launch_bounds__(256, 1)
void gemm_h2(int K, const __half* __restrict__ A,
             const __half* __restrict__ W, int ldw,
             const float* __restrict__ bias,
             void* __restrict__ Cv, int ldc, int Nc) {
    extern __shared__ char smraw[];
    __half* As = reinterpret_cast<__half*>(smraw);
    __half* Bs = reinterpret_cast<__half*>(smraw + 30720);
    const uint32_t sb = smem_u32(smraw);
    const uint32_t sbB = sb + 30720;

    const int tid = threadIdx.x;
    const int wid = tid >> 5;
    const int wm = wid & 1, wn = wid >> 1;
    const int crow = blockIdx.y * 128;
    const int ccol = blockIdx.x * 256;

    wmma::fragment<wmma::accumulator, 16, 16, 16, float> acc[4][4];
#pragma unroll
    for (int i = 0; i < 4; i++)
#pragma unroll
        for (int j = 0; j < 4; j++) wmma::fill_fragment(acc[i][j], 0.f);

    const __half* Ab = A + (size_t)crow * K;
    const int T = K >> 5;

    auto issue_stage = [&](int st, int t) {
        const int k0 = t << 5;
#pragma unroll
        for (int rep = 0; rep < 2; rep++) {
            int c = rep * 256 + tid;
            int row = c >> 2, seg = c & 3;
            CP_ASYNC16(sb + st * 10240 + row * 80 + seg * 16,
                       &Ab[(size_t)row * K + k0 + seg * 8]);
        }
#pragma unroll
        for (int rep = 0; rep < 4; rep++) {
            int c = rep * 256 + tid;
            int row = c >> 5, seg = c & 31;
            CP_ASYNC16(sbB + st * 17408 + row * 544 + seg * 16,
                       &W[(size_t)(k0 + row) * ldw + ccol + seg * 8]);
        }
        CP_COMMIT();
    };

    issue_stage(0, 0);
    issue_stage(1, 1);

    for (int t = 0; t < T; t++) {
        if (t + 2 < T) issue_stage((t + 2) % 3, t + 2);
        CP_WAIT(2);
        __syncthreads();
        const int st = t % 3;
        __half* Ast = As + st * 128 * 40;
        __half* Bst = Bs + st * 32 * 272;
#pragma unroll
        for (int ks = 0; ks < 2; ks++) {
            wmma::fragment<wmma::matrix_a, 16, 16, 16, __half, wmma::row_major> af[4];
            wmma::fragment<wmma::matrix_b, 16, 16, 16, __half, wmma::row_major> bf[4];
#pragma unroll
            for (int i = 0; i < 4; i++)
                wmma::load_matrix_sync(af[i], Ast + (wm * 64 + i * 16) * 40 + ks * 16, 40);
#pragma unroll
            for (int j = 0; j < 4; j++)
                wmma::load_matrix_sync(bf[j], Bst + (ks * 16) * 272 + wn * 64 + j * 16, 272);
#pragma unroll
            for (int i = 0; i < 4; i++)
#pragma unroll
                for (int j = 0; j < 4; j++)
                    wmma::mma_sync(acc[i][j], af[i], bf[j], acc[i][j]);
        }
        __syncthreads();
    }

    float* stg = reinterpret_cast<float*>(smraw);
#pragma unroll
    for (int i = 0; i < 4; i++) {
        __syncthreads();
#pragma unroll
        for (int j = 0; j < 4; j++)
            wmma::store_matrix_sync(stg + wid * 1088 + j * 16, acc[i][j], 68, wmma::mem_row_major);
        __syncthreads();
#pragma unroll
        for (int it = 0; it < 8; it++) {
            int idx = it * 256 + tid;
            int r = idx >> 6;
            int c4 = (idx & 63) * 4;
            int wmg = r >> 4, rr = r & 15;
            int wng = c4 >> 6, cc = c4 & 63;
            const float* sp = stg + (wng * 2 + wmg) * 1088 + rr * 68 + cc;
            int row = crow + wmg * 64 + i * 16 + rr;
            int colb = ccol + c4;
            float4 bvv = *reinterpret_cast<const float4*>(&bias[colb]);
            float v0 = sp[0] + bvv.x, v1 = sp[1] + bvv.y;
            float v2 = sp[2] + bvv.z, v3 = sp[3] + bvv.w;
            if (ACT == 1) {
                v0 = 0.5f * v0 * (1.0f + erff(v0 * 0.70710678118654752f));
                v1 = 0.5f * v1 * (1.0f + erff(v1 * 0.70710678118654752f));
                v2 = 0.5f * v2 * (1.0f + erff(v2 * 0.70710678118654752f));
                v3 = 0.5f * v3 * (1.0f + erff(v3 * 0.70710678118654752f));
            }
            if (OUTH == 1) {
                __half* C = reinterpret_cast<__half*>(Cv);
                __half2 h0 = __floats2half2_rn(v0, v1);
                __half2 h1 = __floats2half2_rn(v2, v3);
                *reinterpret_cast<uint2*>(&C[(size_t)row * ldc + colb]) =
                    make_uint2(*(uint32_t*)&h0, *(uint32_t*)&h1);
            } else {
                float* C = reinterpret_cast<float*>(Cv);
                float* cp = &C[(size_t)row * ldc + colb];
                if (colb + 0 < Nc) cp[0] = v0;
                if (colb + 1 < Nc) cp[1] = v1;
                if (colb + 2 < Nc) cp[2] = v2;
                if (colb + 3 < Nc) cp[3] = v3;
            }
        }
    }
}

// ================= GEMM h3: 64x128, BK=32, half, 3 CTA/SM =================
// smem: A [3][64][40]h (15360B) + B [3][32][144]h (27648B) = 43008B
#define H3_BYTES 43008

template <int ACT>
__global__ __launch_bounds__(128, 3)
void gemm_h3(int K, const __half* __restrict__ A,
             const __half* __restrict__ W, int ldw,
             const float* __restrict__ bias,
             __half* __restrict__ C, int ldc) {
    extern __shared__ char smraw[];
    __half* As = reinterpret_cast<__half*>(smraw);            // [3][64][40]
    __half* Bs = reinterpret_cast<__half*>(smraw + 15360);    // [3][32][144]
    const uint32_t sb = smem_u32(smraw);
    const uint32_t sbB = sb + 15360;

    const int tid = threadIdx.x;
    const int wid = tid >> 5;                 // 0..3
    const int wm = wid & 1, wn = wid >> 1;    // 2x2 warps, warp tile 32x64
    const int crow = blockIdx.y * 64;
    const int ccol = blockIdx.x * 128;

    wmma::fragment<wmma::accumulator, 16, 16, 16, float> acc[2][4];
#pragma unroll
    for (int i = 0; i < 2; i++)
#pragma unroll
        for (int j = 0; j < 4; j++) wmma::fill_fragment(acc[i][j], 0.f);

    const __half* Ab = A + (size_t)crow * K;
    const int T = K >> 5;

    auto issue_stage = [&](int st, int t) {
        const int k0 = t << 5;
        // A: 64 rows x 4 segs = 256 chunks
#pragma unroll
        for (int rep = 0; rep < 2; rep++) {
            int c = rep * 128 + tid;
            int row = c >> 2, seg = c & 3;
            CP_ASYNC16(sb + st * 5120 + row * 80 + seg * 16,
                       &Ab[(size_t)row * K + k0 + seg * 8]);
        }
        // B: 32 rows x 16 segs = 512 chunks
#pragma unroll
        for (int rep = 0; rep < 4; rep++) {
            int c = rep * 128 + tid;
            int row = c >> 4, seg = c & 15;
            CP_ASYNC16(sbB + st * 9216 + row * 288 + seg * 16,
                       &W[(size_t)(k0 + row) * ldw + ccol + seg * 8]);
        }
        CP_COMMIT();
    };

    issue_stage(0, 0);
    issue_stage(1, 1);

    for (int t = 0; t < T; t++) {
        if (t + 2 < T) issue_stage((t + 2) % 3, t + 2);
        CP_WAIT(2);
        __syncthreads();
        const int st = t % 3;
        __half* Ast = As + st * 64 * 40;
        __half* Bst = Bs + st * 32 * 144;
#pragma unroll
        for (int ks = 0; ks < 2; ks++) {
            wmma::fragment<wmma::matrix_a, 16, 16, 16, __half, wmma::row_major> af[2];
            wmma::fragment<wmma::matrix_b, 16, 16, 16, __half, wmma::row_major> bf[4];
#pragma unroll
            for (int i = 0; i < 2; i++)
                wmma::load_matrix_sync(af[i], Ast + (wm * 32 + i * 16) * 40 + ks * 16, 40);
#pragma unroll
            for (int j = 0; j < 4; j++)
                wmma::load_matrix_sync(bf[j], Bst + (ks * 16) * 144 + wn * 64 + j * 16, 144);
#pragma unroll
            for (int i = 0; i < 2; i++)
#pragma unroll
                for (int j = 0; j < 4; j++)
                    wmma::mma_sync(acc[i][j], af[i], bf[j], acc[i][j]);
        }
        __syncthreads();
    }

    float* stg = reinterpret_cast<float*>(smraw);   // [4][16][68] = 17408B
#pragma unroll
    for (int i = 0; i < 2; i++) {
        __syncthreads();
#pragma unroll
        for (int j = 0; j < 4; j++)
            wmma::store_matrix_sync(stg + wid * 1088 + j * 16, acc[i][j], 68, wmma::mem_row_major);
        __syncthreads();
#pragma unroll
        for (int it = 0; it < 8; it++) {
            int idx = it * 128 + tid;            // 1024 float4 slots = 32 rows x 32 c4
            int r = idx >> 5;                     // 0..31
            int c4 = (idx & 31) * 4;              // 0..124
            int wmg = r >> 4, rr = r & 15;
            int wng = c4 >> 6, cc = c4 & 63;
            const float* sp = stg + (wng * 2 + wmg) * 1088 + rr * 68 + cc;
            int row = crow + wmg * 32 + i * 16 + rr;
            int colb = ccol + c4;
            float4 bvv = *reinterpret_cast<const float4*>(&bias[colb]);
            float v0 = sp[0] + bvv.x, v1 = sp[1] + bvv.y;
            float v2 = sp[2] + bvv.z, v3 = sp[3] + bvv.w;
            if (ACT == 1) {
                v0 = 0.5f * v0 * (1.0f + erff(v0 * 0.70710678118654752f));
                v1 = 0.5f * v1 * (1.0f + erff(v1 * 0.70710678118654752f));
                v2 = 0.5f * v2 * (1.0f + erff(v2 * 0.70710678118654752f));
                v3 = 0.5f * v3 * (1.0f + erff(v3 * 0.70710678118654752f));
            }
            __half2 h0 = __floats2half2_rn(v0, v1);
            __half2 h1 = __floats2half2_rn(v2, v3);
            *reinterpret_cast<uint2*>(&C[(size_t)row * ldc + colb]) =
                make_uint2(*(uint32_t*)&h0, *(uint32_t*)&h1);
        }
    }
}

// ================= fused attention =================
// One CTA = (b, h, q-tile of 64). Phase1: S = 0.125*QK^T -> smem fp32.
// Phase2: row softmax in smem -> half P. Phase3: O = P @ V -> global half.
#define ATT_SLD 516
#define ATT_PLD 528
#define ATT_BYTES (64*ATT_SLD*4 + 64*ATT_PLD*2)   // 132096 + 67584 = 199680

__global__ __launch_bounds__(256, 1)
void attn_fused(const __half* __restrict__ QKV, __half* __restrict__ O) {
    extern __shared__ char sm[];
    float* Ssm = reinterpret_cast<float*>(sm);                       // [64][516]
    __half* Psm = reinterpret_cast<__half*>(sm + 64 * ATT_SLD * 4);  // [64][528]

    const int tid = threadIdx.x;
    const int wid = tid >> 5, lane = tid & 31;
    const int bh = blockIdx.y;
    const int b = bh >> 3, h = bh & 7;
    const int q0 = blockIdx.x * 64;

    const __half* qb = QKV + (size_t)b * Sq * QKVLD + h * DKh;
    const __half* kb = QKV + (size_t)b * Sq * QKVLD + 512 + h * DKh;
    const __half* vb = QKV + (size_t)b * Sq * QKVLD + 1024 + h * DKh;

    // ---- Phase 1: scores. 8 warps = 4(q) x 2(k); warp tile 16q x 256k ----
    {
        const int wq = wid & 3, wk = wid >> 2;
        wmma::fragment<wmma::accumulator, 16, 16, 16, float> acc[16];
#pragma unroll
        for (int j = 0; j < 16; j++) wmma::fill_fragment(acc[j], 0.f);

#pragma unroll
        for (int d0 = 0; d0 < DKh; d0 += 16) {
            wmma::fragment<wmma::matrix_a, 16, 16, 16, __half, wmma::row_major> af;
            wmma::load_matrix_sync(af, &qb[(size_t)(q0 + wq * 16) * QKVLD + d0], QKVLD);
#pragma unroll
            for (int j = 0; j < 16; j++) {
                wmma::fragment<wmma::matrix_b, 16, 16, 16, __half, wmma::col_major> bf;
                wmma::load_matrix_sync(bf, &kb[(size_t)(wk * 256 + j * 16) * QKVLD + d0], QKVLD);
                wmma::mma_sync(acc[j], af, bf, acc[j]);
            }
        }
#pragma unroll
        for (int j = 0; j < 16; j++) {
#pragma unroll
            for (int e = 0; e < acc[j].num_elements; e++) acc[j].x[e] *= 0.125f;
            wmma::store_matrix_sync(&Ssm[(wq * 16) * ATT_SLD + wk * 256 + j * 16],
                                    acc[j], ATT_SLD, wmma::mem_row_major);
        }
    }
    __syncthreads();

    // ---- Phase 2: softmax. warp w owns rows w*8..w*8+7; 4 lanes per row ----
    {
        const int row = wid * 8 + (lane >> 2);
        const int sub = lane & 3;
        const float* srow = Ssm + row * ATT_SLD;
        __half* prow = Psm + row * ATT_PLD;

        float mx = -1e30f;
#pragma unroll 8
        for (int i = 0; i < 128; i++) mx = fmaxf(mx, srow[sub + 4 * i]);
        mx = fmaxf(mx, __shfl_xor_sync(0xffffffffu, mx, 1));
        mx = fmaxf(mx, __shfl_xor_sync(0xffffffffu, mx, 2));

        float sum = 0.f;
#pragma unroll 8
        for (int i = 0; i < 128; i++) {
            float e = __expf(srow[sub + 4 * i] - mx);
            sum += e;
            prow[sub + 4 * i] = __float2half(e);
        }
        sum += __shfl_xor_sync(0xffffffffu, sum, 1);
        sum += __shfl_xor_sync(0xffffffffu, sum, 2);
        float inv = 1.0f / sum;
#pragma unroll 8
        for (int i = 0; i < 128; i++) {
            int c = sub + 4 * i;
            prow[c] = __float2half(__half2float(prow[c]) * inv);
        }
    }
    __syncthreads();

    // ---- Phase 3: O = P @ V. 8 warps = 4(q) x 2(d); warp tile 16q x 32d ----
    {
        const int wq = wid & 3, wd = wid >> 2;
        wmma::fragment<wmma::accumulator, 16, 16, 16, float> acc[2];
#pragma unroll
        for (int j = 0; j < 2; j++) wmma::fill_fragment(acc[j], 0.f);

        for (int k0 = 0; k0 < Sq; k0 += 16) {
            wmma::fragment<wmma::matrix_a, 16, 16, 16, __half, wmma::row_major> af;
            wmma::load_matrix_sync(af, &Psm[(wq * 16) * ATT_PLD + k0], ATT_PLD);
#pragma unroll
            for (int j = 0; j < 2; j++) {
                wmma::fragment<wmma::matrix_b, 16, 16, 16, __half, wmma::row_major> bf;
                wmma::load_matrix_sync(bf, &vb[(size_t)k0 * QKVLD + wd * 32 + j * 16], QKVLD);
                wmma::mma_sync(acc[j], af, bf, acc[j]);
            }
        }
        // stage into Ssm reused as [64][68] floats (each warp writes a distinct area)
        float* stg = Ssm;
#pragma unroll
        for (int j = 0; j < 2; j++)
            wmma::store_matrix_sync(&stg[(wq * 16) * 68 + wd * 32 + j * 16],
                                    acc[j], 68, wmma::mem_row_major);
    }
    __syncthreads();
    {
        float* stg = Ssm;
        __half* ob = O + (size_t)b * Sq * Dm + h * DKh;
#pragma unroll
        for (int it = 0; it < 8; it++) {
            int idx = it * 256 + tid;        // 2048 half2 slots = 64 rows x 32
            int r = idx >> 5, c2 = idx & 31;
            __half2 hh = __floats2half2_rn(stg[r * 68 + c2 * 2], stg[r * 68 + c2 * 2 + 1]);
            *reinterpret_cast<uint32_t*>(&ob[(size_t)(q0 + r) * Dm + c2 * 2]) = *(uint32_t*)&hh;
        }
    }
}

// LN: half in (a [+ res]), half out; fp32 math
__global__ void ln_kernel(const __half* __restrict__ a, const __half* __restrict__ res,
                          const float* __restrict__ g, const float* __restrict__ beta,
                          __half* __restrict__ out) {
    const size_t row = blockIdx.x;
    const int t = threadIdx.x;
    __half2 a2 = reinterpret_cast<const __half2*>(a + row * Dm)[t];
    float v0 = __half2float(__low2half(a2)), v1 = __half2float(__high2half(a2));
    if (res) {
        __half2 r2 = reinterpret_cast<const __half2*>(res + row * Dm)[t];
        v0 += __half2float(__low2half(r2));
        v1 += __half2float(__high2half(r2));
    }
    __shared__ float sh[32];
    float s = blockReduceSum(v0 + v1, sh);
    float mean = s * (1.0f / Dm);
    float d0 = v0 - mean, d1 = v1 - mean;
    float ss = blockReduceSum(d0 * d0 + d1 * d1, sh);
    float inv = rsqrtf(ss * (1.0f / Dm) + 1e-5f);
    float o0 = d0 * inv * g[2 * t] + beta[2 * t];
    float o1 = d1 * inv * g[2 * t + 1] + beta[2 * t + 1];
    reinterpret_cast<__half2*>(out + row * Dm)[t] = __floats2half2_rn(o0, o1);
}

// ================= orchestration =================
extern "C" void kernel_launch(void* const* d_in, const int* in_sizes, int n_in,
                              void* d_out, int out_size) {
    const int*   ids  = (const int*)  d_in[0];
    const float* tok  = (const float*)d_in[1];
    const float* pos  = (const float*)d_in[2];
    const float* Wq   = (const float*)d_in[3];
    const float* bq   = (const float*)d_in[4];
    const float* Wk   = (const float*)d_in[5];
    const float* bk   = (const float*)d_in[6];
    const float* Wv   = (const float*)d_in[7];
    const float* bv   = (const float*)d_in[8];
    const float* Wo   = (const float*)d_in[9];
    const float* bo   = (const float*)d_in[10];
    const float* ln_g = (const float*)d_in[11];
    const float* ln_b = (const float*)d_in[12];
    const float* W1   = (const float*)d_in[13];
    const float* b1   = (const float*)d_in[14];
    const float* W2   = (const float*)d_in[15];
    const float* b2   = (const float*)d_in[16];
    const float* on_g = (const float*)d_in[17];
    const float* on_b = (const float*)d_in[18];
    const float* Wout = (const float*)d_in[19];
    const float* bout = (const float*)d_in[20];
    float* out = (float*)d_out;

    __half *x, *qkv, *t, *tmp, *ff, *wqkv, *wo, *w1, *w2, *wout;
    float *bqkv, *boutp;
    cudaGetSymbolAddress((void**)&x,     g_x);
    cudaGetSymbolAddress((void**)&qkv,   g_qkv);
    cudaGetSymbolAddress((void**)&t,     g_t);
    cudaGetSymbolAddress((void**)&tmp,   g_tmp);
    cudaGetSymbolAddress((void**)&ff,    g_ff);
    cudaGetSymbolAddress((void**)&wqkv,  g_wqkv);
    cudaGetSymbolAddress((void**)&wo,    g_wo);
    cudaGetSymbolAddress((void**)&w1,    g_w1);
    cudaGetSymbolAddress((void**)&w2,    g_w2);
    cudaGetSymbolAddress((void**)&wout,  g_wout);
    cudaGetSymbolAddress((void**)&bqkv,  g_bqkv);
    cudaGetSymbolAddress((void**)&boutp, g_bout);

    cudaFuncSetAttribute(gemm_h2<0,1>, cudaFuncAttributeMaxDynamicSharedMemorySize, H2_BYTES);
    cudaFuncSetAttribute(gemm_h2<1,1>, cudaFuncAttributeMaxDynamicSharedMemorySize, H2_BYTES);
    cudaFuncSetAttribute(gemm_h2<0,0>, cudaFuncAttributeMaxDynamicSharedMemorySize, H2_BYTES);
    cudaFuncSetAttribute(gemm_h3<0>,   cudaFuncAttributeMaxDynamicSharedMemorySize, H3_BYTES);
    cudaFuncSetAttribute(attn_fused,   cudaFuncAttributeMaxDynamicSharedMemorySize, ATT_BYTES);

    // ---- weight preprocessing ----
    {
        size_t n4;
        n4 = (size_t)Lyr * Dm * (QKVLD / 4);
        build_wqkv<<<(unsigned)((n4 + 255) / 256), 256>>>(Wq, Wk, Wv, wqkv);
        n4 = (size_t)Lyr * Dm * Dm / 4;
        cvt_copy_h<<<(unsigned)((n4 + 255) / 256), 256>>>(Wo, wo, n4);
        n4 = (size_t)Dm * DFFn / 4;
        cvt_copy_h<<<(unsigned)((n4 + 255) / 256), 256>>>(W1, w1, n4);
        cvt_copy_h<<<(unsigned)((n4 + 255) / 256), 256>>>(W2, w2, n4);
        pad_cvt_wout<<<4096, 256>>>(Wout, wout, bout, boutp);
        concat_bias<<<(Lyr * QKVLD + 255) / 256, 256>>>(bq, bk, bv, bqkv);
    }

    embed_kernel<<<NTOK, 128>>>(ids, tok, pos, x);

    for (int l = 0; l < Lyr; l++) {
        const size_t bOff = (size_t)l * Dm;
        // fused QKV via h3: grid (1536/128=12, 2048/64=32) = 384 CTAs
        gemm_h3<0><<<dim3(QKVLD / 128, NTOK / 64), 128, H3_BYTES>>>(
            Dm, x, wqkv + (size_t)l * Dm * QKVLD, QKVLD,
            bqkv + (size_t)l * QKVLD, qkv, QKVLD);

        attn_fused<<<dim3(Sq / 64, Bsz * Hn), 256, ATT_BYTES>>>(qkv, t);

        // O-proj via h3: grid (4, 32) = 128 CTAs
        gemm_h3<0><<<dim3(Dm / 128, NTOK / 64), 128, H3_BYTES>>>(
            Dm, t, wo + (size_t)l * Dm * Dm, Dm, bo + bOff, tmp, Dm);
        ln_kernel<<<NTOK, 256>>>(x, tmp, ln_g + bOff, ln_b + bOff, x);
    }

    // FFN1 (N=2048) via h2
    gemm_h2<1,1><<<dim3(DFFn / 256, NTOK / 128), 256, H2_BYTES>>>(
        Dm, x, w1, DFFn, b1, ff, DFFn, DFFn);
    // FFN2 (N=512, K=2048) via h3: grid (4, 32)
    gemm_h3<0><<<dim3(Dm / 128, NTOK / 64), 128, H3_BYTES>>>(
        DFFn, ff, w2, Dm, b2, t, Dm);
    ln_kernel<<<NTOK, 256>>>(t, nullptr, on_g, on_b, x);

    // logits
    gemm_h2<0,0><<<dim3(VPAD / 256, NTOK / 128), 256, H2_BYTES>>>(
        Dm, x, wout, VPAD, boutp, out, VOCn, VOCn);
}

// round 8
// speedup vs baseline: 4.1540x; 1.0163x over previous
#include <cuda_runtime.h>
#include <cuda_fp16.h>
#include <mma.h>
#include <cstdint>
#include <math.h>

using namespace nvcuda;

#define Bsz 4
#define Sq 512
#define Dm 512
#define Hn 8
#define DKh 64
#define Lyr 6
#define DFFn 2048
#define VOCn 50257
#define NTOK (Bsz*Sq)      // 2048
#define VPAD 50432         // 197*256
#define QKVLD 1536

// ---------------- helpers ----------------
__device__ __forceinline__ uint32_t smem_u32(const void* p) {
    uint32_t a;
    asm("{ .reg .u64 t; cvta.to.shared.u64 t, %1; cvt.u32.u64 %0, t; }" : "=r"(a) : "l"(p));
    return a;
}
#define CP_ASYNC16(dst, src) \
    asm volatile("cp.async.cg.shared.global [%0], [%1], 16;" :: "r"(dst), "l"(src))
#define CP_COMMIT()  asm volatile("cp.async.commit_group;" ::: "memory")
#define CP_WAIT(n)   asm volatile("cp.async.wait_group %0;" :: "n"(n) : "memory")

// ---------------- device scratch ----------------
__device__ __half g_x[NTOK*Dm];
__device__ __half g_qkv[(size_t)NTOK*QKVLD];
__device__ __half g_t[NTOK*Dm];
__device__ __half g_tmp[NTOK*Dm];
__device__ __half g_ff[(size_t)NTOK*DFFn];
__device__ __half g_wqkv[(size_t)Lyr*Dm*QKVLD];
__device__ __half g_wo[(size_t)Lyr*Dm*Dm];
__device__ __half g_w1[(size_t)Dm*DFFn];
__device__ __half g_w2[(size_t)DFFn*Dm];
__device__ __half g_wout[(size_t)Dm*VPAD];
__device__ float  g_bqkv[Lyr*QKVLD];
__device__ float  g_bout[VPAD];

// ---------------- reductions ----------------
__device__ __forceinline__ float blockReduceSum(float v, float* sh) {
    int lane = threadIdx.x & 31, w = threadIdx.x >> 5;
#pragma unroll
    for (int o = 16; o; o >>= 1) v += __shfl_xor_sync(0xffffffffu, v, o);
    if (!lane) sh[w] = v;
    __syncthreads();
    if (threadIdx.x < 8) {
        v = sh[threadIdx.x];
#pragma unroll
        for (int o = 4; o; o >>= 1) v += __shfl_xor_sync(0xffu, v, o);
        if (!threadIdx.x) sh[0] = v;
    }
    __syncthreads();
    float r = sh[0];
    __syncthreads();
    return r;
}

// ---------------- prep kernels ----------------
__global__ void build_wqkv(const float* __restrict__ Wq, const float* __restrict__ Wk,
                           const float* __restrict__ Wv, __half* __restrict__ out) {
    size_t i = (size_t)blockIdx.x * blockDim.x + threadIdx.x;
    size_t total = (size_t)Lyr * Dm * (QKVLD / 4);
    if (i >= total) return;
    size_t n4 = i % (QKVLD / 4);
    size_t k  = (i / (QKVLD / 4)) % Dm;
    size_t l  = i / ((size_t)(QKVLD / 4) * Dm);
    const float* src = (n4 < 128) ? Wq : (n4 < 256) ? Wk : Wv;
    size_t nn = (n4 % 128) * 4;
    float4 v = *reinterpret_cast<const float4*>(&src[(l * Dm + k) * Dm + nn]);
    __half2 h0 = __floats2half2_rn(v.x, v.y);
    __half2 h1 = __floats2half2_rn(v.z, v.w);
    reinterpret_cast<uint2*>(out)[i] = make_uint2(*(uint32_t*)&h0, *(uint32_t*)&h1);
}

// merged conversion of Wo, W1, W2 (one launch)
#define N4_WO ((size_t)Lyr*Dm*Dm/4)
#define N4_W1 ((size_t)Dm*DFFn/4)
#define N4_W2 ((size_t)DFFn*Dm/4)
__global__ void cvt3(const float* __restrict__ Wo, const float* __restrict__ W1,
                     const float* __restrict__ W2, __half* __restrict__ wo,
                     __half* __restrict__ w1, __half* __restrict__ w2) {
    size_t i = (size_t)blockIdx.x * blockDim.x + threadIdx.x;
    const float* src; __half* dst; size_t j;
    if (i < N4_WO) { src = Wo; dst = wo; j = i; }
    else if (i < N4_WO + N4_W1) { src = W1; dst = w1; j = i - N4_WO; }
    else if (i < N4_WO + N4_W1 + N4_W2) { src = W2; dst = w2; j = i - N4_WO - N4_W1; }
    else return;
    float4 v = reinterpret_cast<const float4*>(src)[j];
    __half2 h0 = __floats2half2_rn(v.x, v.y);
    __half2 h1 = __floats2half2_rn(v.z, v.w);
    reinterpret_cast<uint2*>(dst)[j] = make_uint2(*(uint32_t*)&h0, *(uint32_t*)&h1);
}

__global__ void pad_cvt_wout(const float* __restrict__ src, __half* __restrict__ dst,
                             const float* __restrict__ bsrc, float* __restrict__ bdst) {
    const size_t total = (size_t)Dm * VPAD;
    for (size_t i = (size_t)blockIdx.x * blockDim.x + threadIdx.x; i < total;
         i += (size_t)gridDim.x * blockDim.x) {
        size_t r = i / VPAD, c = i % VPAD;
        dst[i] = (c < VOCn) ? __float2half(src[r * VOCn + c]) : __half(0.f);
        if (i < VPAD) bdst[i] = (i < VOCn) ? bsrc[i] : 0.f;
    }
}

__global__ void concat_bias(const float* __restrict__ bq, const float* __restrict__ bk,
                            const float* __restrict__ bv, float* __restrict__ o) {
    int i = blockIdx.x * blockDim.x + threadIdx.x;
    if (i >= Lyr * QKVLD) return;
    int l = i / QKVLD, j = i % QKVLD;
    float v = (j < 512) ? bq[l * 512 + j] : (j < 1024) ? bk[l * 512 + j - 512]
                                                       : bv[l * 512 + j - 1024];
    o[i] = v;
}

__global__ void embed_kernel(const int* __restrict__ ids,
                             const float* __restrict__ tok,
                             const float* __restrict__ pos,
                             __half* __restrict__ x) {
    int row = blockIdx.x;
    int s = row % Sq;
    int id = ids[row];
    const float4* t4 = reinterpret_cast<const float4*>(tok) + (size_t)id * (Dm / 4);
    const float4* p4 = reinterpret_cast<const float4*>(pos) + (size_t)s * (Dm / 4);
    int t = threadIdx.x;
    float4 a = t4[t], b = p4[t];
    __half2 h0 = __floats2half2_rn(a.x + b.x, a.y + b.y);
    __half2 h1 = __floats2half2_rn(a.z + b.z, a.w + b.w);
    reinterpret_cast<uint2*>(x + (size_t)row * Dm)[t] = make_uint2(*(uint32_t*)&h0, *(uint32_t*)&h1);
}

// ================= GEMM h2: 128x256, BK=64, half, 1 CTA/SM =================
// smem: A [3][128][72]h (55296B) + B [3][64][272]h (104448B) = 159744B
#define H2_BYTES 159744

template <int ACT, int OUTH>
__global__ __launch_bounds__(256, 1)
void gemm_h2(int K, const __half* __restrict__ A,
             const __half* __restrict__ W, int ldw,
             const float* __restrict__ bias,
             void* __restrict__ Cv, int ldc, int Nc) {
    extern __shared__ char smraw[];
    __half* As = reinterpret_cast<__half*>(smraw);
    __half* Bs = reinterpret_cast<__half*>(smraw + 55296);
    const uint32_t sb = smem_u32(smraw);
    const uint32_t sbB = sb + 55296;

    const int tid = threadIdx.x;
    const int wid = tid >> 5;
    const int wm = wid & 1, wn = wid >> 1;
    const int crow = blockIdx.y * 128;
    const int ccol = blockIdx.x * 256;

    wmma::fragment<wmma::accumulator, 16, 16, 16, float> acc[4][4];
#pragma unroll
    for (int i = 0; i < 4; i++)
#pragma unroll
        for (int j = 0; j < 4; j++) wmma::fill_fragment(acc[i][j], 0.f);

    const __half* Ab = A + (size_t)crow * K;
    const int T = K >> 6;

    auto issue_stage = [&](int st, int t) {
        const int k0 = t << 6;
        // A: 128 rows x 8 segs = 1024 chunks
#pragma unroll
        for (int rep = 0; rep < 4; rep++) {
            int c = rep * 256 + tid;
            int row = c >> 3, seg = c & 7;
            CP_ASYNC16(sb + st * 18432 + row * 144 + seg * 16,
                       &Ab[(size_t)row * K + k0 + seg * 8]);
        }
        // B: 64 rows x 32 segs = 2048 chunks
#pragma unroll
        for (int rep = 0; rep < 8; rep++) {
            int c = rep * 256 + tid;
            int row = c >> 5, seg = c & 31;
            CP_ASYNC16(sbB + st * 34816 + row * 544 + seg * 16,
                       &W[(size_t)(k0 + row) * ldw + ccol + seg * 8]);
        }
        CP_COMMIT();
    };

    issue_stage(0, 0);
    issue_stage(1, 1);

    for (int t = 0; t < T; t++) {
        CP_WAIT(1);
        __syncthreads();
        if (t + 2 < T) issue_stage((t + 2) % 3, t + 2); else CP_COMMIT();
        const int st = t % 3;
        __half* Ast = As + st * 128 * 72;
        __half* Bst = Bs + st * 64 * 272;
#pragma unroll
        for (int ks = 0; ks < 4; ks++) {
            wmma::fragment<wmma::matrix_a, 16, 16, 16, __half, wmma::row_major> af[4];
            wmma::fragment<wmma::matrix_b, 16, 16, 16, __half, wmma::row_major> bf[4];
#pragma unroll
            for (int i = 0; i < 4; i++)
                wmma::load_matrix_sync(af[i], Ast + (wm * 64 + i * 16) * 72 + ks * 16, 72);
#pragma unroll
            for (int j = 0; j < 4; j++)
                wmma::load_matrix_sync(bf[j], Bst + (ks * 16) * 272 + wn * 64 + j * 16, 272);
#pragma unroll
            for (int i = 0; i < 4; i++)
#pragma unroll
                for (int j = 0; j < 4; j++)
                    wmma::mma_sync(acc[i][j], af[i], bf[j], acc[i][j]);
        }
    }

    float* stg = reinterpret_cast<float*>(smraw);
#pragma unroll
    for (int i = 0; i < 4; i++) {
        __syncthreads();
#pragma unroll
        for (int j = 0; j < 4; j++)
            wmma::store_matrix_sync(stg + wid * 1088 + j * 16, acc[i][j], 68, wmma::mem_row_major);
        __syncthreads();
#pragma unroll
        for (int it = 0; it < 8; it++) {
            int idx = it * 256 + tid;
            int r = idx >> 6;
            int c4 = (idx & 63) * 4;
            int wmg = r >> 4, rr = r & 15;
            int wng = c4 >> 6, cc = c4 & 63;
            const float* sp = stg + (wng * 2 + wmg) * 1088 + rr * 68 + cc;
            int row = crow + wmg * 64 + i * 16 + rr;
            int colb = ccol + c4;
            float4 bvv = *reinterpret_cast<const float4*>(&bias[colb]);
            float v0 = sp[0] + bvv.x, v1 = sp[1] + bvv.y;
            float v2 = sp[2] + bvv.z, v3 = sp[3] + bvv.w;
            if (ACT == 1) {
                v0 = 0.5f * v0 * (1.0f + erff(v0 * 0.70710678118654752f));
                v1 = 0.5f * v1 * (1.0f + erff(v1 * 0.70710678118654752f));
                v2 = 0.5f * v2 * (1.0f + erff(v2 * 0.70710678118654752f));
                v3 = 0.5f * v3 * (1.0f + erff(v3 * 0.70710678118654752f));
            }
            if (OUTH == 1) {
                __half* C = reinterpret_cast<__half*>(Cv);
                __half2 h0 = __floats2half2_rn(v0, v1);
                __half2 h1 = __floats2half2_rn(v2, v3);
                *reinterpret_cast<uint2*>(&C[(size_t)row * ldc + colb]) =
                    make_uint2(*(uint32_t*)&h0, *(uint32_t*)&h1);
            } else {
                float* C = reinterpret_cast<float*>(Cv);
                float* cp = &C[(size_t)row * ldc + colb];
                if (colb + 0 < Nc) cp[0] = v0;
                if (colb + 1 < Nc) cp[1] = v1;
                if (colb + 2 < Nc) cp[2] = v2;
                if (colb + 3 < Nc) cp[3] = v3;
            }
        }
    }
}

// ================= GEMM h3: 64x128, BK=32, half, 3 CTA/SM =================
#define H3_BYTES 43008

template <int ACT>
__global__ __launch_bounds__(128, 3)
void gemm_h3(int K, const __half* __restrict__ A,
             const __half* __restrict__ W, int ldw,
             const float* __restrict__ bias,
             __half* __restrict__ C, int ldc) {
    extern __shared__ char smraw[];
    __half* As = reinterpret_cast<__half*>(smraw);            // [3][64][40]
    __half* Bs = reinterpret_cast<__half*>(smraw + 15360);    // [3][32][144]
    const uint32_t sb = smem_u32(smraw);
    const uint32_t sbB = sb + 15360;

    const int tid = threadIdx.x;
    const int wid = tid >> 5;
    const int wm = wid & 1, wn = wid >> 1;
    const int crow = blockIdx.y * 64;
    const int ccol = blockIdx.x * 128;

    wmma::fragment<wmma::accumulator, 16, 16, 16, float> acc[2][4];
#pragma unroll
    for (int i = 0; i < 2; i++)
#pragma unroll
        for (int j = 0; j < 4; j++) wmma::fill_fragment(acc[i][j], 0.f);

    const __half* Ab = A + (size_t)crow * K;
    const int T = K >> 5;

    auto issue_stage = [&](int st, int t) {
        const int k0 = t << 5;
#pragma unroll
        for (int rep = 0; rep < 2; rep++) {
            int c = rep * 128 + tid;
            int row = c >> 2, seg = c & 3;
            CP_ASYNC16(sb + st * 5120 + row * 80 + seg * 16,
                       &Ab[(size_t)row * K + k0 + seg * 8]);
        }
#pragma unroll
        for (int rep = 0; rep < 4; rep++) {
            int c = rep * 128 + tid;
            int row = c >> 4, seg = c & 15;
            CP_ASYNC16(sbB + st * 9216 + row * 288 + seg * 16,
                       &W[(size_t)(k0 + row) * ldw + ccol + seg * 8]);
        }
        CP_COMMIT();
    };

    issue_stage(0, 0);
    issue_stage(1, 1);

    for (int t = 0; t < T; t++) {
        CP_WAIT(1);
        __syncthreads();
        if (t + 2 < T) issue_stage((t + 2) % 3, t + 2); else CP_COMMIT();
        const int st = t % 3;
        __half* Ast = As + st * 64 * 40;
        __half* Bst = Bs + st * 32 * 144;
#pragma unroll
        for (int ks = 0; ks < 2; ks++) {
            wmma::fragment<wmma::matrix_a, 16, 16, 16, __half, wmma::row_major> af[2];
            wmma::fragment<wmma::matrix_b, 16, 16, 16, __half, wmma::row_major> bf[4];
#pragma unroll
            for (int i = 0; i < 2; i++)
                wmma::load_matrix_sync(af[i], Ast + (wm * 32 + i * 16) * 40 + ks * 16, 40);
#pragma unroll
            for (int j = 0; j < 4; j++)
                wmma::load_matrix_sync(bf[j], Bst + (ks * 16) * 144 + wn * 64 + j * 16, 144);
#pragma unroll
            for (int i = 0; i < 2; i++)
#pragma unroll
                for (int j = 0; j < 4; j++)
                    wmma::mma_sync(acc[i][j], af[i], bf[j], acc[i][j]);
        }
    }

    float* stg = reinterpret_cast<float*>(smraw);
#pragma unroll
    for (int i = 0; i < 2; i++) {
        __syncthreads();
#pragma unroll
        for (int j = 0; j < 4; j++)
            wmma::store_matrix_sync(stg + wid * 1088 + j * 16, acc[i][j], 68, wmma::mem_row_major);
        __syncthreads();
#pragma unroll
        for (int it = 0; it < 8; it++) {
            int idx = it * 128 + tid;
            int r = idx >> 5;
            int c4 = (idx & 31) * 4;
            int wmg = r >> 4, rr = r & 15;
            int wng = c4 >> 6, cc = c4 & 63;
            const float* sp = stg + (wng * 2 + wmg) * 1088 + rr * 68 + cc;
            int row = crow + wmg * 32 + i * 16 + rr;
            int colb = ccol + c4;
            float4 bvv = *reinterpret_cast<const float4*>(&bias[colb]);
            float v0 = sp[0] + bvv.x, v1 = sp[1] + bvv.y;
            float v2 = sp[2] + bvv.z, v3 = sp[3] + bvv.w;
            if (ACT == 1) {
                v0 = 0.5f * v0 * (1.0f + erff(v0 * 0.70710678118654752f));
                v1 = 0.5f * v1 * (1.0f + erff(v1 * 0.70710678118654752f));
                v2 = 0.5f * v2 * (1.0f + erff(v2 * 0.70710678118654752f));
                v3 = 0.5f * v3 * (1.0f + erff(v3 * 0.70710678118654752f));
            }
            __half2 h0 = __floats2half2_rn(v0, v1);
            __half2 h1 = __floats2half2_rn(v2, v3);
            *reinterpret_cast<uint2*>(&C[(size_t)row * ldc + colb]) =
                make_uint2(*(uint32_t*)&h0, *(uint32_t*)&h1);
        }
    }
}

// ================= fused attention =================
#define ATT_SLD 516
#define ATT_PLD 528
#define ATT_BYTES (64*ATT_SLD*4 + 64*ATT_PLD*2)

__global__ __launch_bounds__(256, 1)
void attn_fused(const __half* __restrict__ QKV, __half* __restrict__ O) {
    extern __shared__ char sm[];
    float* Ssm = reinterpret_cast<float*>(sm);
    __half* Psm = reinterpret_cast<__half*>(sm + 64 * ATT_SLD * 4);

    const int tid = threadIdx.x;
    const int wid = tid >> 5, lane = tid & 31;
    const int bh = blockIdx.y;
    const int b = bh >> 3, h = bh & 7;
    const int q0 = blockIdx.x * 64;

    const __half* qb = QKV + (size_t)b * Sq * QKVLD + h * DKh;
    const __half* kb = QKV + (size_t)b * Sq * QKVLD + 512 + h * DKh;
    const __half* vb = QKV + (size_t)b * Sq * QKVLD + 1024 + h * DKh;

    {
        const int wq = wid & 3, wk = wid >> 2;
        wmma::fragment<wmma::accumulator, 16, 16, 16, float> acc[16];
#pragma unroll
        for (int j = 0; j < 16; j++) wmma::fill_fragment(acc[j], 0.f);

#pragma unroll
        for (int d0 = 0; d0 < DKh; d0 += 16) {
            wmma::fragment<wmma::matrix_a, 16, 16, 16, __half, wmma::row_major> af;
            wmma::load_matrix_sync(af, &qb[(size_t)(q0 + wq * 16) * QKVLD + d0], QKVLD);
#pragma unroll
            for (int j = 0; j < 16; j++) {
                wmma::fragment<wmma::matrix_b, 16, 16, 16, __half, wmma::col_major> bf;
                wmma::load_matrix_sync(bf, &kb[(size_t)(wk * 256 + j * 16) * QKVLD + d0], QKVLD);
                wmma::mma_sync(acc[j], af, bf, acc[j]);
            }
        }
#pragma unroll
        for (int j = 0; j < 16; j++) {
#pragma unroll
            for (int e = 0; e < acc[j].num_elements; e++) acc[j].x[e] *= 0.125f;
            wmma::store_matrix_sync(&Ssm[(wq * 16) * ATT_SLD + wk * 256 + j * 16],
                                    acc[j], ATT_SLD, wmma::mem_row_major);
        }
    }
    __syncthreads();

    {
        const int row = wid * 8 + (lane >> 2);
        const int sub = lane & 3;
        const float* srow = Ssm + row * ATT_SLD;
        __half* prow = Psm + row * ATT_PLD;

        float mx = -1e30f;
#pragma unroll 8
        for (int i = 0; i < 128; i++) mx = fmaxf(mx, srow[sub + 4 * i]);
        mx = fmaxf(mx, __shfl_xor_sync(0xffffffffu, mx, 1));
        mx = fmaxf(mx, __shfl_xor_sync(0xffffffffu, mx, 2));

        float sum = 0.f;
#pragma unroll 8
        for (int i = 0; i < 128; i++) {
            float e = __expf(srow[sub + 4 * i] - mx);
            sum += e;
            prow[sub + 4 * i] = __float2half(e);
        }
        sum += __shfl_xor_sync(0xffffffffu, sum, 1);
        sum += __shfl_xor_sync(0xffffffffu, sum, 2);
        float inv = 1.0f / sum;
#pragma unroll 8
        for (int i = 0; i < 128; i++) {
            int c = sub + 4 * i;
            prow[c] = __float2half(__half2float(prow[c]) * inv);
        }
    }
    __syncthreads();

    {
        const int wq = wid & 3, wd = wid >> 2;
        wmma::fragment<wmma::accumulator, 16, 16, 16, float> acc[2];
#pragma unroll
        for (int j = 0; j < 2; j++) wmma::fill_fragment(acc[j], 0.f);

        for (int k0 = 0; k0 < Sq; k0 += 16) {
            wmma::fragment<wmma::matrix_a, 16, 16, 16, __half, wmma::row_major> af;
            wmma::load_matrix_sync(af, &Psm[(wq * 16) * ATT_PLD + k0], ATT_PLD);
#pragma unroll
            for (int j = 0; j < 2; j++) {
                wmma::fragment<wmma::matrix_b, 16, 16, 16, __half, wmma::row_major> bf;
                wmma::load_matrix_sync(bf, &vb[(size_t)k0 * QKVLD + wd * 32 + j * 16], QKVLD);
                wmma::mma_sync(acc[j], af, bf, acc[j]);
            }
        }
        float* stg = Ssm;
#pragma unroll
        for (int j = 0; j < 2; j++)
            wmma::store_matrix_sync(&stg[(wq * 16) * 68 + wd * 32 + j * 16],
                                    acc[j], 68, wmma::mem_row_major);
    }
    __syncthreads();
    {
        float* stg = Ssm;
        __half* ob = O + (size_t)b * Sq * Dm + h * DKh;
#pragma unroll
        for (int it = 0; it < 8; it++) {
            int idx = it * 256 + tid;
            int r = idx >> 5, c2 = idx & 31;
            __half2 hh = __floats2half2_rn(stg[r * 68 + c2 * 2], stg[r * 68 + c2 * 2 + 1]);
            *reinterpret_cast<uint32_t*>(&ob[(size_t)(q0 + r) * Dm + c2 * 2]) = *(uint32_t*)&hh;
        }
    }
}

__global__ void ln_kernel(const __half* __restrict__ a, const __half* __restrict__ res,
                          const float* __restrict__ g, const float* __restrict__ beta,
                          __half* __restrict__ out) {
    const size_t row = blockIdx.x;
    const int t = threadIdx.x;
    __half2 a2 = reinterpret_cast<const __half2*>(a + row * Dm)[t];
    float v0 = __half2float(__low2half(a2)), v1 = __half2float(__high2half(a2));
    if (res) {
        __half2 r2 = reinterpret_cast<const __half2*>(res + row * Dm)[t];
        v0 += __half2float(__low2half(r2));
        v1 += __half2float(__high2half(r2));
    }
    __shared__ float sh[32];
    float s = blockReduceSum(v0 + v1, sh);
    float mean = s * (1.0f / Dm);
    float d0 = v0 - mean, d1 = v1 - mean;
    float ss = blockReduceSum(d0 * d0 + d1 * d1, sh);
    float inv = rsqrtf(ss * (1.0f / Dm) + 1e-5f);
    float o0 = d0 * inv * g[2 * t] + beta[2 * t];
    float o1 = d1 * inv * g[2 * t + 1] + beta[2 * t + 1];
    reinterpret_cast<__half2*>(out + row * Dm)[t] = __floats2half2_rn(o0, o1);
}

// ================= orchestration =================
extern "C" void kernel_launch(void* const* d_in, const int* in_sizes, int n_in,
                              void* d_out, int out_size) {
    const int*   ids  = (const int*)  d_in[0];
    const float* tok  = (const float*)d_in[1];
    const float* pos  = (const float*)d_in[2];
    const float* Wq   = (const float*)d_in[3];
    const float* bq   = (const float*)d_in[4];
    const float* Wk   = (const float*)d_in[5];
    const float* bk   = (const float*)d_in[6];
    const float* Wv   = (const float*)d_in[7];
    const float* bv   = (const float*)d_in[8];
    const float* Wo   = (const float*)d_in[9];
    const float* bo   = (const float*)d_in[10];
    const float* ln_g = (const float*)d_in[11];
    const float* ln_b = (const float*)d_in[12];
    const float* W1   = (const float*)d_in[13];
    const float* b1   = (const float*)d_in[14];
    const float* W2   = (const float*)d_in[15];
    const float* b2   = (const float*)d_in[16];
    const float* on_g = (const float*)d_in[17];
    const float* on_b = (const float*)d_in[18];
    const float* Wout = (const float*)d_in[19];
    const float* bout = (const float*)d_in[20];
    float* out = (float*)d_out;

    __half *x, *qkv, *t, *tmp, *ff, *wqkv, *wo, *w1, *w2, *wout;
    float *bqkv, *boutp;
    cudaGetSymbolAddress((void**)&x,     g_x);
    cudaGetSymbolAddress((void**)&qkv,   g_qkv);
    cudaGetSymbolAddress((void**)&t,     g_t);
    cudaGetSymbolAddress((void**)&tmp,   g_tmp);
    cudaGetSymbolAddress((void**)&ff,    g_ff);
    cudaGetSymbolAddress((void**)&wqkv,  g_wqkv);
    cudaGetSymbolAddress((void**)&wo,    g_wo);
    cudaGetSymbolAddress((void**)&w1,    g_w1);
    cudaGetSymbolAddress((void**)&w2,    g_w2);
    cudaGetSymbolAddress((void**)&wout,  g_wout);
    cudaGetSymbolAddress((void**)&bqkv,  g_bqkv);
    cudaGetSymbolAddress((void**)&boutp, g_bout);

    cudaFuncSetAttribute(gemm_h2<0,1>, cudaFuncAttributeMaxDynamicSharedMemorySize, H2_BYTES);
    cudaFuncSetAttribute(gemm_h2<1,1>, cudaFuncAttributeMaxDynamicSharedMemorySize, H2_BYTES);
    cudaFuncSetAttribute(gemm_h2<0,0>, cudaFuncAttributeMaxDynamicSharedMemorySize, H2_BYTES);
    cudaFuncSetAttribute(gemm_h3<0>,   cudaFuncAttributeMaxDynamicSharedMemorySize, H3_BYTES);
    cudaFuncSetAttribute(attn_fused,   cudaFuncAttributeMaxDynamicSharedMemorySize, ATT_BYTES);

    // ---- prep: exactly 4 launches so launch #5 is the QKV GEMM ----
    {
        size_t n4 = (size_t)Lyr * Dm * (QKVLD / 4);
        build_wqkv<<<(unsigned)((n4 + 255) / 256), 256>>>(Wq, Wk, Wv, wqkv);       // 0
        size_t tot = N4_WO + N4_W1 + N4_W2;
        cvt3<<<(unsigned)((tot + 255) / 256), 256>>>(Wo, W1, W2, wo, w1, w2);      // 1
        pad_cvt_wout<<<4096, 256>>>(Wout, wout, bout, boutp);                      // 2
        concat_bias<<<(Lyr * QKVLD + 255) / 256, 256>>>(bq, bk, bv, bqkv);         // 3
    }

    embed_kernel<<<NTOK, 128>>>(ids, tok, pos, x);                                 // 4

    for (int l = 0; l < Lyr; l++) {
        const size_t bOff = (size_t)l * Dm;
        gemm_h3<0><<<dim3(QKVLD / 128, NTOK / 64), 128, H3_BYTES>>>(               // 5 (l=0)
            Dm, x, wqkv + (size_t)l * Dm * QKVLD, QKVLD,
            bqkv + (size_t)l * QKVLD, qkv, QKVLD);

        attn_fused<<<dim3(Sq / 64, Bsz * Hn), 256, ATT_BYTES>>>(qkv, t);

        gemm_h3<0><<<dim3(Dm / 128, NTOK / 64), 128, H3_BYTES>>>(
            Dm, t, wo + (size_t)l * Dm * Dm, Dm, bo + bOff, tmp, Dm);
        ln_kernel<<<NTOK, 256>>>(x, tmp, ln_g + bOff, ln_b + bOff, x);
    }

    gemm_h2<1,1><<<dim3(DFFn / 256, NTOK / 128), 256, H2_BYTES>>>(
        Dm, x, w1, DFFn, b1, ff, DFFn, DFFn);
    gemm_h3<0><<<dim3(Dm / 128, NTOK / 64), 128, H3_BYTES>>>(
        DFFn, ff, w2, Dm, b2, t, Dm);
    ln_kernel<<<NTOK, 256>>>(t, nullptr, on_g, on_b, x);

    gemm_h2<0,0><<<dim3(VPAD / 256, NTOK / 128), 256, H2_BYTES>>>(
        Dm, x, wout, VPAD, boutp, out, VOCn, VOCn);
}

// round 9
// speedup vs baseline: 4.3828x; 1.0551x over previous
#include <cuda_runtime.h>
#include <cuda_fp16.h>
#include <mma.h>
#include <cstdint>
#include <math.h>

using namespace nvcuda;

#define Bsz 4
#define Sq 512
#define Dm 512
#define Hn 8
#define DKh 64
#define Lyr 6
#define DFFn 2048
#define VOCn 50257
#define NTOK (Bsz*Sq)      // 2048
#define VPAD 50432         // 394*128
#define QKVLD 1536

// ---------------- helpers ----------------
__device__ __forceinline__ uint32_t smem_u32(const void* p) {
    uint32_t a;
    asm("{ .reg .u64 t; cvta.to.shared.u64 t, %1; cvt.u32.u64 %0, t; }" : "=r"(a) : "l"(p));
    return a;
}
#define CP_ASYNC16(dst, src) \
    asm volatile("cp.async.cg.shared.global [%0], [%1], 16;" :: "r"(dst), "l"(src))
#define CP_COMMIT()  asm volatile("cp.async.commit_group;" ::: "memory")
#define CP_WAIT(n)   asm volatile("cp.async.wait_group %0;" :: "n"(n) : "memory")

// ---------------- device scratch ----------------
__device__ __half g_x[NTOK*Dm];
__device__ __half g_qkv[(size_t)NTOK*QKVLD];
__device__ __half g_t[NTOK*Dm];
__device__ __half g_tmp[NTOK*Dm];
__device__ __half g_ff[(size_t)NTOK*DFFn];
__device__ __half g_wqkv[(size_t)Lyr*Dm*QKVLD];
__device__ __half g_wo[(size_t)Lyr*Dm*Dm];
__device__ __half g_w1[(size_t)Dm*DFFn];
__device__ __half g_w2[(size_t)DFFn*Dm];
__device__ __half g_wout[(size_t)Dm*VPAD];
__device__ float  g_bqkv[Lyr*QKVLD];
__device__ float  g_bout[VPAD];

// ---------------- prep kernels ----------------
__global__ void build_wqkv(const float* __restrict__ Wq, const float* __restrict__ Wk,
                           const float* __restrict__ Wv, __half* __restrict__ out) {
    size_t i = (size_t)blockIdx.x * blockDim.x + threadIdx.x;
    size_t total = (size_t)Lyr * Dm * (QKVLD / 4);
    if (i >= total) return;
    size_t n4 = i % (QKVLD / 4);
    size_t k  = (i / (QKVLD / 4)) % Dm;
    size_t l  = i / ((size_t)(QKVLD / 4) * Dm);
    const float* src = (n4 < 128) ? Wq : (n4 < 256) ? Wk : Wv;
    size_t nn = (n4 % 128) * 4;
    float4 v = *reinterpret_cast<const float4*>(&src[(l * Dm + k) * Dm + nn]);
    __half2 h0 = __floats2half2_rn(v.x, v.y);
    __half2 h1 = __floats2half2_rn(v.z, v.w);
    reinterpret_cast<uint2*>(out)[i] = make_uint2(*(uint32_t*)&h0, *(uint32_t*)&h1);
}

#define N4_WO ((size_t)Lyr*Dm*Dm/4)
#define N4_W1 ((size_t)Dm*DFFn/4)
#define N4_W2 ((size_t)DFFn*Dm/4)
__global__ void cvt3(const float* __restrict__ Wo, const float* __restrict__ W1,
                     const float* __restrict__ W2, __half* __restrict__ wo,
                     __half* __restrict__ w1, __half* __restrict__ w2) {
    size_t i = (size_t)blockIdx.x * blockDim.x + threadIdx.x;
    const float* src; __half* dst; size_t j;
    if (i < N4_WO) { src = Wo; dst = wo; j = i; }
    else if (i < N4_WO + N4_W1) { src = W1; dst = w1; j = i - N4_WO; }
    else if (i < N4_WO + N4_W1 + N4_W2) { src = W2; dst = w2; j = i - N4_WO - N4_W1; }
    else return;
    float4 v = reinterpret_cast<const float4*>(src)[j];
    __half2 h0 = __floats2half2_rn(v.x, v.y);
    __half2 h1 = __floats2half2_rn(v.z, v.w);
    reinterpret_cast<uint2*>(dst)[j] = make_uint2(*(uint32_t*)&h0, *(uint32_t*)&h1);
}

__global__ void pad_cvt_wout(const float* __restrict__ src, __half* __restrict__ dst,
                             const float* __restrict__ bsrc, float* __restrict__ bdst) {
    const size_t total = (size_t)Dm * VPAD;
    for (size_t i = (size_t)blockIdx.x * blockDim.x + threadIdx.x; i < total;
         i += (size_t)gridDim.x * blockDim.x) {
        size_t r = i / VPAD, c = i % VPAD;
        dst[i] = (c < VOCn) ? __float2half(src[r * VOCn + c]) : __half(0.f);
        if (i < VPAD) bdst[i] = (i < VOCn) ? bsrc[i] : 0.f;
    }
}

__global__ void concat_bias(const float* __restrict__ bq, const float* __restrict__ bk,
                            const float* __restrict__ bv, float* __restrict__ o) {
    int i = blockIdx.x * blockDim.x + threadIdx.x;
    if (i >= Lyr * QKVLD) return;
    int l = i / QKVLD, j = i % QKVLD;
    float v = (j < 512) ? bq[l * 512 + j] : (j < 1024) ? bk[l * 512 + j - 512]
                                                       : bv[l * 512 + j - 1024];
    o[i] = v;
}

__global__ void embed_kernel(const int* __restrict__ ids,
                             const float* __restrict__ tok,
                             const float* __restrict__ pos,
                             __half* __restrict__ x) {
    int row = blockIdx.x;
    int s = row % Sq;
    int id = ids[row];
    const float4* t4 = reinterpret_cast<const float4*>(tok) + (size_t)id * (Dm / 4);
    const float4* p4 = reinterpret_cast<const float4*>(pos) + (size_t)s * (Dm / 4);
    int t = threadIdx.x;
    float4 a = t4[t], b = p4[t];
    __half2 h0 = __floats2half2_rn(a.x + b.x, a.y + b.y);
    __half2 h1 = __floats2half2_rn(a.z + b.z, a.w + b.w);
    reinterpret_cast<uint2*>(x + (size_t)row * Dm)[t] = make_uint2(*(uint32_t*)&h0, *(uint32_t*)&h1);
}

// ================= GEMM hL: 128x128, BK=64, half, 2 CTA/SM =================
// smem: A [3][128][72]h (55296B) + B [3][64][136]h (52224B) = 107520B
#define HL_BYTES 107520

template <int ACT, int OUTH>
__global__ __launch_bounds__(256, 2)
void gemm_hL(int K, const __half* __restrict__ A,
             const __half* __restrict__ W, int ldw,
             const float* __restrict__ bias,
             void* __restrict__ Cv, int ldc, int Nc) {
    extern __shared__ char smraw[];
    __half* As = reinterpret_cast<__half*>(smraw);            // [3][128][72]
    __half* Bs = reinterpret_cast<__half*>(smraw + 55296);    // [3][64][136]
    const uint32_t sb = smem_u32(smraw);
    const uint32_t sbB = sb + 55296;

    const int tid = threadIdx.x;
    const int wid = tid >> 5;
    const int wm = wid & 3, wn = wid >> 2;   // 4x2 warps, warp tile 32x64
    const int crow = blockIdx.y * 128;
    const int ccol = blockIdx.x * 128;

    wmma::fragment<wmma::accumulator, 16, 16, 16, float> acc[2][4];
#pragma unroll
    for (int i = 0; i < 2; i++)
#pragma unroll
        for (int j = 0; j < 4; j++) wmma::fill_fragment(acc[i][j], 0.f);

    const __half* Ab = A + (size_t)crow * K;
    const int T = K >> 6;

    auto issue_stage = [&](int st, int t) {
        const int k0 = t << 6;
        // A: 128 rows x 8 segs = 1024 chunks
#pragma unroll
        for (int rep = 0; rep < 4; rep++) {
            int c = rep * 256 + tid;
            int row = c >> 3, seg = c & 7;
            CP_ASYNC16(sb + st * 18432 + row * 144 + seg * 16,
                       &Ab[(size_t)row * K + k0 + seg * 8]);
        }
        // B: 64 rows x 16 segs = 1024 chunks
#pragma unroll
        for (int rep = 0; rep < 4; rep++) {
            int c = rep * 256 + tid;
            int row = c >> 4, seg = c & 15;
            CP_ASYNC16(sbB + st * 17408 + row * 272 + seg * 16,
                       &W[(size_t)(k0 + row) * ldw + ccol + seg * 8]);
        }
        CP_COMMIT();
    };

    issue_stage(0, 0);
    issue_stage(1, 1);

    for (int t = 0; t < T; t++) {
        CP_WAIT(1);
        __syncthreads();
        if (t + 2 < T) issue_stage((t + 2) % 3, t + 2); else CP_COMMIT();
        const int st = t % 3;
        __half* Ast = As + st * 128 * 72;
        __half* Bst = Bs + st * 64 * 136;
#pragma unroll
        for (int ks = 0; ks < 4; ks++) {
            wmma::fragment<wmma::matrix_a, 16, 16, 16, __half, wmma::row_major> af[2];
            wmma::fragment<wmma::matrix_b, 16, 16, 16, __half, wmma::row_major> bf[4];
#pragma unroll
            for (int i = 0; i < 2; i++)
                wmma::load_matrix_sync(af[i], Ast + (wm * 32 + i * 16) * 72 + ks * 16, 72);
#pragma unroll
            for (int j = 0; j < 4; j++)
                wmma::load_matrix_sync(bf[j], Bst + (ks * 16) * 136 + wn * 64 + j * 16, 136);
#pragma unroll
            for (int i = 0; i < 2; i++)
#pragma unroll
                for (int j = 0; j < 4; j++)
                    wmma::mma_sync(acc[i][j], af[i], bf[j], acc[i][j]);
        }
    }

    float* stg = reinterpret_cast<float*>(smraw);   // [8][16][68]
#pragma unroll
    for (int i = 0; i < 2; i++) {
        __syncthreads();
#pragma unroll
        for (int j = 0; j < 4; j++)
            wmma::store_matrix_sync(stg + wid * 1088 + j * 16, acc[i][j], 68, wmma::mem_row_major);
        __syncthreads();
#pragma unroll
        for (int it = 0; it < 8; it++) {
            int idx = it * 256 + tid;          // 2048 float4 = 64 rows x 32 c4
            int r = idx >> 5;
            int c4 = (idx & 31) * 4;
            int wmg = r >> 4, rr = r & 15;
            int wng = c4 >> 6, cc = c4 & 63;
            const float* sp = stg + (wng * 4 + wmg) * 1088 + rr * 68 + cc;
            int row = crow + wmg * 32 + i * 16 + rr;
            int colb = ccol + c4;
            float4 bvv = *reinterpret_cast<const float4*>(&bias[colb]);
            float v0 = sp[0] + bvv.x, v1 = sp[1] + bvv.y;
            float v2 = sp[2] + bvv.z, v3 = sp[3] + bvv.w;
            if (ACT == 1) {
                v0 = 0.5f * v0 * (1.0f + erff(v0 * 0.70710678118654752f));
                v1 = 0.5f * v1 * (1.0f + erff(v1 * 0.70710678118654752f));
                v2 = 0.5f * v2 * (1.0f + erff(v2 * 0.70710678118654752f));
                v3 = 0.5f * v3 * (1.0f + erff(v3 * 0.70710678118654752f));
            }
            if (OUTH == 1) {
                __half* C = reinterpret_cast<__half*>(Cv);
                __half2 h0 = __floats2half2_rn(v0, v1);
                __half2 h1 = __floats2half2_rn(v2, v3);
                *reinterpret_cast<uint2*>(&C[(size_t)row * ldc + colb]) =
                    make_uint2(*(uint32_t*)&h0, *(uint32_t*)&h1);
            } else {
                float* C = reinterpret_cast<float*>(Cv);
                float* cp = &C[(size_t)row * ldc + colb];
                if (colb + 0 < Nc) cp[0] = v0;
                if (colb + 1 < Nc) cp[1] = v1;
                if (colb + 2 < Nc) cp[2] = v2;
                if (colb + 3 < Nc) cp[3] = v3;
            }
        }
    }
}

// ================= GEMM h3: 64x128, BK=32, half, 3 CTA/SM =================
#define H3_BYTES 43008

template <int ACT>
__global__ __launch_bounds__(128, 3)
void gemm_h3(int K, const __half* __restrict__ A,
             const __half* __restrict__ W, int ldw,
             const float* __restrict__ bias,
             __half* __restrict__ C, int ldc) {
    extern __shared__ char smraw[];
    __half* As = reinterpret_cast<__half*>(smraw);            // [3][64][40]
    __half* Bs = reinterpret_cast<__half*>(smraw + 15360);    // [3][32][144]
    const uint32_t sb = smem_u32(smraw);
    const uint32_t sbB = sb + 15360;

    const int tid = threadIdx.x;
    const int wid = tid >> 5;
    const int wm = wid & 1, wn = wid >> 1;
    const int crow = blockIdx.y * 64;
    const int ccol = blockIdx.x * 128;

    wmma::fragment<wmma::accumulator, 16, 16, 16, float> acc[2][4];
#pragma unroll
    for (int i = 0; i < 2; i++)
#pragma unroll
        for (int j = 0; j < 4; j++) wmma::fill_fragment(acc[i][j], 0.f);

    const __half* Ab = A + (size_t)crow * K;
    const int T = K >> 5;

    auto issue_stage = [&](int st, int t) {
        const int k0 = t << 5;
#pragma unroll
        for (int rep = 0; rep < 2; rep++) {
            int c = rep * 128 + tid;
            int row = c >> 2, seg = c & 3;
            CP_ASYNC16(sb + st * 5120 + row * 80 + seg * 16,
                       &Ab[(size_t)row * K + k0 + seg * 8]);
        }
#pragma unroll
        for (int rep = 0; rep < 4; rep++) {
            int c = rep * 128 + tid;
            int row = c >> 4, seg = c & 15;
            CP_ASYNC16(sbB + st * 9216 + row * 288 + seg * 16,
                       &W[(size_t)(k0 + row) * ldw + ccol + seg * 8]);
        }
        CP_COMMIT();
    };

    issue_stage(0, 0);
    issue_stage(1, 1);

    for (int t = 0; t < T; t++) {
        CP_WAIT(1);
        __syncthreads();
        if (t + 2 < T) issue_stage((t + 2) % 3, t + 2); else CP_COMMIT();
        const int st = t % 3;
        __half* Ast = As + st * 64 * 40;
        __half* Bst = Bs + st * 32 * 144;
#pragma unroll
        for (int ks = 0; ks < 2; ks++) {
            wmma::fragment<wmma::matrix_a, 16, 16, 16, __half, wmma::row_major> af[2];
            wmma::fragment<wmma::matrix_b, 16, 16, 16, __half, wmma::row_major> bf[4];
#pragma unroll
            for (int i = 0; i < 2; i++)
                wmma::load_matrix_sync(af[i], Ast + (wm * 32 + i * 16) * 40 + ks * 16, 40);
#pragma unroll
            for (int j = 0; j < 4; j++)
                wmma::load_matrix_sync(bf[j], Bst + (ks * 16) * 144 + wn * 64 + j * 16, 144);
#pragma unroll
            for (int i = 0; i < 2; i++)
#pragma unroll
                for (int j = 0; j < 4; j++)
                    wmma::mma_sync(acc[i][j], af[i], bf[j], acc[i][j]);
        }
    }

    float* stg = reinterpret_cast<float*>(smraw);
#pragma unroll
    for (int i = 0; i < 2; i++) {
        __syncthreads();
#pragma unroll
        for (int j = 0; j < 4; j++)
            wmma::store_matrix_sync(stg + wid * 1088 + j * 16, acc[i][j], 68, wmma::mem_row_major);
        __syncthreads();
#pragma unroll
        for (int it = 0; it < 8; it++) {
            int idx = it * 128 + tid;
            int r = idx >> 5;
            int c4 = (idx & 31) * 4;
            int wmg = r >> 4, rr = r & 15;
            int wng = c4 >> 6, cc = c4 & 63;
            const float* sp = stg + (wng * 2 + wmg) * 1088 + rr * 68 + cc;
            int row = crow + wmg * 32 + i * 16 + rr;
            int colb = ccol + c4;
            float4 bvv = *reinterpret_cast<const float4*>(&bias[colb]);
            float v0 = sp[0] + bvv.x, v1 = sp[1] + bvv.y;
            float v2 = sp[2] + bvv.z, v3 = sp[3] + bvv.w;
            if (ACT == 1) {
                v0 = 0.5f * v0 * (1.0f + erff(v0 * 0.70710678118654752f));
                v1 = 0.5f * v1 * (1.0f + erff(v1 * 0.70710678118654752f));
                v2 = 0.5f * v2 * (1.0f + erff(v2 * 0.70710678118654752f));
                v3 = 0.5f * v3 * (1.0f + erff(v3 * 0.70710678118654752f));
            }
            __half2 h0 = __floats2half2_rn(v0, v1);
            __half2 h1 = __floats2half2_rn(v2, v3);
            *reinterpret_cast<uint2*>(&C[(size_t)row * ldc + colb]) =
                make_uint2(*(uint32_t*)&h0, *(uint32_t*)&h1);
        }
    }
}

// ================= fused attention: q-tile 32, 2 CTA/SM =================
#define ATT_SLD 516
#define ATT_PLD 528
#define ATT_BYTES (32*ATT_SLD*4 + 32*ATT_PLD*2)   // 66048 + 33792 = 99840

__global__ __launch_bounds__(256, 2)
void attn_fused(const __half* __restrict__ QKV, __half* __restrict__ O) {
    extern __shared__ char sm[];
    float* Ssm = reinterpret_cast<float*>(sm);                       // [32][516]
    __half* Psm = reinterpret_cast<__half*>(sm + 32 * ATT_SLD * 4);  // [32][528]

    const int tid = threadIdx.x;
    const int wid = tid >> 5, lane = tid & 31;
    const int bh = blockIdx.y;
    const int b = bh >> 3, h = bh & 7;
    const int q0 = blockIdx.x * 32;

    const __half* qb = QKV + (size_t)b * Sq * QKVLD + h * DKh;
    const __half* kb = QKV + (size_t)b * Sq * QKVLD + 512 + h * DKh;
    const __half* vb = QKV + (size_t)b * Sq * QKVLD + 1024 + h * DKh;

    // Phase 1: scores. 8 warps = 2(q) x 4(k); warp tile 16q x 128k
    {
        const int wq = wid & 1, wk = wid >> 1;
        wmma::fragment<wmma::accumulator, 16, 16, 16, float> acc[8];
#pragma unroll
        for (int j = 0; j < 8; j++) wmma::fill_fragment(acc[j], 0.f);

#pragma unroll
        for (int d0 = 0; d0 < DKh; d0 += 16) {
            wmma::fragment<wmma::matrix_a, 16, 16, 16, __half, wmma::row_major> af;
            wmma::load_matrix_sync(af, &qb[(size_t)(q0 + wq * 16) * QKVLD + d0], QKVLD);
#pragma unroll
            for (int j = 0; j < 8; j++) {
                wmma::fragment<wmma::matrix_b, 16, 16, 16, __half, wmma::col_major> bf;
                wmma::load_matrix_sync(bf, &kb[(size_t)(wk * 128 + j * 16) * QKVLD + d0], QKVLD);
                wmma::mma_sync(acc[j], af, bf, acc[j]);
            }
        }
#pragma unroll
        for (int j = 0; j < 8; j++) {
#pragma unroll
            for (int e = 0; e < acc[j].num_elements; e++) acc[j].x[e] *= 0.125f;
            wmma::store_matrix_sync(&Ssm[(wq * 16) * ATT_SLD + wk * 128 + j * 16],
                                    acc[j], ATT_SLD, wmma::mem_row_major);
        }
    }
    __syncthreads();

    // Phase 2: softmax. 8 warps x 4 rows; 8 lanes per row
    {
        const int row = wid * 4 + (lane >> 3);
        const int sub = lane & 7;
        const float* srow = Ssm + row * ATT_SLD;
        __half* prow = Psm + row * ATT_PLD;

        float mx = -1e30f;
#pragma unroll 8
        for (int i = 0; i < 64; i++) mx = fmaxf(mx, srow[sub + 8 * i]);
        mx = fmaxf(mx, __shfl_xor_sync(0xffffffffu, mx, 1));
        mx = fmaxf(mx, __shfl_xor_sync(0xffffffffu, mx, 2));
        mx = fmaxf(mx, __shfl_xor_sync(0xffffffffu, mx, 4));

        float sum = 0.f;
#pragma unroll 8
        for (int i = 0; i < 64; i++) {
            float e = __expf(srow[sub + 8 * i] - mx);
            sum += e;
            prow[sub + 8 * i] = __float2half(e);
        }
        sum += __shfl_xor_sync(0xffffffffu, sum, 1);
        sum += __shfl_xor_sync(0xffffffffu, sum, 2);
        sum += __shfl_xor_sync(0xffffffffu, sum, 4);
        float inv = 1.0f / sum;
#pragma unroll 8
        for (int i = 0; i < 64; i++) {
            int c = sub + 8 * i;
            prow[c] = __float2half(__half2float(prow[c]) * inv);
        }
    }
    __syncthreads();

    // Phase 3: O = P @ V. 8 warps = 2(q) x 4(d); warp tile 16q x 16d
    {
        const int wq = wid & 1, wd = wid >> 1;
        wmma::fragment<wmma::accumulator, 16, 16, 16, float> acc;
        wmma::fill_fragment(acc, 0.f);

        for (int k0 = 0; k0 < Sq; k0 += 16) {
            wmma::fragment<wmma::matrix_a, 16, 16, 16, __half, wmma::row_major> af;
            wmma::fragment<wmma::matrix_b, 16, 16, 16, __half, wmma::row_major> bf;
            wmma::load_matrix_sync(af, &Psm[(wq * 16) * ATT_PLD + k0], ATT_PLD);
            wmma::load_matrix_sync(bf, &vb[(size_t)k0 * QKVLD + wd * 16], QKVLD);
            wmma::mma_sync(acc, af, bf, acc);
        }
        float* stg = Ssm;   // reuse as [32][68]
        wmma::store_matrix_sync(&stg[(wq * 16) * 68 + wd * 16], acc, 68, wmma::mem_row_major);
    }
    __syncthreads();
    {
        float* stg = Ssm;
        __half* ob = O + (size_t)b * Sq * Dm + h * DKh;
#pragma unroll
        for (int it = 0; it < 4; it++) {
            int idx = it * 256 + tid;        // 1024 half2 = 32 rows x 32
            int r = idx >> 5, c2 = idx & 31;
            __half2 hh = __floats2half2_rn(stg[r * 68 + c2 * 2], stg[r * 68 + c2 * 2 + 1]);
            *reinterpret_cast<uint32_t*>(&ob[(size_t)(q0 + r) * Dm + c2 * 2]) = *(uint32_t*)&hh;
        }
    }
}

// ================= warp-per-row LayerNorm (single pass) =================
// block 256 = 8 warps, each warp one row of 512; grid NTOK/8
__global__ __launch_bounds__(256)
void ln_kernel(const __half* __restrict__ a, const __half* __restrict__ res,
               const float* __restrict__ g, const float* __restrict__ beta,
               __half* __restrict__ out) {
    const int wid = threadIdx.x >> 5, lane = threadIdx.x & 31;
    const size_t row = blockIdx.x * 8 + wid;
    const __half2* a2 = reinterpret_cast<const __half2*>(a + row * Dm);
    const __half2* r2 = res ? reinterpret_cast<const __half2*>(res + row * Dm) : nullptr;

    float v[16];
    float s = 0.f, sq = 0.f;
#pragma unroll
    for (int k = 0; k < 8; k++) {
        int i = lane + 32 * k;
        __half2 h = a2[i];
        float x0 = __half2float(__low2half(h)), x1 = __half2float(__high2half(h));
        if (r2) {
            __half2 rr = r2[i];
            x0 += __half2float(__low2half(rr));
            x1 += __half2float(__high2half(rr));
        }
        v[2 * k] = x0; v[2 * k + 1] = x1;
        s += x0 + x1;
        sq += x0 * x0 + x1 * x1;
    }
#pragma unroll
    for (int o = 16; o; o >>= 1) {
        s  += __shfl_xor_sync(0xffffffffu, s, o);
        sq += __shfl_xor_sync(0xffffffffu, sq, o);
    }
    float mean = s * (1.0f / Dm);
    float var = sq * (1.0f / Dm) - mean * mean;
    float inv = rsqrtf(var + 1e-5f);

    const float2* gf = reinterpret_cast<const float2*>(g);
    const float2* bf = reinterpret_cast<const float2*>(beta);
    __half2* o2 = reinterpret_cast<__half2*>(out + row * Dm);
#pragma unroll
    for (int k = 0; k < 8; k++) {
        int i = lane + 32 * k;
        float2 gg = gf[i], bb = bf[i];
        float y0 = (v[2 * k]     - mean) * inv * gg.x + bb.x;
        float y1 = (v[2 * k + 1] - mean) * inv * gg.y + bb.y;
        o2[i] = __floats2half2_rn(y0, y1);
    }
}

// ================= orchestration =================
extern "C" void kernel_launch(void* const* d_in, const int* in_sizes, int n_in,
                              void* d_out, int out_size) {
    const int*   ids  = (const int*)  d_in[0];
    const float* tok  = (const float*)d_in[1];
    const float* pos  = (const float*)d_in[2];
    const float* Wq   = (const float*)d_in[3];
    const float* bq   = (const float*)d_in[4];
    const float* Wk   = (const float*)d_in[5];
    const float* bk   = (const float*)d_in[6];
    const float* Wv   = (const float*)d_in[7];
    const float* bv   = (const float*)d_in[8];
    const float* Wo   = (const float*)d_in[9];
    const float* bo   = (const float*)d_in[10];
    const float* ln_g = (const float*)d_in[11];
    const float* ln_b = (const float*)d_in[12];
    const float* W1   = (const float*)d_in[13];
    const float* b1   = (const float*)d_in[14];
    const float* W2   = (const float*)d_in[15];
    const float* b2   = (const float*)d_in[16];
    const float* on_g = (const float*)d_in[17];
    const float* on_b = (const float*)d_in[18];
    const float* Wout = (const float*)d_in[19];
    const float* bout = (const float*)d_in[20];
    float* out = (float*)d_out;

    __half *x, *qkv, *t, *tmp, *ff, *wqkv, *wo, *w1, *w2, *wout;
    float *bqkv, *boutp;
    cudaGetSymbolAddress((void**)&x,     g_x);
    cudaGetSymbolAddress((void**)&qkv,   g_qkv);
    cudaGetSymbolAddress((void**)&t,     g_t);
    cudaGetSymbolAddress((void**)&tmp,   g_tmp);
    cudaGetSymbolAddress((void**)&ff,    g_ff);
    cudaGetSymbolAddress((void**)&wqkv,  g_wqkv);
    cudaGetSymbolAddress((void**)&wo,    g_wo);
    cudaGetSymbolAddress((void**)&w1,    g_w1);
    cudaGetSymbolAddress((void**)&w2,    g_w2);
    cudaGetSymbolAddress((void**)&wout,  g_wout);
    cudaGetSymbolAddress((void**)&bqkv,  g_bqkv);
    cudaGetSymbolAddress((void**)&boutp, g_bout);

    cudaFuncSetAttribute(gemm_hL<0,0>, cudaFuncAttributeMaxDynamicSharedMemorySize, HL_BYTES);
    cudaFuncSetAttribute(gemm_hL<1,1>, cudaFuncAttributeMaxDynamicSharedMemorySize, HL_BYTES);
    cudaFuncSetAttribute(gemm_h3<0>,   cudaFuncAttributeMaxDynamicSharedMemorySize, H3_BYTES);
    cudaFuncSetAttribute(attn_fused,   cudaFuncAttributeMaxDynamicSharedMemorySize, ATT_BYTES);

    // ---- prep ----
    {
        size_t n4 = (size_t)Lyr * Dm * (QKVLD / 4);
        build_wqkv<<<(unsigned)((n4 + 255) / 256), 256>>>(Wq, Wk, Wv, wqkv);
        size_t tot = N4_WO + N4_W1 + N4_W2;
        cvt3<<<(unsigned)((tot + 255) / 256), 256>>>(Wo, W1, W2, wo, w1, w2);
        pad_cvt_wout<<<4096, 256>>>(Wout, wout, bout, boutp);
        concat_bias<<<(Lyr * QKVLD + 255) / 256, 256>>>(bq, bk, bv, bqkv);
    }

    embed_kernel<<<NTOK, 128>>>(ids, tok, pos, x);

    for (int l = 0; l < Lyr; l++) {
        const size_t bOff = (size_t)l * Dm;
        gemm_h3<0><<<dim3(QKVLD / 128, NTOK / 64), 128, H3_BYTES>>>(
            Dm, x, wqkv + (size_t)l * Dm * QKVLD, QKVLD,
            bqkv + (size_t)l * QKVLD, qkv, QKVLD);

        attn_fused<<<dim3(Sq / 32, Bsz * Hn), 256, ATT_BYTES>>>(qkv, t);

        gemm_h3<0><<<dim3(Dm / 128, NTOK / 64), 128, H3_BYTES>>>(
            Dm, t, wo + (size_t)l * Dm * Dm, Dm, bo + bOff, tmp, Dm);
        ln_kernel<<<NTOK / 8, 256>>>(x, tmp, ln_g + bOff, ln_b + bOff, x);
    }

    // FFN1 (N=2048) via hL: grid (16, 16) = 256 CTAs, 2/SM
    gemm_hL<1,1><<<dim3(DFFn / 128, NTOK / 128), 256, HL_BYTES>>>(
        Dm, x, w1, DFFn, b1, ff, DFFn, DFFn);
    gemm_h3<0><<<dim3(Dm / 128, NTOK / 64), 128, H3_BYTES>>>(
        DFFn, ff, w2, Dm, b2, t, Dm);
    ln_kernel<<<NTOK / 8, 256>>>(t, nullptr, on_g, on_b, x);

    // logits via hL: grid (394, 16), 2 CTA/SM
    gemm_hL<0,0><<<dim3(VPAD / 128, NTOK / 128), 256, HL_BYTES>>>(
        Dm, x, wout, VPAD, boutp, out, VOCn, VOCn);
}

// round 10
// speedup vs baseline: 4.6180x; 1.0537x over previous
#include <cuda_runtime.h>
#include <cuda_fp16.h>
#include <mma.h>
#include <cstdint>
#include <math.h>

using namespace nvcuda;

#define Bsz 4
#define Sq 512
#define Dm 512
#define Hn 8
#define DKh 64
#define Lyr 6
#define DFFn 2048
#define VOCn 50257
#define NTOK (Bsz*Sq)      // 2048
#define VPAD 50432         // 394*128
#define QKVLD 1536

// ---------------- helpers ----------------
__device__ __forceinline__ uint32_t smem_u32(const void* p) {
    uint32_t a;
    asm("{ .reg .u64 t; cvta.to.shared.u64 t, %1; cvt.u32.u64 %0, t; }" : "=r"(a) : "l"(p));
    return a;
}
#define CP_ASYNC16(dst, src) \
    asm volatile("cp.async.cg.shared.global [%0], [%1], 16;" :: "r"(dst), "l"(src))
#define CP_COMMIT()  asm volatile("cp.async.commit_group;" ::: "memory")
#define CP_WAIT(n)   asm volatile("cp.async.wait_group %0;" :: "n"(n) : "memory")

// ---------------- device scratch ----------------
__device__ __half g_x[NTOK*Dm];
__device__ __half g_qkv[(size_t)NTOK*QKVLD];
__device__ __half g_t[NTOK*Dm];
__device__ __half g_tmp[NTOK*Dm];
__device__ __half g_ff[(size_t)NTOK*DFFn];
__device__ __half g_wqkv[(size_t)Lyr*Dm*QKVLD];
__device__ __half g_wo[(size_t)Lyr*Dm*Dm];
__device__ __half g_w1[(size_t)Dm*DFFn];
__device__ __half g_w2[(size_t)DFFn*Dm];
__device__ __half g_wout[(size_t)Dm*VPAD];
__device__ float  g_bqkv[Lyr*QKVLD];
__device__ float  g_bout[VPAD];

// ---------------- prep kernels ----------------
__global__ void build_wqkv(const float* __restrict__ Wq, const float* __restrict__ Wk,
                           const float* __restrict__ Wv, __half* __restrict__ out) {
    size_t i = (size_t)blockIdx.x * blockDim.x + threadIdx.x;
    size_t total = (size_t)Lyr * Dm * (QKVLD / 4);
    if (i >= total) return;
    size_t n4 = i % (QKVLD / 4);
    size_t k  = (i / (QKVLD / 4)) % Dm;
    size_t l  = i / ((size_t)(QKVLD / 4) * Dm);
    const float* src = (n4 < 128) ? Wq : (n4 < 256) ? Wk : Wv;
    size_t nn = (n4 % 128) * 4;
    float4 v = *reinterpret_cast<const float4*>(&src[(l * Dm + k) * Dm + nn]);
    __half2 h0 = __floats2half2_rn(v.x, v.y);
    __half2 h1 = __floats2half2_rn(v.z, v.w);
    reinterpret_cast<uint2*>(out)[i] = make_uint2(*(uint32_t*)&h0, *(uint32_t*)&h1);
}

#define N4_WO ((size_t)Lyr*Dm*Dm/4)
#define N4_W1 ((size_t)Dm*DFFn/4)
#define N4_W2 ((size_t)DFFn*Dm/4)
__global__ void cvt3(const float* __restrict__ Wo, const float* __restrict__ W1,
                     const float* __restrict__ W2, __half* __restrict__ wo,
                     __half* __restrict__ w1, __half* __restrict__ w2) {
    size_t i = (size_t)blockIdx.x * blockDim.x + threadIdx.x;
    const float* src; __half* dst; size_t j;
    if (i < N4_WO) { src = Wo; dst = wo; j = i; }
    else if (i < N4_WO + N4_W1) { src = W1; dst = w1; j = i - N4_WO; }
    else if (i < N4_WO + N4_W1 + N4_W2) { src = W2; dst = w2; j = i - N4_WO - N4_W1; }
    else return;
    float4 v = reinterpret_cast<const float4*>(src)[j];
    __half2 h0 = __floats2half2_rn(v.x, v.y);
    __half2 h1 = __floats2half2_rn(v.z, v.w);
    reinterpret_cast<uint2*>(dst)[j] = make_uint2(*(uint32_t*)&h0, *(uint32_t*)&h1);
}

__global__ void pad_cvt_wout(const float* __restrict__ src, __half* __restrict__ dst,
                             const float* __restrict__ bsrc, float* __restrict__ bdst) {
    const size_t total = (size_t)Dm * VPAD;
    for (size_t i = (size_t)blockIdx.x * blockDim.x + threadIdx.x; i < total;
         i += (size_t)gridDim.x * blockDim.x) {
        size_t r = i / VPAD, c = i % VPAD;
        dst[i] = (c < VOCn) ? __float2half(src[r * VOCn + c]) : __half(0.f);
        if (i < VPAD) bdst[i] = (i < VOCn) ? bsrc[i] : 0.f;
    }
}

__global__ void concat_bias(const float* __restrict__ bq, const float* __restrict__ bk,
                            const float* __restrict__ bv, float* __restrict__ o) {
    int i = blockIdx.x * blockDim.x + threadIdx.x;
    if (i >= Lyr * QKVLD) return;
    int l = i / QKVLD, j = i % QKVLD;
    float v = (j < 512) ? bq[l * 512 + j] : (j < 1024) ? bk[l * 512 + j - 512]
                                                       : bv[l * 512 + j - 1024];
    o[i] = v;
}

__global__ void embed_kernel(const int* __restrict__ ids,
                             const float* __restrict__ tok,
                             const float* __restrict__ pos,
                             __half* __restrict__ x) {
    int row = blockIdx.x;
    int s = row % Sq;
    int id = ids[row];
    const float4* t4 = reinterpret_cast<const float4*>(tok) + (size_t)id * (Dm / 4);
    const float4* p4 = reinterpret_cast<const float4*>(pos) + (size_t)s * (Dm / 4);
    int t = threadIdx.x;
    float4 a = t4[t], b = p4[t];
    __half2 h0 = __floats2half2_rn(a.x + b.x, a.y + b.y);
    __half2 h1 = __floats2half2_rn(a.z + b.z, a.w + b.w);
    reinterpret_cast<uint2*>(x + (size_t)row * Dm)[t] = make_uint2(*(uint32_t*)&h0, *(uint32_t*)&h1);
}

// ===== GEMM h4: 128x128, BK=32, 128 thr (4 warps, warp tile 64x64), 2 CTA/SM =====
// smem: A [3][128][40]h (30720B) + B [3][32][144]h (27648B) = 58368B
#define H4_BYTES 58368

template <int ACT, int OUTH>
__global__ __launch_bounds__(128, 2)
void gemm_h4(int K, const __half* __restrict__ A,
             const __half* __restrict__ W, int ldw,
             const float* __restrict__ bias,
             void* __restrict__ Cv, int ldc, int Nc) {
    extern __shared__ char smraw[];
    __half* As = reinterpret_cast<__half*>(smraw);            // [3][128][40]
    __half* Bs = reinterpret_cast<__half*>(smraw + 30720);    // [3][32][144]
    const uint32_t sb = smem_u32(smraw);
    const uint32_t sbB = sb + 30720;

    const int tid = threadIdx.x;
    const int wid = tid >> 5;
    const int wm = wid & 1, wn = wid >> 1;   // 2x2 warps, warp tile 64x64
    const int crow = blockIdx.y * 128;
    const int ccol = blockIdx.x * 128;

    wmma::fragment<wmma::accumulator, 16, 16, 16, float> acc[4][4];
#pragma unroll
    for (int i = 0; i < 4; i++)
#pragma unroll
        for (int j = 0; j < 4; j++) wmma::fill_fragment(acc[i][j], 0.f);

    const __half* Ab = A + (size_t)crow * K;
    const int T = K >> 5;

    auto issue_stage = [&](int st, int t) {
        const int k0 = t << 5;
        // A: 128 rows x 4 segs = 512 chunks / 128 thr = 4 reps
#pragma unroll
        for (int rep = 0; rep < 4; rep++) {
            int c = rep * 128 + tid;
            int row = c >> 2, seg = c & 3;
            CP_ASYNC16(sb + st * 10240 + row * 80 + seg * 16,
                       &Ab[(size_t)row * K + k0 + seg * 8]);
        }
        // B: 32 rows x 16 segs = 512 chunks
#pragma unroll
        for (int rep = 0; rep < 4; rep++) {
            int c = rep * 128 + tid;
            int row = c >> 4, seg = c & 15;
            CP_ASYNC16(sbB + st * 9216 + row * 288 + seg * 16,
                       &W[(size_t)(k0 + row) * ldw + ccol + seg * 8]);
        }
        CP_COMMIT();
    };

    issue_stage(0, 0);
    issue_stage(1, 1);

    for (int t = 0; t < T; t++) {
        CP_WAIT(1);
        __syncthreads();
        if (t + 2 < T) issue_stage((t + 2) % 3, t + 2); else CP_COMMIT();
        const int st = t % 3;
        __half* Ast = As + st * 128 * 40;
        __half* Bst = Bs + st * 32 * 144;
#pragma unroll
        for (int ks = 0; ks < 2; ks++) {
            wmma::fragment<wmma::matrix_a, 16, 16, 16, __half, wmma::row_major> af[4];
            wmma::fragment<wmma::matrix_b, 16, 16, 16, __half, wmma::row_major> bf[4];
#pragma unroll
            for (int i = 0; i < 4; i++)
                wmma::load_matrix_sync(af[i], Ast + (wm * 64 + i * 16) * 40 + ks * 16, 40);
#pragma unroll
            for (int j = 0; j < 4; j++)
                wmma::load_matrix_sync(bf[j], Bst + (ks * 16) * 144 + wn * 64 + j * 16, 144);
#pragma unroll
            for (int i = 0; i < 4; i++)
#pragma unroll
                for (int j = 0; j < 4; j++)
                    wmma::mma_sync(acc[i][j], af[i], bf[j], acc[i][j]);
        }
    }

    // epilogue: 4 passes, each stages 32 rows x 128 cols
    float* stg = reinterpret_cast<float*>(smraw);   // [4][16][68]
#pragma unroll
    for (int i = 0; i < 4; i++) {
        __syncthreads();
#pragma unroll
        for (int j = 0; j < 4; j++)
            wmma::store_matrix_sync(stg + wid * 1088 + j * 16, acc[i][j], 68, wmma::mem_row_major);
        __syncthreads();
#pragma unroll
        for (int it = 0; it < 8; it++) {
            int idx = it * 128 + tid;            // 1024 float4 = 32 rows x 32 c4
            int r = idx >> 5;                     // 0..31
            int c4 = (idx & 31) * 4;
            int wmg = r >> 4, rr = r & 15;        // which warp-row, row in frag
            int wng = c4 >> 6, cc = c4 & 63;
            const float* sp = stg + (wng * 2 + wmg) * 1088 + rr * 68 + cc;
            int row = crow + wmg * 64 + i * 16 + rr;
            int colb = ccol + c4;
            float4 bvv = *reinterpret_cast<const float4*>(&bias[colb]);
            float v0 = sp[0] + bvv.x, v1 = sp[1] + bvv.y;
            float v2 = sp[2] + bvv.z, v3 = sp[3] + bvv.w;
            if (ACT == 1) {
                v0 = 0.5f * v0 * (1.0f + erff(v0 * 0.70710678118654752f));
                v1 = 0.5f * v1 * (1.0f + erff(v1 * 0.70710678118654752f));
                v2 = 0.5f * v2 * (1.0f + erff(v2 * 0.70710678118654752f));
                v3 = 0.5f * v3 * (1.0f + erff(v3 * 0.70710678118654752f));
            }
            if (OUTH == 1) {
                __half* C = reinterpret_cast<__half*>(Cv);
                __half2 h0 = __floats2half2_rn(v0, v1);
                __half2 h1 = __floats2half2_rn(v2, v3);
                *reinterpret_cast<uint2*>(&C[(size_t)row * ldc + colb]) =
                    make_uint2(*(uint32_t*)&h0, *(uint32_t*)&h1);
            } else {
                float* C = reinterpret_cast<float*>(Cv);
                float* cp = &C[(size_t)row * ldc + colb];
                if (colb + 0 < Nc) cp[0] = v0;
                if (colb + 1 < Nc) cp[1] = v1;
                if (colb + 2 < Nc) cp[2] = v2;
                if (colb + 3 < Nc) cp[3] = v3;
            }
        }
    }
}

// ================= GEMM h3: 64x128, BK=32, half, 3 CTA/SM =================
#define H3_BYTES 43008

template <int ACT>
__global__ __launch_bounds__(128, 3)
void gemm_h3(int K, const __half* __restrict__ A,
             const __half* __restrict__ W, int ldw,
             const float* __restrict__ bias,
             __half* __restrict__ C, int ldc) {
    extern __shared__ char smraw[];
    __half* As = reinterpret_cast<__half*>(smraw);            // [3][64][40]
    __half* Bs = reinterpret_cast<__half*>(smraw + 15360);    // [3][32][144]
    const uint32_t sb = smem_u32(smraw);
    const uint32_t sbB = sb + 15360;

    const int tid = threadIdx.x;
    const int wid = tid >> 5;
    const int wm = wid & 1, wn = wid >> 1;
    const int crow = blockIdx.y * 64;
    const int ccol = blockIdx.x * 128;

    wmma::fragment<wmma::accumulator, 16, 16, 16, float> acc[2][4];
#pragma unroll
    for (int i = 0; i < 2; i++)
#pragma unroll
        for (int j = 0; j < 4; j++) wmma::fill_fragment(acc[i][j], 0.f);

    const __half* Ab = A + (size_t)crow * K;
    const int T = K >> 5;

    auto issue_stage = [&](int st, int t) {
        const int k0 = t << 5;
#pragma unroll
        for (int rep = 0; rep < 2; rep++) {
            int c = rep * 128 + tid;
            int row = c >> 2, seg = c & 3;
            CP_ASYNC16(sb + st * 5120 + row * 80 + seg * 16,
                       &Ab[(size_t)row * K + k0 + seg * 8]);
        }
#pragma unroll
        for (int rep = 0; rep < 4; rep++) {
            int c = rep * 128 + tid;
            int row = c >> 4, seg = c & 15;
            CP_ASYNC16(sbB + st * 9216 + row * 288 + seg * 16,
                       &W[(size_t)(k0 + row) * ldw + ccol + seg * 8]);
        }
        CP_COMMIT();
    };

    issue_stage(0, 0);
    issue_stage(1, 1);

    for (int t = 0; t < T; t++) {
        CP_WAIT(1);
        __syncthreads();
        if (t + 2 < T) issue_stage((t + 2) % 3, t + 2); else CP_COMMIT();
        const int st = t % 3;
        __half* Ast = As + st * 64 * 40;
        __half* Bst = Bs + st * 32 * 144;
#pragma unroll
        for (int ks = 0; ks < 2; ks++) {
            wmma::fragment<wmma::matrix_a, 16, 16, 16, __half, wmma::row_major> af[2];
            wmma::fragment<wmma::matrix_b, 16, 16, 16, __half, wmma::row_major> bf[4];
#pragma unroll
            for (int i = 0; i < 2; i++)
                wmma::load_matrix_sync(af[i], Ast + (wm * 32 + i * 16) * 40 + ks * 16, 40);
#pragma unroll
            for (int j = 0; j < 4; j++)
                wmma::load_matrix_sync(bf[j], Bst + (ks * 16) * 144 + wn * 64 + j * 16, 144);
#pragma unroll
            for (int i = 0; i < 2; i++)
#pragma unroll
                for (int j = 0; j < 4; j++)
                    wmma::mma_sync(acc[i][j], af[i], bf[j], acc[i][j]);
        }
    }

    float* stg = reinterpret_cast<float*>(smraw);
#pragma unroll
    for (int i = 0; i < 2; i++) {
        __syncthreads();
#pragma unroll
        for (int j = 0; j < 4; j++)
            wmma::store_matrix_sync(stg + wid * 1088 + j * 16, acc[i][j], 68, wmma::mem_row_major);
        __syncthreads();
#pragma unroll
        for (int it = 0; it < 8; it++) {
            int idx = it * 128 + tid;
            int r = idx >> 5;
            int c4 = (idx & 31) * 4;
            int wmg = r >> 4, rr = r & 15;
            int wng = c4 >> 6, cc = c4 & 63;
            const float* sp = stg + (wng * 2 + wmg) * 1088 + rr * 68 + cc;
            int row = crow + wmg * 32 + i * 16 + rr;
            int colb = ccol + c4;
            float4 bvv = *reinterpret_cast<const float4*>(&bias[colb]);
            float v0 = sp[0] + bvv.x, v1 = sp[1] + bvv.y;
            float v2 = sp[2] + bvv.z, v3 = sp[3] + bvv.w;
            if (ACT == 1) {
                v0 = 0.5f * v0 * (1.0f + erff(v0 * 0.70710678118654752f));
                v1 = 0.5f * v1 * (1.0f + erff(v1 * 0.70710678118654752f));
                v2 = 0.5f * v2 * (1.0f + erff(v2 * 0.70710678118654752f));
                v3 = 0.5f * v3 * (1.0f + erff(v3 * 0.70710678118654752f));
            }
            __half2 h0 = __floats2half2_rn(v0, v1);
            __half2 h1 = __floats2half2_rn(v2, v3);
            *reinterpret_cast<uint2*>(&C[(size_t)row * ldc + colb]) =
                make_uint2(*(uint32_t*)&h0, *(uint32_t*)&h1);
        }
    }
}

// ================= fused attention: q-tile 32, 2 CTA/SM =================
#define ATT_SLD 516
#define ATT_PLD 528
#define ATT_BYTES (32*ATT_SLD*4 + 32*ATT_PLD*2)

__global__ __launch_bounds__(256, 2)
void attn_fused(const __half* __restrict__ QKV, __half* __restrict__ O) {
    extern __shared__ char sm[];
    float* Ssm = reinterpret_cast<float*>(sm);
    __half* Psm = reinterpret_cast<__half*>(sm + 32 * ATT_SLD * 4);

    const int tid = threadIdx.x;
    const int wid = tid >> 5, lane = tid & 31;
    const int bh = blockIdx.y;
    const int b = bh >> 3, h = bh & 7;
    const int q0 = blockIdx.x * 32;

    const __half* qb = QKV + (size_t)b * Sq * QKVLD + h * DKh;
    const __half* kb = QKV + (size_t)b * Sq * QKVLD + 512 + h * DKh;
    const __half* vb = QKV + (size_t)b * Sq * QKVLD + 1024 + h * DKh;

    {
        const int wq = wid & 1, wk = wid >> 1;
        wmma::fragment<wmma::accumulator, 16, 16, 16, float> acc[8];
#pragma unroll
        for (int j = 0; j < 8; j++) wmma::fill_fragment(acc[j], 0.f);

#pragma unroll
        for (int d0 = 0; d0 < DKh; d0 += 16) {
            wmma::fragment<wmma::matrix_a, 16, 16, 16, __half, wmma::row_major> af;
            wmma::load_matrix_sync(af, &qb[(size_t)(q0 + wq * 16) * QKVLD + d0], QKVLD);
#pragma unroll
            for (int j = 0; j < 8; j++) {
                wmma::fragment<wmma::matrix_b, 16, 16, 16, __half, wmma::col_major> bf;
                wmma::load_matrix_sync(bf, &kb[(size_t)(wk * 128 + j * 16) * QKVLD + d0], QKVLD);
                wmma::mma_sync(acc[j], af, bf, acc[j]);
            }
        }
#pragma unroll
        for (int j = 0; j < 8; j++) {
#pragma unroll
            for (int e = 0; e < acc[j].num_elements; e++) acc[j].x[e] *= 0.125f;
            wmma::store_matrix_sync(&Ssm[(wq * 16) * ATT_SLD + wk * 128 + j * 16],
                                    acc[j], ATT_SLD, wmma::mem_row_major);
        }
    }
    __syncthreads();

    {
        const int row = wid * 4 + (lane >> 3);
        const int sub = lane & 7;
        const float* srow = Ssm + row * ATT_SLD;
        __half* prow = Psm + row * ATT_PLD;

        float mx = -1e30f;
#pragma unroll 8
        for (int i = 0; i < 64; i++) mx = fmaxf(mx, srow[sub + 8 * i]);
        mx = fmaxf(mx, __shfl_xor_sync(0xffffffffu, mx, 1));
        mx = fmaxf(mx, __shfl_xor_sync(0xffffffffu, mx, 2));
        mx = fmaxf(mx, __shfl_xor_sync(0xffffffffu, mx, 4));

        float sum = 0.f;
#pragma unroll 8
        for (int i = 0; i < 64; i++) {
            float e = __expf(srow[sub + 8 * i] - mx);
            sum += e;
            prow[sub + 8 * i] = __float2half(e);
        }
        sum += __shfl_xor_sync(0xffffffffu, sum, 1);
        sum += __shfl_xor_sync(0xffffffffu, sum, 2);
        sum += __shfl_xor_sync(0xffffffffu, sum, 4);
        float inv = 1.0f / sum;
#pragma unroll 8
        for (int i = 0; i < 64; i++) {
            int c = sub + 8 * i;
            prow[c] = __float2half(__half2float(prow[c]) * inv);
        }
    }
    __syncthreads();

    {
        const int wq = wid & 1, wd = wid >> 1;
        wmma::fragment<wmma::accumulator, 16, 16, 16, float> acc;
        wmma::fill_fragment(acc, 0.f);

        for (int k0 = 0; k0 < Sq; k0 += 16) {
            wmma::fragment<wmma::matrix_a, 16, 16, 16, __half, wmma::row_major> af;
            wmma::fragment<wmma::matrix_b, 16, 16, 16, __half, wmma::row_major> bf;
            wmma::load_matrix_sync(af, &Psm[(wq * 16) * ATT_PLD + k0], ATT_PLD);
            wmma::load_matrix_sync(bf, &vb[(size_t)k0 * QKVLD + wd * 16], QKVLD);
            wmma::mma_sync(acc, af, bf, acc);
        }
        float* stg = Ssm;
        wmma::store_matrix_sync(&stg[(wq * 16) * 68 + wd * 16], acc, 68, wmma::mem_row_major);
    }
    __syncthreads();
    {
        float* stg = Ssm;
        __half* ob = O + (size_t)b * Sq * Dm + h * DKh;
#pragma unroll
        for (int it = 0; it < 4; it++) {
            int idx = it * 256 + tid;
            int r = idx >> 5, c2 = idx & 31;
            __half2 hh = __floats2half2_rn(stg[r * 68 + c2 * 2], stg[r * 68 + c2 * 2 + 1]);
            *reinterpret_cast<uint32_t*>(&ob[(size_t)(q0 + r) * Dm + c2 * 2]) = *(uint32_t*)&hh;
        }
    }
}

// ================= warp-per-row LayerNorm (single pass) =================
__global__ __launch_bounds__(256)
void ln_kernel(const __half* __restrict__ a, const __half* __restrict__ res,
               const float* __restrict__ g, const float* __restrict__ beta,
               __half* __restrict__ out) {
    const int wid = threadIdx.x >> 5, lane = threadIdx.x & 31;
    const size_t row = blockIdx.x * 8 + wid;
    const __half2* a2 = reinterpret_cast<const __half2*>(a + row * Dm);
    const __half2* r2 = res ? reinterpret_cast<const __half2*>(res + row * Dm) : nullptr;

    float v[16];
    float s = 0.f, sq = 0.f;
#pragma unroll
    for (int k = 0; k < 8; k++) {
        int i = lane + 32 * k;
        __half2 h = a2[i];
        float x0 = __half2float(__low2half(h)), x1 = __half2float(__high2half(h));
        if (r2) {
            __half2 rr = r2[i];
            x0 += __half2float(__low2half(rr));
            x1 += __half2float(__high2half(rr));
        }
        v[2 * k] = x0; v[2 * k + 1] = x1;
        s += x0 + x1;
        sq += x0 * x0 + x1 * x1;
    }
#pragma unroll
    for (int o = 16; o; o >>= 1) {
        s  += __shfl_xor_sync(0xffffffffu, s, o);
        sq += __shfl_xor_sync(0xffffffffu, sq, o);
    }
    float mean = s * (1.0f / Dm);
    float var = sq * (1.0f / Dm) - mean * mean;
    float inv = rsqrtf(var + 1e-5f);

    const float2* gf = reinterpret_cast<const float2*>(g);
    const float2* bf = reinterpret_cast<const float2*>(beta);
    __half2* o2 = reinterpret_cast<__half2*>(out + row * Dm);
#pragma unroll
    for (int k = 0; k < 8; k++) {
        int i = lane + 32 * k;
        float2 gg = gf[i], bb = bf[i];
        float y0 = (v[2 * k]     - mean) * inv * gg.x + bb.x;
        float y1 = (v[2 * k + 1] - mean) * inv * gg.y + bb.y;
        o2[i] = __floats2half2_rn(y0, y1);
    }
}

// ================= orchestration =================
extern "C" void kernel_launch(void* const* d_in, const int* in_sizes, int n_in,
                              void* d_out, int out_size) {
    const int*   ids  = (const int*)  d_in[0];
    const float* tok  = (const float*)d_in[1];
    const float* pos  = (const float*)d_in[2];
    const float* Wq   = (const float*)d_in[3];
    const float* bq   = (const float*)d_in[4];
    const float* Wk   = (const float*)d_in[5];
    const float* bk   = (const float*)d_in[6];
    const float* Wv   = (const float*)d_in[7];
    const float* bv   = (const float*)d_in[8];
    const float* Wo   = (const float*)d_in[9];
    const float* bo   = (const float*)d_in[10];
    const float* ln_g = (const float*)d_in[11];
    const float* ln_b = (const float*)d_in[12];
    const float* W1   = (const float*)d_in[13];
    const float* b1   = (const float*)d_in[14];
    const float* W2   = (const float*)d_in[15];
    const float* b2   = (const float*)d_in[16];
    const float* on_g = (const float*)d_in[17];
    const float* on_b = (const float*)d_in[18];
    const float* Wout = (const float*)d_in[19];
    const float* bout = (const float*)d_in[20];
    float* out = (float*)d_out;

    __half *x, *qkv, *t, *tmp, *ff, *wqkv, *wo, *w1, *w2, *wout;
    float *bqkv, *boutp;
    cudaGetSymbolAddress((void**)&x,     g_x);
    cudaGetSymbolAddress((void**)&qkv,   g_qkv);
    cudaGetSymbolAddress((void**)&t,     g_t);
    cudaGetSymbolAddress((void**)&tmp,   g_tmp);
    cudaGetSymbolAddress((void**)&ff,    g_ff);
    cudaGetSymbolAddress((void**)&wqkv,  g_wqkv);
    cudaGetSymbolAddress((void**)&wo,    g_wo);
    cudaGetSymbolAddress((void**)&w1,    g_w1);
    cudaGetSymbolAddress((void**)&w2,    g_w2);
    cudaGetSymbolAddress((void**)&wout,  g_wout);
    cudaGetSymbolAddress((void**)&bqkv,  g_bqkv);
    cudaGetSymbolAddress((void**)&boutp, g_bout);

    cudaFuncSetAttribute(gemm_h4<0,0>, cudaFuncAttributeMaxDynamicSharedMemorySize, H4_BYTES);
    cudaFuncSetAttribute(gemm_h4<1,1>, cudaFuncAttributeMaxDynamicSharedMemorySize, H4_BYTES);
    cudaFuncSetAttribute(gemm_h3<0>,   cudaFuncAttributeMaxDynamicSharedMemorySize, H3_BYTES);
    cudaFuncSetAttribute(attn_fused,   cudaFuncAttributeMaxDynamicSharedMemorySize, ATT_BYTES);

    // ---- prep ----
    {
        size_t n4 = (size_t)Lyr * Dm * (QKVLD / 4);
        build_wqkv<<<(unsigned)((n4 + 255) / 256), 256>>>(Wq, Wk, Wv, wqkv);
        size_t tot = N4_WO + N4_W1 + N4_W2;
        cvt3<<<(unsigned)((tot + 255) / 256), 256>>>(Wo, W1, W2, wo, w1, w2);
        pad_cvt_wout<<<4096, 256>>>(Wout, wout, bout, boutp);
        concat_bias<<<(Lyr * QKVLD + 255) / 256, 256>>>(bq, bk, bv, bqkv);
    }

    embed_kernel<<<NTOK, 128>>>(ids, tok, pos, x);

    for (int l = 0; l < Lyr; l++) {
        const size_t bOff = (size_t)l * Dm;
        gemm_h3<0><<<dim3(QKVLD / 128, NTOK / 64), 128, H3_BYTES>>>(
            Dm, x, wqkv + (size_t)l * Dm * QKVLD, QKVLD,
            bqkv + (size_t)l * QKVLD, qkv, QKVLD);

        attn_fused<<<dim3(Sq / 32, Bsz * Hn), 256, ATT_BYTES>>>(qkv, t);

        gemm_h3<0><<<dim3(Dm / 128, NTOK / 64), 128, H3_BYTES>>>(
            Dm, t, wo + (size_t)l * Dm * Dm, Dm, bo + bOff, tmp, Dm);
        ln_kernel<<<NTOK / 8, 256>>>(x, tmp, ln_g + bOff, ln_b + bOff, x);
    }

    // FFN1 (N=2048) via h4: grid (16, 16)
    gemm_h4<1,1><<<dim3(DFFn / 128, NTOK / 128), 128, H4_BYTES>>>(
        Dm, x, w1, DFFn, b1, ff, DFFn, DFFn);
    gemm_h3<0><<<dim3(Dm / 128, NTOK / 64), 128, H3_BYTES>>>(
        DFFn, ff, w2, Dm, b2, t, Dm);
    ln_kernel<<<NTOK / 8, 256>>>(t, nullptr, on_g, on_b, x);

    // logits via h4: grid (394, 16)
    gemm_h4<0,0><<<dim3(VPAD / 128, NTOK / 128), 128, H4_BYTES>>>(
        Dm, x, wout, VPAD, boutp, out, VOCn, VOCn);
}